// round 1
// baseline (speedup 1.0000x reference)
#include <cuda_runtime.h>
#include <math.h>

#define BSZ  8
#define SLEN 100
#define GG   800            // BSZ*SLEN
#define NNODE 200
#define NEDGE 600
#define DD   128
#define DCC  64
#define HHID 256
#define CP1N 111
#define FEATN 177           // 2 + CP1 + DC
#define GN   160000         // GG*NNODE

// ---------------- scratch (device globals; no allocation allowed) ----------
__device__ float g_x[(size_t)GN * DD];          // node states
__device__ float g_mgh[(size_t)GN * 512];       // [m(128) | gh(384)]
__device__ float g_agg[(size_t)GN * DD];
__device__ float g_gi[(size_t)GN * 384];
__device__ float g_ggnn[(size_t)GN * DCC];
__device__ float g_attn[GG * DCC];
__device__ float g_ew[GG * NEDGE];
__device__ float g_mean8[8];
__device__ float g_Bcat[4 * 128 * 512];         // per-layer [ggnn_w_l | W_hh^T]
__device__ float g_WihT[128 * 384];
__device__ float g_TdT[128 * 64];
__device__ float g_LihT[FEATN * 1024];          // gate-permuted lstm W_ih^T
__device__ float g_WhhP[256 * 1024];            // gate-permuted lstm W_hh^T
__device__ float g_pre[(size_t)GG * 1024];
__device__ float g_hout[(size_t)GG * HHID];
__device__ float g_fp[GG];
__device__ float g_bce[GG];
__device__ float g_mf[GG];

__device__ __forceinline__ float sigmoidf_(float v) { return 1.f / (1.f + expf(-v)); }

// ---------------- prep: weight transposes / permutations / edge-type means --
__global__ void prep_kernel(const float* __restrict__ edge_embed_w,
                            const float* __restrict__ ggnn_w,
                            const float* __restrict__ gru_w_ih,
                            const float* __restrict__ gru_w_hh,
                            const float* __restrict__ transdim_w,
                            const float* __restrict__ lstm_w_ih,
                            const float* __restrict__ lstm_w_hh) {
    const int T1 = 4 * 128 * 512, T2 = 128 * 384, T3 = 128 * 64,
              T4 = FEATN * 1024, T5 = 256 * 1024;
    int total = 8 + T1 + T2 + T3 + T4 + T5;
    for (int i = blockIdx.x * blockDim.x + threadIdx.x; i < total;
         i += gridDim.x * blockDim.x) {
        int t = i;
        if (t < 8) {
            float s = 0.f;
            for (int d = 0; d < DD; d++) s += edge_embed_w[t * DD + d];
            g_mean8[t] = s / (float)DD;
            continue;
        }
        t -= 8;
        if (t < T1) {
            int l = t / (128 * 512); int r = t % (128 * 512);
            int k = r / 512; int e = r % 512;
            g_Bcat[t] = (e < 128) ? ggnn_w[(l * 128 + k) * 128 + e]
                                  : gru_w_hh[(e - 128) * 128 + k];
            continue;
        }
        t -= T1;
        if (t < T2) { int k = t / 384, j = t % 384; g_WihT[t] = gru_w_ih[j * 128 + k]; continue; }
        t -= T2;
        if (t < T3) { int k = t / 64, c = t % 64;  g_TdT[t] = transdim_w[c * 128 + k]; continue; }
        t -= T3;
        if (t < T4) {
            int k = t / 1024, p = t % 1024; int q = p & 3, j = p >> 2;
            g_LihT[t] = lstm_w_ih[(q * 256 + j) * FEATN + k];
            continue;
        }
        t -= T4;
        {
            int k = t / 1024, p = t % 1024; int q = p & 3, j = p >> 2;
            g_WhhP[t] = lstm_w_hh[(q * 256 + j) * 256 + k];
        }
    }
}

__global__ void ew_kernel(const int* __restrict__ edge_type) {
    int i = blockIdx.x * blockDim.x + threadIdx.x;
    if (i < GG * NEDGE) g_ew[i] = g_mean8[edge_type[i]];
}

// ---------------- node-embedding gather (warp per row) ----------------------
__global__ void gather_kernel(const int* __restrict__ node_id,
                              const float* __restrict__ embed) {
    int warp = threadIdx.x >> 5, lane = threadIdx.x & 31;
    int row = blockIdx.x * 8 + warp;
    if (row >= GN) return;
    int nid = node_id[row];
    float4 v = *(const float4*)&embed[(size_t)nid * DD + lane * 4];
    *(float4*)&g_x[(size_t)row * DD + lane * 4] = v;
}

// ---------------- generic fp32 GEMM: C[M,N] = A[M,128] @ B[128,N] -----------
// 64x64 block tile, 4x4 per thread, K chunked 2x64 through smem.
__global__ void gemm_k128(const float* __restrict__ A, const float* __restrict__ B,
                          float* __restrict__ C, int Ncols) {
    __shared__ float Ast[64][68];   // [k][row], padded
    __shared__ float Bs[64][64];    // [k][col]
    int tid = threadIdx.x;
    int tx = tid & 15, ty = tid >> 4;
    int rowBase = blockIdx.x * 64;
    int colBase = blockIdx.y * 64;
    float acc[4][4] = {};
    for (int kc = 0; kc < 2; kc++) {
        {
            int c4 = tid & 15;
            int r0 = tid >> 4;
#pragma unroll
            for (int rr = 0; rr < 4; rr++) {
                int row = r0 + 16 * rr;
                float4 v = *(const float4*)&A[(size_t)(rowBase + row) * 128 + kc * 64 + c4 * 4];
                Ast[c4 * 4 + 0][row] = v.x;
                Ast[c4 * 4 + 1][row] = v.y;
                Ast[c4 * 4 + 2][row] = v.z;
                Ast[c4 * 4 + 3][row] = v.w;
            }
#pragma unroll
            for (int kk2 = 0; kk2 < 4; kk2++) {
                int kr = r0 + 16 * kk2;
                float4 v = *(const float4*)&B[(size_t)(kc * 64 + kr) * Ncols + colBase + c4 * 4];
                *(float4*)&Bs[kr][c4 * 4] = v;
            }
        }
        __syncthreads();
#pragma unroll 8
        for (int kk = 0; kk < 64; kk++) {
            float4 a = *(const float4*)&Ast[kk][ty * 4];
            float4 b = *(const float4*)&Bs[kk][tx * 4];
            float av[4] = {a.x, a.y, a.z, a.w};
            float bv[4] = {b.x, b.y, b.z, b.w};
#pragma unroll
            for (int i = 0; i < 4; i++)
#pragma unroll
                for (int j = 0; j < 4; j++) acc[i][j] += av[i] * bv[j];
        }
        __syncthreads();
    }
#pragma unroll
    for (int i = 0; i < 4; i++) {
        float4 o = make_float4(acc[i][0], acc[i][1], acc[i][2], acc[i][3]);
        *(float4*)&C[(size_t)(rowBase + ty * 4 + i) * Ncols + colBase + tx * 4] = o;
    }
}

// ---------------- edge message scatter: per-graph smem accumulation ---------
__global__ void scatter_kernel(const int* __restrict__ edge) {
    extern __shared__ float sh[];   // NNODE*DD floats
    int g = blockIdx.x;
    int tid = threadIdx.x;
    for (int i = tid; i < NNODE * DD; i += blockDim.x) sh[i] = 0.f;
    __syncthreads();
    int warp = tid >> 5, lane = tid & 31, nw = blockDim.x >> 5;
    const int* eg = edge + (size_t)g * 2 * NEDGE;
    for (int e = warp; e < NEDGE; e += nw) {
        int src = eg[e];
        int dst = eg[NEDGE + e];
        float w = g_ew[g * NEDGE + e];
        const float* mr = g_mgh + (size_t)(g * NNODE + src) * 512;
#pragma unroll
        for (int i = 0; i < 4; i++) {
            float v = mr[lane + 32 * i] * w;
            atomicAdd(&sh[dst * DD + lane + 32 * i], v);
        }
    }
    __syncthreads();
    float* ag = g_agg + (size_t)g * NNODE * DD;
    for (int i = tid; i < NNODE * DD; i += blockDim.x) ag[i] = sh[i];
}

// ---------------- GRU elementwise update -----------------------------------
__global__ void gru_kernel(const float* __restrict__ b_ih, const float* __restrict__ b_hh) {
    int t = blockIdx.x * blockDim.x + threadIdx.x;
    if (t >= GN * 32) return;
    int row = t >> 5;
    int j4 = (t & 31) << 2;
    const float* gi = g_gi + (size_t)row * 384;
    const float* mg = g_mgh + (size_t)row * 512;
    float4 ir = *(const float4*)&gi[j4];
    float4 iz = *(const float4*)&gi[128 + j4];
    float4 in_ = *(const float4*)&gi[256 + j4];
    float4 hr = *(const float4*)&mg[128 + j4];
    float4 hz = *(const float4*)&mg[256 + j4];
    float4 hn = *(const float4*)&mg[384 + j4];
    float4 bir = *(const float4*)&b_ih[j4];
    float4 biz = *(const float4*)&b_ih[128 + j4];
    float4 bin = *(const float4*)&b_ih[256 + j4];
    float4 bhr = *(const float4*)&b_hh[j4];
    float4 bhz = *(const float4*)&b_hh[128 + j4];
    float4 bhn = *(const float4*)&b_hh[256 + j4];
    float4 xo = *(const float4*)&g_x[(size_t)row * DD + j4];
    float4 xn;
    {
        float r = sigmoidf_(ir.x + bir.x + hr.x + bhr.x);
        float z = sigmoidf_(iz.x + biz.x + hz.x + bhz.x);
        float n = tanhf(in_.x + bin.x + r * (hn.x + bhn.x));
        xn.x = (1.f - z) * n + z * xo.x;
    }
    {
        float r = sigmoidf_(ir.y + bir.y + hr.y + bhr.y);
        float z = sigmoidf_(iz.y + biz.y + hz.y + bhz.y);
        float n = tanhf(in_.y + bin.y + r * (hn.y + bhn.y));
        xn.y = (1.f - z) * n + z * xo.y;
    }
    {
        float r = sigmoidf_(ir.z + bir.z + hr.z + bhr.z);
        float z = sigmoidf_(iz.z + biz.z + hz.z + bhz.z);
        float n = tanhf(in_.z + bin.z + r * (hn.z + bhn.z));
        xn.z = (1.f - z) * n + z * xo.z;
    }
    {
        float r = sigmoidf_(ir.w + bir.w + hr.w + bhr.w);
        float z = sigmoidf_(iz.w + biz.w + hz.w + bhz.w);
        float n = tanhf(in_.w + bin.w + r * (hn.w + bhn.w));
        xn.w = (1.f - z) * n + z * xo.w;
    }
    *(float4*)&g_x[(size_t)row * DD + j4] = xn;
}

// ---------------- attention (block per graph) -------------------------------
__global__ void attn_kernel(const float* __restrict__ c_id,
                            const float* __restrict__ c_embed,
                            const float* __restrict__ concept_embedding) {
    extern __shared__ float sm[];
    float* shg = sm;                        // 200*65
    float* pbuf = shg + NNODE * 65;         // 8*200
    float* qbuf = pbuf + 8 * NNODE;         // 8*64
    float* acc = qbuf + 8 * 64;             // 64
    float* snum = acc + 64;                 // 1
    int g = blockIdx.x;
    int tid = threadIdx.x;
    for (int i = tid; i < NNODE * DCC; i += 256) {
        int n = i >> 6, d = i & 63;
        shg[n * 65 + d] = g_ggnn[(size_t)(g * NNODE + n) * DCC + d];
    }
    if (tid < 64) acc[tid] = 0.f;
    if (tid == 0) snum[0] = 0.f;
    __syncthreads();
    if (tid < CP1N) atomicAdd(snum, c_id[g * CP1N + tid]);
    __syncthreads();
    int warp = tid >> 5, lane = tid & 31;
    for (int c = warp; c < CP1N; c += 8) {
        float ce = c_embed[g * CP1N + c];
        if (ce == 0.f) continue;            // exact zero contribution
        qbuf[warp * 64 + lane] = ce * concept_embedding[c * DCC + lane];
        qbuf[warp * 64 + lane + 32] = ce * concept_embedding[c * DCC + lane + 32];
        __syncwarp();
        float mx = -1e30f;
        for (int n = lane; n < NNODE; n += 32) {
            float s = 0.f;
#pragma unroll 16
            for (int d = 0; d < DCC; d++) s += qbuf[warp * 64 + d] * shg[n * 65 + d];
            pbuf[warp * NNODE + n] = s;
            mx = fmaxf(mx, s);
        }
#pragma unroll
        for (int o = 16; o > 0; o >>= 1) mx = fmaxf(mx, __shfl_xor_sync(0xffffffffu, mx, o));
        float ssum = 0.f;
        for (int n = lane; n < NNODE; n += 32) {
            float p = expf(pbuf[warp * NNODE + n] - mx);
            pbuf[warp * NNODE + n] = p;
            ssum += p;
        }
#pragma unroll
        for (int o = 16; o > 0; o >>= 1) ssum += __shfl_xor_sync(0xffffffffu, ssum, o);
        __syncwarp();
        float inv = ce / ssum;
        float a0 = 0.f, a1 = 0.f;
        for (int n = 0; n < NNODE; n++) {
            float p = pbuf[warp * NNODE + n];
            a0 += p * shg[n * 65 + lane];
            a1 += p * shg[n * 65 + lane + 32];
        }
        atomicAdd(&acc[lane], a0 * inv);
        atomicAdd(&acc[lane + 32], a1 * inv);
        __syncwarp();
    }
    __syncthreads();
    if (tid < DCC) {
        float nv = snum[0];
        if (nv == 0.f) nv = 1.f;
        g_attn[g * DCC + tid] = acc[tid] / nv;
    }
}

// ---------------- LSTM input GEMM (gate-permuted output) -------------------
__global__ void lstm_pre_kernel(const float* __restrict__ c_embed,
                                const float* __restrict__ cur_result,
                                const float* __restrict__ lstm_b_ih) {
    __shared__ float xin[FEATN];
    int s = blockIdx.x;
    int tid = threadIdx.x;
    if (tid < CP1N) xin[tid] = c_embed[s * CP1N + tid];
    else if (tid < CP1N + DCC) xin[tid] = g_attn[s * DCC + (tid - CP1N)];
    else if (tid < FEATN) xin[tid] = cur_result[s * 2 + (tid - CP1N - DCC)];
    __syncthreads();
    int m = blockIdx.y * 256 + tid;
    int q = m & 3, j = m >> 2;
    float acc = lstm_b_ih[q * 256 + j];
    for (int k = 0; k < FEATN; k++) acc += xin[k] * g_LihT[k * 1024 + m];
    g_pre[(size_t)s * 1024 + m] = acc;
}

// ---------------- LSTM recurrence (block per batch element) ----------------
__global__ void lstm_rec_kernel(const float* __restrict__ b_hh) {
    int b = blockIdx.x;
    int j = threadIdx.x;        // 256 threads: one hidden unit each, 4 gates
    __shared__ float sh_h[HHID];
    sh_h[j] = 0.f;
    float c = 0.f;
    float bi = b_hh[j], bf = b_hh[256 + j], bg = b_hh[512 + j], bo = b_hh[768 + j];
    __syncthreads();
    for (int t = 0; t < SLEN; t++) {
        int s = b * SLEN + t;
        float4 acc = *(const float4*)&g_pre[(size_t)s * 1024 + 4 * j];
        acc.x += bi; acc.y += bf; acc.z += bg; acc.w += bo;
#pragma unroll 4
        for (int k = 0; k < HHID; k++) {
            float hk = sh_h[k];
            float4 w = *(const float4*)&g_WhhP[k * 1024 + 4 * j];
            acc.x += hk * w.x; acc.y += hk * w.y; acc.z += hk * w.z; acc.w += hk * w.w;
        }
        float ii = sigmoidf_(acc.x), ff = sigmoidf_(acc.y);
        float gg = tanhf(acc.z), oo = sigmoidf_(acc.w);
        c = ff * c + ii * gg;
        float h = oo * tanhf(c);
        __syncthreads();
        sh_h[j] = h;
        g_hout[(size_t)s * HHID + j] = h;
        __syncthreads();
    }
}

// ---------------- pred + per-sample BCE -------------------------------------
__global__ void pred_kernel(const float* __restrict__ target_c,
                            const float* __restrict__ result,
                            const float* __restrict__ pred_w,
                            const float* __restrict__ pred_b) {
    __shared__ float sh[HHID];
    __shared__ float s_p, s_n;
    int i = blockIdx.x, tid = threadIdx.x;
    sh[tid] = g_hout[(size_t)i * HHID + tid];
    sh[tid + 128] = g_hout[(size_t)i * HHID + tid + 128];
    if (tid == 0) { s_p = 0.f; s_n = 0.f; }
    __syncthreads();
    int warp = tid >> 5, lane = tid & 31;
    float lp = 0.f, ln = 0.f;
    for (int c = warp; c < CP1N; c += 4) {
        float tc = target_c[i * CP1N + c];
        if (tc != 0.f) {
            float s = 0.f;
            for (int d = lane; d < HHID; d += 32) s += pred_w[c * HHID + d] * sh[d];
#pragma unroll
            for (int o = 16; o > 0; o >>= 1) s += __shfl_xor_sync(0xffffffffu, s, o);
            if (lane == 0) { lp += tc * (s + pred_b[c]); ln += tc; }
        }
    }
    if (lane == 0) { atomicAdd(&s_p, lp); atomicAdd(&s_n, ln); }
    __syncthreads();
    if (tid == 0) {
        float nc = s_n;
        int mask = nc > 0.f;
        float fp = s_p / (mask ? nc : 1.f);
        float ft = result[i];
        float bce = fmaxf(fp, 0.f) - fp * ft + log1pf(expf(-fabsf(fp)));
        g_fp[i] = fp;
        g_mf[i] = mask ? 1.f : 0.f;
        g_bce[i] = mask ? bce : 0.f;
    }
}

// ---------------- final reduction + output ----------------------------------
__global__ void final_kernel(const float* __restrict__ result, float* __restrict__ out,
                             int out_size) {
    __shared__ float rb[256], rm[256];
    int tid = threadIdx.x;
    float sb = 0.f, smm = 0.f;
    for (int i = tid; i < GG; i += 256) { sb += g_bce[i]; smm += g_mf[i]; }
    rb[tid] = sb; rm[tid] = smm;
    __syncthreads();
    for (int o = 128; o > 0; o >>= 1) {
        if (tid < o) { rb[tid] += rb[tid + o]; rm[tid] += rm[tid + o]; }
        __syncthreads();
    }
    if (tid == 0 && out_size > 0) out[0] = rb[0] / fmaxf(rm[0], 1.f);
    for (int i = tid; i < GG; i += 256) {
        if (1 + i < out_size) out[1 + i] = 1.f / (1.f + expf(-g_fp[i]));
        if (1 + GG + i < out_size) out[1 + GG + i] = result[i];
    }
}

// ---------------- launcher ---------------------------------------------------
extern "C" void kernel_launch(void* const* d_in, const int* in_sizes, int n_in,
                              void* d_out, int out_size) {
    const float* c_id       = (const float*)d_in[1];
    const int*   node_id    = (const int*)d_in[2];
    const int*   edge       = (const int*)d_in[3];
    const int*   edge_type  = (const int*)d_in[4];
    const float* target_c   = (const float*)d_in[5];
    const float* result     = (const float*)d_in[6];
    const float* c_embed    = (const float*)d_in[7];
    const float* cur_result = (const float*)d_in[8];
    const float* node_embed_w = (const float*)d_in[9];
    const float* edge_embed_w = (const float*)d_in[10];
    const float* ggnn_w     = (const float*)d_in[11];
    const float* gru_w_ih   = (const float*)d_in[12];
    const float* gru_w_hh   = (const float*)d_in[13];
    const float* gru_b_ih   = (const float*)d_in[14];
    const float* gru_b_hh   = (const float*)d_in[15];
    const float* transdim_w = (const float*)d_in[16];
    const float* concept_embedding = (const float*)d_in[17];
    const float* lstm_w_ih  = (const float*)d_in[18];
    const float* lstm_w_hh  = (const float*)d_in[19];
    const float* lstm_b_ih  = (const float*)d_in[20];
    const float* lstm_b_hh  = (const float*)d_in[21];
    const float* pred_w     = (const float*)d_in[22];
    const float* pred_b     = (const float*)d_in[23];
    float* out = (float*)d_out;
    (void)in_sizes; (void)n_in;

    // opt-in to >48KB dynamic shared (device-wide config; not a stream op)
    cudaFuncSetAttribute(scatter_kernel, cudaFuncAttributeMaxDynamicSharedMemorySize,
                         NNODE * DD * 4);
    cudaFuncSetAttribute(attn_kernel, cudaFuncAttributeMaxDynamicSharedMemorySize, 61440);

    // scratch symbol addresses
    void *px, *pmgh, *pagg, *pgi, *pggnn, *pBcat, *pWihT, *pTdT;
    cudaGetSymbolAddress(&px, g_x);
    cudaGetSymbolAddress(&pmgh, g_mgh);
    cudaGetSymbolAddress(&pagg, g_agg);
    cudaGetSymbolAddress(&pgi, g_gi);
    cudaGetSymbolAddress(&pggnn, g_ggnn);
    cudaGetSymbolAddress(&pBcat, g_Bcat);
    cudaGetSymbolAddress(&pWihT, g_WihT);
    cudaGetSymbolAddress(&pTdT, g_TdT);

    prep_kernel<<<2980, 256>>>(edge_embed_w, ggnn_w, gru_w_ih, gru_w_hh,
                               transdim_w, lstm_w_ih, lstm_w_hh);
    ew_kernel<<<(GG * NEDGE + 255) / 256, 256>>>(edge_type);
    gather_kernel<<<GN / 8, 256>>>(node_id, node_embed_w);

    for (int l = 0; l < 4; l++) {
        // [m | gh] = x @ [ggnn_w_l | W_hh^T]
        gemm_k128<<<dim3(GN / 64, 8), 256>>>((const float*)px,
                                             (const float*)pBcat + l * 128 * 512,
                                             (float*)pmgh, 512);
        scatter_kernel<<<GG, 256, NNODE * DD * 4>>>(edge);
        // gi = agg @ W_ih^T
        gemm_k128<<<dim3(GN / 64, 6), 256>>>((const float*)pagg, (const float*)pWihT,
                                             (float*)pgi, 384);
        gru_kernel<<<GN * 32 / 256, 256>>>(gru_b_ih, gru_b_hh);
    }

    // ggnn = x @ transdim^T
    gemm_k128<<<dim3(GN / 64, 1), 256>>>((const float*)px, (const float*)pTdT,
                                         (float*)pggnn, 64);
    attn_kernel<<<GG, 256, 61440>>>(c_id, c_embed, concept_embedding);
    lstm_pre_kernel<<<dim3(GG, 4), 256>>>(c_embed, cur_result, lstm_b_ih);
    lstm_rec_kernel<<<BSZ, 256>>>(lstm_b_hh);
    pred_kernel<<<GG, 128>>>(target_c, result, pred_w, pred_b);
    final_kernel<<<1, 256>>>(result, out, out_size);
}

// round 2
// speedup vs baseline: 1.3555x; 1.3555x over previous
#include <cuda_runtime.h>
#include <math.h>

#define BSZ  8
#define SLEN 100
#define GG   800            // BSZ*SLEN
#define NNODE 200
#define NEDGE 600
#define DD   128
#define DCC  64
#define HHID 256
#define CP1N 111
#define FEATN 177           // 2 + CP1 + DC
#define GN   160000         // GG*NNODE

// ---------------- scratch (device globals; no allocation allowed) ----------
__device__ float g_x[(size_t)GN * DD];          // node states
__device__ float g_agg[(size_t)GN * DD];        // scattered ew-weighted x
__device__ float g_gigh[(size_t)GN * 768];      // [gi(384) | gh(384)]
__device__ float g_ggnn[(size_t)GN * DCC];
__device__ float g_attn[GG * DCC];
__device__ float g_ew[GG * NEDGE];
__device__ float g_mean8[8];
__device__ float g_Wcomb[4 * 128 * 384];        // per-layer W_l @ W_ih^T  [k][j]
__device__ float g_WhhT[128 * 384];             // W_hh^T [k][j]
__device__ float g_TdT[128 * 64];
__device__ float g_LihT[FEATN * 1024];          // gate-permuted lstm W_ih^T
__device__ float g_WhhP[256 * 1024];            // gate-permuted lstm W_hh^T
__device__ float g_pre[(size_t)GG * 1024];
__device__ float g_hout[(size_t)GG * HHID];
__device__ float g_fp[GG];
__device__ float g_bce[GG];
__device__ float g_mf[GG];

__device__ __forceinline__ float sigmoidf_(float v) { return 1.f / (1.f + expf(-v)); }

// ---------------- prep: weight transposes / permutations / edge-type means --
__global__ void prep_kernel(const float* __restrict__ edge_embed_w,
                            const float* __restrict__ gru_w_hh,
                            const float* __restrict__ transdim_w,
                            const float* __restrict__ lstm_w_ih,
                            const float* __restrict__ lstm_w_hh) {
    const int T1 = 128 * 384, T3 = 128 * 64, T4 = FEATN * 1024, T5 = 256 * 1024;
    int total = 8 + T1 + T3 + T4 + T5;
    for (int i = blockIdx.x * blockDim.x + threadIdx.x; i < total;
         i += gridDim.x * blockDim.x) {
        int t = i;
        if (t < 8) {
            float s = 0.f;
            for (int d = 0; d < DD; d++) s += edge_embed_w[t * DD + d];
            g_mean8[t] = s / (float)DD;
            continue;
        }
        t -= 8;
        if (t < T1) { int k = t / 384, j = t % 384; g_WhhT[t] = gru_w_hh[j * 128 + k]; continue; }
        t -= T1;
        if (t < T3) { int k = t / 64, c = t % 64;  g_TdT[t] = transdim_w[c * 128 + k]; continue; }
        t -= T3;
        if (t < T4) {
            int k = t / 1024, p = t % 1024; int q = p & 3, j = p >> 2;
            g_LihT[t] = lstm_w_ih[(q * 256 + j) * FEATN + k];
            continue;
        }
        t -= T4;
        {
            int k = t / 1024, p = t % 1024; int q = p & 3, j = p >> 2;
            g_WhhP[t] = lstm_w_hh[(q * 256 + j) * 256 + k];
        }
    }
}

// W_comb[l] = ggnn_w[l] @ gru_w_ih^T : comb[k][j] = sum_d W_l[k,d] * W_ih[j,d]
__global__ void comb_kernel(const float* __restrict__ ggnn_w,
                            const float* __restrict__ gru_w_ih) {
    int t = blockIdx.x * blockDim.x + threadIdx.x;
    if (t >= 4 * 128 * 384) return;
    int l = t / (128 * 384); int r = t % (128 * 384);
    int k = r / 384, j = r % 384;
    const float4* wl = (const float4*)(ggnn_w + ((size_t)l * 128 + k) * 128);
    const float4* wi = (const float4*)(gru_w_ih + (size_t)j * 128);
    float s = 0.f;
#pragma unroll 8
    for (int d = 0; d < 32; d++) {
        float4 a = wl[d], b = wi[d];
        s += a.x * b.x + a.y * b.y + a.z * b.z + a.w * b.w;
    }
    g_Wcomb[t] = s;
}

__global__ void ew_kernel(const int* __restrict__ edge_type) {
    int i = blockIdx.x * blockDim.x + threadIdx.x;
    if (i < GG * NEDGE) g_ew[i] = g_mean8[edge_type[i]];
}

// ---------------- node-embedding gather (warp per row) ----------------------
__global__ void gather_kernel(const int* __restrict__ node_id,
                              const float* __restrict__ embed) {
    int warp = threadIdx.x >> 5, lane = threadIdx.x & 31;
    int row = blockIdx.x * 8 + warp;
    if (row >= GN) return;
    int nid = node_id[row];
    float4 v = *(const float4*)&embed[(size_t)nid * DD + lane * 4];
    *(float4*)&g_x[(size_t)row * DD + lane * 4] = v;
}

// ---------------- big GEMM: C[128blk,128blk] = A[M,128] @ B[128,384] --------
// Full K=128 resident in smem, 8x8 micro-tile, 256 threads.
#define SA 132
#define SB 132
__global__ void __launch_bounds__(256) gemm128(const float* __restrict__ A,
                                               const float* __restrict__ B,
                                               float* __restrict__ C, int Cstride) {
    extern __shared__ float sm[];
    float* As = sm;              // [128 m][SA] m-major
    float* Bs = sm + 128 * SA;   // [128 k][SB] k-major
    int tid = threadIdx.x;
    int rowBase = blockIdx.x * 128;
    int colBase = blockIdx.y * 128;
    // load A tile (coalesced, float4, conflict-free stores)
#pragma unroll
    for (int i = 0; i < 16; i++) {
        int idx = tid + 256 * i;           // 4096 float4
        int m = idx >> 5, kq = idx & 31;
        float4 v = *(const float4*)&A[(size_t)(rowBase + m) * 128 + kq * 4];
        *(float4*)&As[m * SA + kq * 4] = v;
    }
    // load B tile (coalesced, float4)
#pragma unroll
    for (int i = 0; i < 16; i++) {
        int idx = tid + 256 * i;
        int k = idx >> 5, c4 = idx & 31;
        float4 v = *(const float4*)&B[(size_t)k * 384 + colBase + c4 * 4];
        *(float4*)&Bs[k * SB + c4 * 4] = v;
    }
    __syncthreads();
    int tx = tid & 15, ty = tid >> 4;
    float acc[8][8] = {};
    const float* Ab = As + ty * 8 * SA;
    const float* Bb = Bs + tx * 8;
#pragma unroll 8
    for (int k = 0; k < 128; k++) {
        float a[8], b[8];
#pragma unroll
        for (int j = 0; j < 8; j++) a[j] = Ab[j * SA + k];
        float4 b0 = *(const float4*)&Bb[k * SB];
        float4 b1 = *(const float4*)&Bb[k * SB + 4];
        b[0] = b0.x; b[1] = b0.y; b[2] = b0.z; b[3] = b0.w;
        b[4] = b1.x; b[5] = b1.y; b[6] = b1.z; b[7] = b1.w;
#pragma unroll
        for (int i = 0; i < 8; i++)
#pragma unroll
            for (int j = 0; j < 8; j++) acc[i][j] += a[i] * b[j];
    }
#pragma unroll
    for (int i = 0; i < 8; i++) {
        float4 o0 = make_float4(acc[i][0], acc[i][1], acc[i][2], acc[i][3]);
        float4 o1 = make_float4(acc[i][4], acc[i][5], acc[i][6], acc[i][7]);
        size_t base = (size_t)(rowBase + ty * 8 + i) * Cstride + colBase + tx * 8;
        *(float4*)&C[base] = o0;
        *(float4*)&C[base + 4] = o1;
    }
}

// ---------------- small GEMM (64-col) for transdim ---------------------------
__global__ void gemm_k128(const float* __restrict__ A, const float* __restrict__ B,
                          float* __restrict__ C, int Ncols) {
    __shared__ float Ast[64][68];
    __shared__ float Bs[64][64];
    int tid = threadIdx.x;
    int tx = tid & 15, ty = tid >> 4;
    int rowBase = blockIdx.x * 64;
    int colBase = blockIdx.y * 64;
    float acc[4][4] = {};
    for (int kc = 0; kc < 2; kc++) {
        {
            int c4 = tid & 15;
            int r0 = tid >> 4;
#pragma unroll
            for (int rr = 0; rr < 4; rr++) {
                int row = r0 + 16 * rr;
                float4 v = *(const float4*)&A[(size_t)(rowBase + row) * 128 + kc * 64 + c4 * 4];
                Ast[c4 * 4 + 0][row] = v.x;
                Ast[c4 * 4 + 1][row] = v.y;
                Ast[c4 * 4 + 2][row] = v.z;
                Ast[c4 * 4 + 3][row] = v.w;
            }
#pragma unroll
            for (int kk2 = 0; kk2 < 4; kk2++) {
                int kr = r0 + 16 * kk2;
                float4 v = *(const float4*)&B[(size_t)(kc * 64 + kr) * Ncols + colBase + c4 * 4];
                *(float4*)&Bs[kr][c4 * 4] = v;
            }
        }
        __syncthreads();
#pragma unroll 8
        for (int kk = 0; kk < 64; kk++) {
            float4 a = *(const float4*)&Ast[kk][ty * 4];
            float4 b = *(const float4*)&Bs[kk][tx * 4];
            float av[4] = {a.x, a.y, a.z, a.w};
            float bv[4] = {b.x, b.y, b.z, b.w};
#pragma unroll
            for (int i = 0; i < 4; i++)
#pragma unroll
                for (int j = 0; j < 4; j++) acc[i][j] += av[i] * bv[j];
        }
        __syncthreads();
    }
#pragma unroll
    for (int i = 0; i < 4; i++) {
        float4 o = make_float4(acc[i][0], acc[i][1], acc[i][2], acc[i][3]);
        *(float4*)&C[(size_t)(rowBase + ty * 4 + i) * Ncols + colBase + tx * 4] = o;
    }
}

// ---------------- edge scatter on x: per-graph CSR (counting sort) ----------
__global__ void scatter_csr(const int* __restrict__ edge) {
    __shared__ int s_src[NEDGE];
    __shared__ int s_dst[NEDGE];
    __shared__ int cnt[NNODE + 1];
    __shared__ int ofs[NNODE + 1];
    __shared__ int o_src[NEDGE];
    __shared__ float o_w[NEDGE];
    int g = blockIdx.x;
    int tid = threadIdx.x;
    const int* eg = edge + (size_t)g * 2 * NEDGE;
    for (int e = tid; e < NEDGE; e += 256) {
        s_src[e] = eg[e];
        s_dst[e] = eg[NEDGE + e];
    }
    for (int i = tid; i <= NNODE; i += 256) cnt[i] = 0;
    __syncthreads();
    for (int e = tid; e < NEDGE; e += 256) atomicAdd(&cnt[s_dst[e]], 1);
    __syncthreads();
    if (tid == 0) {
        int acc = 0;
        for (int n = 0; n <= NNODE; n++) { int c = cnt[n]; ofs[n] = acc; acc += c; }
    }
    __syncthreads();
    for (int i = tid; i < NNODE; i += 256) cnt[i] = ofs[i];
    __syncthreads();
    for (int e = tid; e < NEDGE; e += 256) {
        int p = atomicAdd(&cnt[s_dst[e]], 1);
        o_src[p] = s_src[e];
        o_w[p] = g_ew[g * NEDGE + e];
    }
    __syncthreads();
    int warp = tid >> 5, lane = tid & 31;
    const float* xg = g_x + (size_t)g * NNODE * DD;
    float* ag = g_agg + (size_t)g * NNODE * DD;
    for (int n = warp; n < NNODE; n += 8) {
        float4 acc = make_float4(0.f, 0.f, 0.f, 0.f);
        int s0 = ofs[n], s1 = ofs[n + 1];
        for (int i = s0; i < s1; i++) {
            int src = o_src[i];
            float w = o_w[i];
            float4 v = *(const float4*)&xg[src * DD + lane * 4];
            acc.x += w * v.x; acc.y += w * v.y; acc.z += w * v.z; acc.w += w * v.w;
        }
        *(float4*)&ag[n * DD + lane * 4] = acc;
    }
}

// ---------------- GRU elementwise update -----------------------------------
__global__ void gru_kernel(const float* __restrict__ b_ih, const float* __restrict__ b_hh) {
    int t = blockIdx.x * blockDim.x + threadIdx.x;
    if (t >= GN * 32) return;
    int row = t >> 5;
    int j4 = (t & 31) << 2;
    const float* gg = g_gigh + (size_t)row * 768;
    float4 ir = *(const float4*)&gg[j4];
    float4 iz = *(const float4*)&gg[128 + j4];
    float4 in_ = *(const float4*)&gg[256 + j4];
    float4 hr = *(const float4*)&gg[384 + j4];
    float4 hz = *(const float4*)&gg[512 + j4];
    float4 hn = *(const float4*)&gg[640 + j4];
    float4 bir = *(const float4*)&b_ih[j4];
    float4 biz = *(const float4*)&b_ih[128 + j4];
    float4 bin = *(const float4*)&b_ih[256 + j4];
    float4 bhr = *(const float4*)&b_hh[j4];
    float4 bhz = *(const float4*)&b_hh[128 + j4];
    float4 bhn = *(const float4*)&b_hh[256 + j4];
    float4 xo = *(const float4*)&g_x[(size_t)row * DD + j4];
    float4 xn;
    {
        float r = sigmoidf_(ir.x + bir.x + hr.x + bhr.x);
        float z = sigmoidf_(iz.x + biz.x + hz.x + bhz.x);
        float n = tanhf(in_.x + bin.x + r * (hn.x + bhn.x));
        xn.x = (1.f - z) * n + z * xo.x;
    }
    {
        float r = sigmoidf_(ir.y + bir.y + hr.y + bhr.y);
        float z = sigmoidf_(iz.y + biz.y + hz.y + bhz.y);
        float n = tanhf(in_.y + bin.y + r * (hn.y + bhn.y));
        xn.y = (1.f - z) * n + z * xo.y;
    }
    {
        float r = sigmoidf_(ir.z + bir.z + hr.z + bhr.z);
        float z = sigmoidf_(iz.z + biz.z + hz.z + bhz.z);
        float n = tanhf(in_.z + bin.z + r * (hn.z + bhn.z));
        xn.z = (1.f - z) * n + z * xo.z;
    }
    {
        float r = sigmoidf_(ir.w + bir.w + hr.w + bhr.w);
        float z = sigmoidf_(iz.w + biz.w + hz.w + bhz.w);
        float n = tanhf(in_.w + bin.w + r * (hn.w + bhn.w));
        xn.w = (1.f - z) * n + z * xo.w;
    }
    *(float4*)&g_x[(size_t)row * DD + j4] = xn;
}

// ---------------- attention (block per graph) -------------------------------
__global__ void attn_kernel(const float* __restrict__ c_id,
                            const float* __restrict__ c_embed,
                            const float* __restrict__ concept_embedding) {
    extern __shared__ float smx[];
    float* shg = smx;                       // 200*65
    float* pbuf = shg + NNODE * 65;         // 8*200
    float* qbuf = pbuf + 8 * NNODE;         // 8*64
    float* acc = qbuf + 8 * 64;             // 64
    float* snum = acc + 64;                 // 1
    int g = blockIdx.x;
    int tid = threadIdx.x;
    for (int i = tid; i < NNODE * DCC; i += 256) {
        int n = i >> 6, d = i & 63;
        shg[n * 65 + d] = g_ggnn[(size_t)(g * NNODE + n) * DCC + d];
    }
    if (tid < 64) acc[tid] = 0.f;
    if (tid == 0) snum[0] = 0.f;
    __syncthreads();
    if (tid < CP1N) atomicAdd(snum, c_id[g * CP1N + tid]);
    __syncthreads();
    int warp = tid >> 5, lane = tid & 31;
    for (int c = warp; c < CP1N; c += 8) {
        float ce = c_embed[g * CP1N + c];
        if (ce == 0.f) continue;
        qbuf[warp * 64 + lane] = ce * concept_embedding[c * DCC + lane];
        qbuf[warp * 64 + lane + 32] = ce * concept_embedding[c * DCC + lane + 32];
        __syncwarp();
        float mx = -1e30f;
        for (int n = lane; n < NNODE; n += 32) {
            float s = 0.f;
#pragma unroll 16
            for (int d = 0; d < DCC; d++) s += qbuf[warp * 64 + d] * shg[n * 65 + d];
            pbuf[warp * NNODE + n] = s;
            mx = fmaxf(mx, s);
        }
#pragma unroll
        for (int o = 16; o > 0; o >>= 1) mx = fmaxf(mx, __shfl_xor_sync(0xffffffffu, mx, o));
        float ssum = 0.f;
        for (int n = lane; n < NNODE; n += 32) {
            float p = expf(pbuf[warp * NNODE + n] - mx);
            pbuf[warp * NNODE + n] = p;
            ssum += p;
        }
#pragma unroll
        for (int o = 16; o > 0; o >>= 1) ssum += __shfl_xor_sync(0xffffffffu, ssum, o);
        __syncwarp();
        float inv = ce / ssum;
        float a0 = 0.f, a1 = 0.f;
        for (int n = 0; n < NNODE; n++) {
            float p = pbuf[warp * NNODE + n];
            a0 += p * shg[n * 65 + lane];
            a1 += p * shg[n * 65 + lane + 32];
        }
        atomicAdd(&acc[lane], a0 * inv);
        atomicAdd(&acc[lane + 32], a1 * inv);
        __syncwarp();
    }
    __syncthreads();
    if (tid < DCC) {
        float nv = snum[0];
        if (nv == 0.f) nv = 1.f;
        g_attn[g * DCC + tid] = acc[tid] / nv;
    }
}

// ---------------- LSTM input GEMM (gate-permuted output) -------------------
__global__ void lstm_pre_kernel(const float* __restrict__ c_embed,
                                const float* __restrict__ cur_result,
                                const float* __restrict__ lstm_b_ih) {
    __shared__ float xin[FEATN];
    int s = blockIdx.x;
    int tid = threadIdx.x;
    if (tid < CP1N) xin[tid] = c_embed[s * CP1N + tid];
    else if (tid < CP1N + DCC) xin[tid] = g_attn[s * DCC + (tid - CP1N)];
    else if (tid < FEATN) xin[tid] = cur_result[s * 2 + (tid - CP1N - DCC)];
    __syncthreads();
    int m = blockIdx.y * 256 + tid;
    int q = m & 3, j = m >> 2;
    float acc = lstm_b_ih[q * 256 + j];
    for (int k = 0; k < FEATN; k++) acc += xin[k] * g_LihT[k * 1024 + m];
    g_pre[(size_t)s * 1024 + m] = acc;
}

// ---------------- LSTM recurrence (block per batch element) ----------------
__global__ void lstm_rec_kernel(const float* __restrict__ b_hh) {
    int b = blockIdx.x;
    int j = threadIdx.x;
    __shared__ float sh_h[HHID];
    sh_h[j] = 0.f;
    float c = 0.f;
    float bi = b_hh[j], bf = b_hh[256 + j], bg = b_hh[512 + j], bo = b_hh[768 + j];
    __syncthreads();
    for (int t = 0; t < SLEN; t++) {
        int s = b * SLEN + t;
        float4 acc = *(const float4*)&g_pre[(size_t)s * 1024 + 4 * j];
        acc.x += bi; acc.y += bf; acc.z += bg; acc.w += bo;
#pragma unroll 4
        for (int k = 0; k < HHID; k++) {
            float hk = sh_h[k];
            float4 w = *(const float4*)&g_WhhP[k * 1024 + 4 * j];
            acc.x += hk * w.x; acc.y += hk * w.y; acc.z += hk * w.z; acc.w += hk * w.w;
        }
        float ii = sigmoidf_(acc.x), ff = sigmoidf_(acc.y);
        float gg = tanhf(acc.z), oo = sigmoidf_(acc.w);
        c = ff * c + ii * gg;
        float h = oo * tanhf(c);
        __syncthreads();
        sh_h[j] = h;
        g_hout[(size_t)s * HHID + j] = h;
        __syncthreads();
    }
}

// ---------------- pred + per-sample BCE -------------------------------------
__global__ void pred_kernel(const float* __restrict__ target_c,
                            const float* __restrict__ result,
                            const float* __restrict__ pred_w,
                            const float* __restrict__ pred_b) {
    __shared__ float sh[HHID];
    __shared__ float s_p, s_n;
    int i = blockIdx.x, tid = threadIdx.x;
    sh[tid] = g_hout[(size_t)i * HHID + tid];
    sh[tid + 128] = g_hout[(size_t)i * HHID + tid + 128];
    if (tid == 0) { s_p = 0.f; s_n = 0.f; }
    __syncthreads();
    int warp = tid >> 5, lane = tid & 31;
    float lp = 0.f, ln = 0.f;
    for (int c = warp; c < CP1N; c += 4) {
        float tc = target_c[i * CP1N + c];
        if (tc != 0.f) {
            float s = 0.f;
            for (int d = lane; d < HHID; d += 32) s += pred_w[c * HHID + d] * sh[d];
#pragma unroll
            for (int o = 16; o > 0; o >>= 1) s += __shfl_xor_sync(0xffffffffu, s, o);
            if (lane == 0) { lp += tc * (s + pred_b[c]); ln += tc; }
        }
    }
    if (lane == 0) { atomicAdd(&s_p, lp); atomicAdd(&s_n, ln); }
    __syncthreads();
    if (tid == 0) {
        float nc = s_n;
        int mask = nc > 0.f;
        float fp = s_p / (mask ? nc : 1.f);
        float ft = result[i];
        float bce = fmaxf(fp, 0.f) - fp * ft + log1pf(expf(-fabsf(fp)));
        g_fp[i] = fp;
        g_mf[i] = mask ? 1.f : 0.f;
        g_bce[i] = mask ? bce : 0.f;
    }
}

// ---------------- final reduction + output ----------------------------------
__global__ void final_kernel(const float* __restrict__ result, float* __restrict__ out,
                             int out_size) {
    __shared__ float rb[256], rm[256];
    int tid = threadIdx.x;
    float sb = 0.f, smm = 0.f;
    for (int i = tid; i < GG; i += 256) { sb += g_bce[i]; smm += g_mf[i]; }
    rb[tid] = sb; rm[tid] = smm;
    __syncthreads();
    for (int o = 128; o > 0; o >>= 1) {
        if (tid < o) { rb[tid] += rb[tid + o]; rm[tid] += rm[tid + o]; }
        __syncthreads();
    }
    if (tid == 0 && out_size > 0) out[0] = rb[0] / fmaxf(rm[0], 1.f);
    for (int i = tid; i < GG; i += 256) {
        if (1 + i < out_size) out[1 + i] = 1.f / (1.f + expf(-g_fp[i]));
        if (1 + GG + i < out_size) out[1 + GG + i] = result[i];
    }
}

// ---------------- launcher ---------------------------------------------------
extern "C" void kernel_launch(void* const* d_in, const int* in_sizes, int n_in,
                              void* d_out, int out_size) {
    const float* c_id       = (const float*)d_in[1];
    const int*   node_id    = (const int*)d_in[2];
    const int*   edge       = (const int*)d_in[3];
    const int*   edge_type  = (const int*)d_in[4];
    const float* target_c   = (const float*)d_in[5];
    const float* result     = (const float*)d_in[6];
    const float* c_embed    = (const float*)d_in[7];
    const float* cur_result = (const float*)d_in[8];
    const float* node_embed_w = (const float*)d_in[9];
    const float* edge_embed_w = (const float*)d_in[10];
    const float* ggnn_w     = (const float*)d_in[11];
    const float* gru_w_ih   = (const float*)d_in[12];
    const float* gru_w_hh   = (const float*)d_in[13];
    const float* gru_b_ih   = (const float*)d_in[14];
    const float* gru_b_hh   = (const float*)d_in[15];
    const float* transdim_w = (const float*)d_in[16];
    const float* concept_embedding = (const float*)d_in[17];
    const float* lstm_w_ih  = (const float*)d_in[18];
    const float* lstm_w_hh  = (const float*)d_in[19];
    const float* lstm_b_ih  = (const float*)d_in[20];
    const float* lstm_b_hh  = (const float*)d_in[21];
    const float* pred_w     = (const float*)d_in[22];
    const float* pred_b     = (const float*)d_in[23];
    float* out = (float*)d_out;
    (void)in_sizes; (void)n_in;

    const int GEMM_SMEM = 2 * 128 * 132 * 4;   // 135168 B
    cudaFuncSetAttribute(gemm128, cudaFuncAttributeMaxDynamicSharedMemorySize, GEMM_SMEM);
    cudaFuncSetAttribute(attn_kernel, cudaFuncAttributeMaxDynamicSharedMemorySize, 61440);

    void *px, *pagg, *pgigh, *pWcomb, *pWhhT, *pggnn, *pTdT;
    cudaGetSymbolAddress(&px, g_x);
    cudaGetSymbolAddress(&pagg, g_agg);
    cudaGetSymbolAddress(&pgigh, g_gigh);
    cudaGetSymbolAddress(&pWcomb, g_Wcomb);
    cudaGetSymbolAddress(&pWhhT, g_WhhT);
    cudaGetSymbolAddress(&pggnn, g_ggnn);
    cudaGetSymbolAddress(&pTdT, g_TdT);

    prep_kernel<<<2000, 256>>>(edge_embed_w, gru_w_hh, transdim_w, lstm_w_ih, lstm_w_hh);
    comb_kernel<<<(4 * 128 * 384 + 255) / 256, 256>>>(ggnn_w, gru_w_ih);
    ew_kernel<<<(GG * NEDGE + 255) / 256, 256>>>(edge_type);
    gather_kernel<<<GN / 8, 256>>>(node_id, node_embed_w);

    for (int l = 0; l < 4; l++) {
        // aggx = scatter(ew * x[src])
        scatter_csr<<<GG, 256>>>(edge);
        // gi = aggx @ (W_l @ W_ih^T)   -> gigh[:, 0:384]
        gemm128<<<dim3(GN / 128, 3), 256, GEMM_SMEM>>>(
            (const float*)pagg, (const float*)pWcomb + (size_t)l * 128 * 384,
            (float*)pgigh, 768);
        // gh = x @ W_hh^T              -> gigh[:, 384:768]
        gemm128<<<dim3(GN / 128, 3), 256, GEMM_SMEM>>>(
            (const float*)px, (const float*)pWhhT,
            (float*)pgigh + 384, 768);
        gru_kernel<<<GN * 32 / 256, 256>>>(gru_b_ih, gru_b_hh);
    }

    // ggnn = x @ transdim^T
    gemm_k128<<<dim3(GN / 64, 1), 256>>>((const float*)px, (const float*)pTdT,
                                         (float*)pggnn, 64);
    attn_kernel<<<GG, 256, 61440>>>(c_id, c_embed, concept_embedding);
    lstm_pre_kernel<<<dim3(GG, 4), 256>>>(c_embed, cur_result, lstm_b_ih);
    lstm_rec_kernel<<<BSZ, 256>>>(lstm_b_hh);
    pred_kernel<<<GG, 128>>>(target_c, result, pred_w, pred_b);
    final_kernel<<<1, 256>>>(result, out, out_size);
}

// round 4
// speedup vs baseline: 1.9323x; 1.4255x over previous
#include <cuda_runtime.h>
#include <cuda_bf16.h>
#include <math.h>
#include <stdint.h>

#define BSZ  8
#define SLEN 100
#define GG   800
#define NNODE 200
#define NEDGE 600
#define DD   128
#define DCC  64
#define HHID 256
#define CP1N 111
#define FEATN 177
#define GN   160000

// ---------------- scratch globals -------------------------------------------
__device__ float g_x[(size_t)GN * DD];
__device__ __nv_bfloat16 g_xhi[(size_t)GN * DD];
__device__ __nv_bfloat16 g_xlo[(size_t)GN * DD];
__device__ __nv_bfloat16 g_agghi[(size_t)GN * DD];
__device__ __nv_bfloat16 g_agglo[(size_t)GN * DD];
__device__ __nv_bfloat16 g_CombT_hi[4 * 384 * 128];   // [l][j][k]
__device__ __nv_bfloat16 g_CombT_lo[4 * 384 * 128];
__device__ __nv_bfloat16 g_Whh_hi[384 * 128];         // [j][k]
__device__ __nv_bfloat16 g_Whh_lo[384 * 128];
__device__ float g_ggnn[(size_t)GN * DCC];
__device__ float g_attn[GG * DCC];
__device__ float g_ew[GG * NEDGE];
__device__ float g_mean8[8];
__device__ float g_TdT[128 * 64];
__device__ float g_LihT[FEATN * 1024];
__device__ float g_WhhP[256 * 1024];
__device__ float g_pre[(size_t)GG * 1024];
__device__ float g_hout[(size_t)GG * HHID];
__device__ float g_fp[GG];
__device__ float g_bce[GG];
__device__ float g_mf[GG];

__device__ __forceinline__ float sigmoidf_(float v) { return 1.f / (1.f + expf(-v)); }

__device__ __forceinline__ void cvt_hilo(float v, __nv_bfloat16& h, __nv_bfloat16& l) {
    h = __float2bfloat16_rn(v);
    l = __float2bfloat16_rn(v - __bfloat162float(h));
}

__device__ __forceinline__ uint32_t smem_u32(const void* p) {
    uint32_t a;
    asm("{ .reg .u64 t; cvta.to.shared.u64 t, %1; cvt.u32.u64 %0, t; }" : "=r"(a) : "l"(p));
    return a;
}
__device__ __forceinline__ void ldsm_x4(uint32_t& a0, uint32_t& a1, uint32_t& a2,
                                        uint32_t& a3, uint32_t addr) {
    asm volatile("ldmatrix.sync.aligned.m8n8.x4.shared.b16 {%0,%1,%2,%3}, [%4];"
                 : "=r"(a0), "=r"(a1), "=r"(a2), "=r"(a3) : "r"(addr));
}
__device__ __forceinline__ void ldsm_x2(uint32_t& b0, uint32_t& b1, uint32_t addr) {
    asm volatile("ldmatrix.sync.aligned.m8n8.x2.shared.b16 {%0,%1}, [%2];"
                 : "=r"(b0), "=r"(b1) : "r"(addr));
}
__device__ __forceinline__ void mma16816(float* d, uint32_t a0, uint32_t a1, uint32_t a2,
                                         uint32_t a3, uint32_t b0, uint32_t b1) {
    asm volatile("mma.sync.aligned.m16n8k16.row.col.f32.bf16.bf16.f32 "
                 "{%0,%1,%2,%3}, {%4,%5,%6,%7}, {%8,%9}, {%0,%1,%2,%3};"
                 : "+f"(d[0]), "+f"(d[1]), "+f"(d[2]), "+f"(d[3])
                 : "r"(a0), "r"(a1), "r"(a2), "r"(a3), "r"(b0), "r"(b1));
}

// ---------------- prep -------------------------------------------------------
__global__ void prep_kernel(const float* __restrict__ edge_embed_w,
                            const float* __restrict__ gru_w_hh,
                            const float* __restrict__ transdim_w,
                            const float* __restrict__ lstm_w_ih,
                            const float* __restrict__ lstm_w_hh) {
    const int T3 = 128 * 64, T4 = FEATN * 1024, T5 = 256 * 1024, T6 = 384 * 128;
    int total = 8 + T3 + T4 + T5 + T6;
    for (int i = blockIdx.x * blockDim.x + threadIdx.x; i < total;
         i += gridDim.x * blockDim.x) {
        int t = i;
        if (t < 8) {
            float s = 0.f;
            for (int d = 0; d < DD; d++) s += edge_embed_w[t * DD + d];
            g_mean8[t] = s / (float)DD;
            continue;
        }
        t -= 8;
        if (t < T3) { int k = t / 64, c = t % 64; g_TdT[t] = transdim_w[c * 128 + k]; continue; }
        t -= T3;
        if (t < T4) {
            int k = t / 1024, p = t % 1024; int q = p & 3, j = p >> 2;
            g_LihT[t] = lstm_w_ih[(q * 256 + j) * FEATN + k];
            continue;
        }
        t -= T4;
        if (t < T5) {
            int k = t / 1024, p = t % 1024; int q = p & 3, j = p >> 2;
            g_WhhP[t] = lstm_w_hh[(q * 256 + j) * 256 + k];
            continue;
        }
        t -= T5;
        { __nv_bfloat16 h, l; cvt_hilo(gru_w_hh[t], h, l); g_Whh_hi[t] = h; g_Whh_lo[t] = l; }
    }
}

// CombT[l][j][k] = sum_d W_l[k,d] * W_ih[j,d]
__global__ void comb_kernel(const float* __restrict__ ggnn_w,
                            const float* __restrict__ gru_w_ih) {
    int t = blockIdx.x * blockDim.x + threadIdx.x;
    if (t >= 4 * 384 * 128) return;
    int l = t / (384 * 128); int r = t % (384 * 128);
    int j = r / 128, k = r % 128;
    const float4* wl = (const float4*)(ggnn_w + ((size_t)l * 128 + k) * 128);
    const float4* wi = (const float4*)(gru_w_ih + (size_t)j * 128);
    float s = 0.f;
#pragma unroll 8
    for (int d = 0; d < 32; d++) {
        float4 a = wl[d], b = wi[d];
        s += a.x * b.x + a.y * b.y + a.z * b.z + a.w * b.w;
    }
    __nv_bfloat16 h, lo; cvt_hilo(s, h, lo);
    g_CombT_hi[t] = h; g_CombT_lo[t] = lo;
}

__global__ void ew_kernel(const int* __restrict__ edge_type) {
    int i = blockIdx.x * blockDim.x + threadIdx.x;
    if (i < GG * NEDGE) g_ew[i] = g_mean8[edge_type[i]];
}

// ---------------- gather -----------------------------------------------------
__global__ void gather_kernel(const int* __restrict__ node_id,
                              const float* __restrict__ embed) {
    int warp = threadIdx.x >> 5, lane = threadIdx.x & 31;
    int row = blockIdx.x * 8 + warp;
    if (row >= GN) return;
    int nid = node_id[row];
    float4 v = *(const float4*)&embed[(size_t)nid * DD + lane * 4];
    size_t o = (size_t)row * DD + lane * 4;
    *(float4*)&g_x[o] = v;
    __nv_bfloat16 h0, l0, h1, l1, h2, l2, h3, l3;
    cvt_hilo(v.x, h0, l0); cvt_hilo(v.y, h1, l1);
    cvt_hilo(v.z, h2, l2); cvt_hilo(v.w, h3, l3);
    ((__nv_bfloat162*)&g_xhi[o])[0] = __nv_bfloat162(h0, h1);
    ((__nv_bfloat162*)&g_xhi[o])[1] = __nv_bfloat162(h2, h3);
    ((__nv_bfloat162*)&g_xlo[o])[0] = __nv_bfloat162(l0, l1);
    ((__nv_bfloat162*)&g_xlo[o])[1] = __nv_bfloat162(l2, l3);
}

// ---------------- edge scatter: per-graph CSR --------------------------------
__global__ void scatter_csr(const int* __restrict__ edge) {
    __shared__ int s_src[NEDGE];
    __shared__ int s_dst[NEDGE];
    __shared__ int cnt[NNODE + 1];
    __shared__ int ofs[NNODE + 1];
    __shared__ int o_src[NEDGE];
    __shared__ float o_w[NEDGE];
    int g = blockIdx.x;
    int tid = threadIdx.x;
    const int* eg = edge + (size_t)g * 2 * NEDGE;
    for (int e = tid; e < NEDGE; e += 256) { s_src[e] = eg[e]; s_dst[e] = eg[NEDGE + e]; }
    for (int i = tid; i <= NNODE; i += 256) cnt[i] = 0;
    __syncthreads();
    for (int e = tid; e < NEDGE; e += 256) atomicAdd(&cnt[s_dst[e]], 1);
    __syncthreads();
    if (tid == 0) {
        int acc = 0;
        for (int n = 0; n <= NNODE; n++) { int c = cnt[n]; ofs[n] = acc; acc += c; }
    }
    __syncthreads();
    for (int i = tid; i < NNODE; i += 256) cnt[i] = ofs[i];
    __syncthreads();
    for (int e = tid; e < NEDGE; e += 256) {
        int p = atomicAdd(&cnt[s_dst[e]], 1);
        o_src[p] = s_src[e];
        o_w[p] = g_ew[g * NEDGE + e];
    }
    __syncthreads();
    int warp = tid >> 5, lane = tid & 31;
    const float* xg = g_x + (size_t)g * NNODE * DD;
    for (int n = warp; n < NNODE; n += 8) {
        float4 acc = make_float4(0.f, 0.f, 0.f, 0.f);
        int s0 = ofs[n], s1 = ofs[n + 1];
        for (int i = s0; i < s1; i++) {
            int src = o_src[i];
            float w = o_w[i];
            float4 v = *(const float4*)&xg[src * DD + lane * 4];
            acc.x += w * v.x; acc.y += w * v.y; acc.z += w * v.z; acc.w += w * v.w;
        }
        size_t o = ((size_t)(g * NNODE + n)) * DD + lane * 4;
        __nv_bfloat16 h0, l0, h1, l1, h2, l2, h3, l3;
        cvt_hilo(acc.x, h0, l0); cvt_hilo(acc.y, h1, l1);
        cvt_hilo(acc.z, h2, l2); cvt_hilo(acc.w, h3, l3);
        ((__nv_bfloat162*)&g_agghi[o])[0] = __nv_bfloat162(h0, h1);
        ((__nv_bfloat162*)&g_agghi[o])[1] = __nv_bfloat162(h2, h3);
        ((__nv_bfloat162*)&g_agglo[o])[0] = __nv_bfloat162(l0, l1);
        ((__nv_bfloat162*)&g_agglo[o])[1] = __nv_bfloat162(l2, l3);
    }
}

// ---------------- fused HMMA GGNN layer: 2 GEMMs + GRU ----------------------
// smem: A tiles (aggh,aggl,xh,xl) each [64r x 128k] bf16 = 16KB at 0/16K/32K/48K
//       B tiles hi/lo each [128j x 128k] bf16 = 32KB at 64K/96K; bias @128K (512 f)
#define SMA_AGH 0
#define SMA_AGL 16384
#define SMA_XH  32768
#define SMA_XL  49152
#define SMB_H   65536
#define SMB_L   98304
#define SMB_BIA 131072
#define SM_TOT  (131072 + 2048)

__global__ void __launch_bounds__(256, 1) layer_mma(int layer,
                                                    const float* __restrict__ b_ih,
                                                    const float* __restrict__ b_hh) {
    extern __shared__ __align__(128) char smx[];
    uint32_t sbase = smem_u32(smx);
    int tid = threadIdx.x, wid = tid >> 5, lane = tid & 31;
    int rowBase = blockIdx.x * 64;
    int rg = wid >> 1;            // 0..3: 16-row group
    int cg = wid & 1;             // 0..1: 64-col group
    float* sb = (float*)(smx + SMB_BIA);
    if (tid < 128) {
        sb[tid]       = b_ih[tid] + b_hh[tid];
        sb[128 + tid] = b_ih[128 + tid] + b_hh[128 + tid];
        sb[256 + tid] = b_ih[256 + tid];
        sb[384 + tid] = b_hh[256 + tid];
    }
    // load A tiles with XOR-16B swizzle
    {
        const uint4* s0 = (const uint4*)(g_agghi + (size_t)rowBase * 128);
        const uint4* s1 = (const uint4*)(g_agglo + (size_t)rowBase * 128);
        const uint4* s2 = (const uint4*)(g_xhi + (size_t)rowBase * 128);
        const uint4* s3 = (const uint4*)(g_xlo + (size_t)rowBase * 128);
#pragma unroll
        for (int q = 0; q < 4; q++) {
            int i = tid + 256 * q;          // 1024 chunks per tile
            int r = i >> 4, c = i & 15;
            uint32_t off = r * 256 + ((c ^ (r & 7)) << 4);
            *(uint4*)(smx + SMA_AGH + off) = s0[i];
            *(uint4*)(smx + SMA_AGL + off) = s1[i];
            *(uint4*)(smx + SMA_XH + off) = s2[i];
            *(uint4*)(smx + SMA_XL + off) = s3[i];
        }
    }

    float acc[4][8][4];
#pragma unroll
    for (int b = 0; b < 4; b++)
#pragma unroll
        for (int n = 0; n < 8; n++)
#pragma unroll
            for (int e = 0; e < 4; e++) acc[b][n][e] = 0.f;

    const int rloc = rg * 16;
    // A ldmatrix address pieces (lane-dependent)
    const int a_r = rloc + (lane & 15);
    const int a_kh = lane >> 4;
    // B ldmatrix: n row + k-half per lane
    const int b_nl = lane & 7;
    const int b_kh = (lane >> 3) & 1;

#pragma unroll
    for (int chunk = 0; chunk < 6; chunk++) {
        const int j0 = (chunk < 2) ? 0 : (chunk < 4) ? 128 : 256;
        const bool isComb = (chunk == 0) || (chunk == 2) || (chunk == 4);
        const int bank = (chunk < 2) ? 0 : (chunk < 4) ? 1 : (chunk == 4) ? 2 : 3;
        const __nv_bfloat16* bh_src = isComb ? (g_CombT_hi + ((size_t)layer * 384 + j0) * 128)
                                             : (g_Whh_hi + (size_t)j0 * 128);
        const __nv_bfloat16* bl_src = isComb ? (g_CombT_lo + ((size_t)layer * 384 + j0) * 128)
                                             : (g_Whh_lo + (size_t)j0 * 128);
        __syncthreads();   // prior chunk's reads done before overwriting B
        {
            const uint4* bh4 = (const uint4*)bh_src;
            const uint4* bl4 = (const uint4*)bl_src;
#pragma unroll
            for (int q = 0; q < 8; q++) {
                int i = tid + 256 * q;      // 2048 chunks per B tile
                int r = i >> 4, c = i & 15;
                uint32_t off = r * 256 + ((c ^ (r & 7)) << 4);
                *(uint4*)(smx + SMB_H + off) = bh4[i];
                *(uint4*)(smx + SMB_L + off) = bl4[i];
            }
        }
        __syncthreads();
        const uint32_t aHi = sbase + (isComb ? SMA_AGH : SMA_XH);
        const uint32_t aLo = sbase + (isComb ? SMA_AGL : SMA_XL);
        for (int ks = 0; ks < 8; ks++) {
            uint32_t ach = (uint32_t)(((ks * 2 + a_kh) ^ (a_r & 7)) << 4) + a_r * 256;
            uint32_t ah0, ah1, ah2, ah3, al0, al1, al2, al3;
            ldsm_x4(ah0, ah1, ah2, ah3, aHi + ach);
            ldsm_x4(al0, al1, al2, al3, aLo + ach);
#pragma unroll
            for (int nt = 0; nt < 8; nt++) {
                int n = cg * 64 + nt * 8 + b_nl;
                uint32_t boff = (uint32_t)n * 256 + (uint32_t)(((ks * 2 + b_kh) ^ (n & 7)) << 4);
                uint32_t bh0, bh1, bl0, bl1;
                ldsm_x2(bh0, bh1, sbase + SMB_H + boff);
                ldsm_x2(bl0, bl1, sbase + SMB_L + boff);
                mma16816(acc[bank][nt], ah0, ah1, ah2, ah3, bh0, bh1);
                mma16816(acc[bank][nt], al0, al1, al2, al3, bh0, bh1);
                mma16816(acc[bank][nt], ah0, ah1, ah2, ah3, bl0, bl1);
            }
        }
    }

    // ---------- GRU epilogue in registers ----------
    int tq = lane >> 2, tr = lane & 3;
#pragma unroll
    for (int nt = 0; nt < 8; nt++) {
        int j = cg * 64 + nt * 8 + tr * 2;
#pragma unroll
        for (int h = 0; h < 2; h++) {
            int m = rowBase + rg * 16 + tq + h * 8;
            float r0 = sigmoidf_(acc[0][nt][2 * h] + sb[j]);
            float r1 = sigmoidf_(acc[0][nt][2 * h + 1] + sb[j + 1]);
            float z0 = sigmoidf_(acc[1][nt][2 * h] + sb[128 + j]);
            float z1 = sigmoidf_(acc[1][nt][2 * h + 1] + sb[128 + j + 1]);
            float n0 = tanhf(acc[2][nt][2 * h] + sb[256 + j] +
                             r0 * (acc[3][nt][2 * h] + sb[384 + j]));
            float n1 = tanhf(acc[2][nt][2 * h + 1] + sb[256 + j + 1] +
                             r1 * (acc[3][nt][2 * h + 1] + sb[384 + j + 1]));
            size_t o = (size_t)m * 128 + j;
            float2 xo = *(const float2*)&g_x[o];
            float xn0 = (1.f - z0) * n0 + z0 * xo.x;
            float xn1 = (1.f - z1) * n1 + z1 * xo.y;
            *(float2*)&g_x[o] = make_float2(xn0, xn1);
            __nv_bfloat16 h0, l0, h1, l1;
            cvt_hilo(xn0, h0, l0); cvt_hilo(xn1, h1, l1);
            *(__nv_bfloat162*)&g_xhi[o] = __nv_bfloat162(h0, h1);
            *(__nv_bfloat162*)&g_xlo[o] = __nv_bfloat162(l0, l1);
        }
    }
}

// ---------------- transdim GEMM (fp32, N=64) ---------------------------------
__global__ void gemm_k128(const float* __restrict__ A, const float* __restrict__ B,
                          float* __restrict__ C, int Ncols) {
    __shared__ float Ast[64][68];
    __shared__ float Bs[64][64];
    int tid = threadIdx.x;
    int tx = tid & 15, ty = tid >> 4;
    int rowBase = blockIdx.x * 64;
    int colBase = blockIdx.y * 64;
    float acc[4][4] = {};
    for (int kc = 0; kc < 2; kc++) {
        {
            int c4 = tid & 15;
            int r0 = tid >> 4;
#pragma unroll
            for (int rr = 0; rr < 4; rr++) {
                int row = r0 + 16 * rr;
                float4 v = *(const float4*)&A[(size_t)(rowBase + row) * 128 + kc * 64 + c4 * 4];
                Ast[c4 * 4 + 0][row] = v.x;
                Ast[c4 * 4 + 1][row] = v.y;
                Ast[c4 * 4 + 2][row] = v.z;
                Ast[c4 * 4 + 3][row] = v.w;
            }
#pragma unroll
            for (int kk2 = 0; kk2 < 4; kk2++) {
                int kr = r0 + 16 * kk2;
                float4 v = *(const float4*)&B[(size_t)(kc * 64 + kr) * Ncols + colBase + c4 * 4];
                *(float4*)&Bs[kr][c4 * 4] = v;
            }
        }
        __syncthreads();
#pragma unroll 8
        for (int kk = 0; kk < 64; kk++) {
            float4 a = *(const float4*)&Ast[kk][ty * 4];
            float4 b = *(const float4*)&Bs[kk][tx * 4];
            float av[4] = {a.x, a.y, a.z, a.w};
            float bv[4] = {b.x, b.y, b.z, b.w};
#pragma unroll
            for (int i = 0; i < 4; i++)
#pragma unroll
                for (int j = 0; j < 4; j++) acc[i][j] += av[i] * bv[j];
        }
        __syncthreads();
    }
#pragma unroll
    for (int i = 0; i < 4; i++) {
        float4 o = make_float4(acc[i][0], acc[i][1], acc[i][2], acc[i][3]);
        *(float4*)&C[(size_t)(rowBase + ty * 4 + i) * Ncols + colBase + tx * 4] = o;
    }
}

// ---------------- attention --------------------------------------------------
__global__ void attn_kernel(const float* __restrict__ c_id,
                            const float* __restrict__ c_embed,
                            const float* __restrict__ concept_embedding) {
    extern __shared__ float smf[];
    float* shg = smf;
    float* pbuf = shg + NNODE * 65;
    float* qbuf = pbuf + 8 * NNODE;
    float* acc = qbuf + 8 * 64;
    float* snum = acc + 64;
    int g = blockIdx.x;
    int tid = threadIdx.x;
    for (int i = tid; i < NNODE * DCC; i += 256) {
        int n = i >> 6, d = i & 63;
        shg[n * 65 + d] = g_ggnn[(size_t)(g * NNODE + n) * DCC + d];
    }
    if (tid < 64) acc[tid] = 0.f;
    if (tid == 0) snum[0] = 0.f;
    __syncthreads();
    if (tid < CP1N) atomicAdd(snum, c_id[g * CP1N + tid]);
    __syncthreads();
    int warp = tid >> 5, lane = tid & 31;
    for (int c = warp; c < CP1N; c += 8) {
        float ce = c_embed[g * CP1N + c];
        if (ce == 0.f) continue;
        qbuf[warp * 64 + lane] = ce * concept_embedding[c * DCC + lane];
        qbuf[warp * 64 + lane + 32] = ce * concept_embedding[c * DCC + lane + 32];
        __syncwarp();
        float mx = -1e30f;
        for (int n = lane; n < NNODE; n += 32) {
            float s = 0.f;
#pragma unroll 16
            for (int d = 0; d < DCC; d++) s += qbuf[warp * 64 + d] * shg[n * 65 + d];
            pbuf[warp * NNODE + n] = s;
            mx = fmaxf(mx, s);
        }
#pragma unroll
        for (int o = 16; o > 0; o >>= 1) mx = fmaxf(mx, __shfl_xor_sync(0xffffffffu, mx, o));
        float ssum = 0.f;
        for (int n = lane; n < NNODE; n += 32) {
            float p = expf(pbuf[warp * NNODE + n] - mx);
            pbuf[warp * NNODE + n] = p;
            ssum += p;
        }
#pragma unroll
        for (int o = 16; o > 0; o >>= 1) ssum += __shfl_xor_sync(0xffffffffu, ssum, o);
        __syncwarp();
        float inv = ce / ssum;
        float a0 = 0.f, a1 = 0.f;
        for (int n = 0; n < NNODE; n++) {
            float p = pbuf[warp * NNODE + n];
            a0 += p * shg[n * 65 + lane];
            a1 += p * shg[n * 65 + lane + 32];
        }
        atomicAdd(&acc[lane], a0 * inv);
        atomicAdd(&acc[lane + 32], a1 * inv);
        __syncwarp();
    }
    __syncthreads();
    if (tid < DCC) {
        float nv = snum[0];
        if (nv == 0.f) nv = 1.f;
        g_attn[g * DCC + tid] = acc[tid] / nv;
    }
}

// ---------------- LSTM -------------------------------------------------------
__global__ void lstm_pre_kernel(const float* __restrict__ c_embed,
                                const float* __restrict__ cur_result,
                                const float* __restrict__ lstm_b_ih) {
    __shared__ float xin[FEATN];
    int s = blockIdx.x;
    int tid = threadIdx.x;
    if (tid < CP1N) xin[tid] = c_embed[s * CP1N + tid];
    else if (tid < CP1N + DCC) xin[tid] = g_attn[s * DCC + (tid - CP1N)];
    else if (tid < FEATN) xin[tid] = cur_result[s * 2 + (tid - CP1N - DCC)];
    __syncthreads();
    int m = blockIdx.y * 256 + tid;
    int q = m & 3, j = m >> 2;
    float acc = lstm_b_ih[q * 256 + j];
    for (int k = 0; k < FEATN; k++) acc += xin[k] * g_LihT[k * 1024 + m];
    g_pre[(size_t)s * 1024 + m] = acc;
}

__global__ void lstm_rec_kernel(const float* __restrict__ b_hh) {
    int b = blockIdx.x;
    int j = threadIdx.x;
    __shared__ float sh_h[HHID];
    sh_h[j] = 0.f;
    float c = 0.f;
    float bi = b_hh[j], bf = b_hh[256 + j], bg = b_hh[512 + j], bo = b_hh[768 + j];
    __syncthreads();
    for (int t = 0; t < SLEN; t++) {
        int s = b * SLEN + t;
        float4 acc = *(const float4*)&g_pre[(size_t)s * 1024 + 4 * j];
        acc.x += bi; acc.y += bf; acc.z += bg; acc.w += bo;
#pragma unroll 4
        for (int k = 0; k < HHID; k++) {
            float hk = sh_h[k];
            float4 w = *(const float4*)&g_WhhP[k * 1024 + 4 * j];
            acc.x += hk * w.x; acc.y += hk * w.y; acc.z += hk * w.z; acc.w += hk * w.w;
        }
        float ii = sigmoidf_(acc.x), ff = sigmoidf_(acc.y);
        float gg = tanhf(acc.z), oo = sigmoidf_(acc.w);
        c = ff * c + ii * gg;
        float h = oo * tanhf(c);
        __syncthreads();
        sh_h[j] = h;
        g_hout[(size_t)s * HHID + j] = h;
        __syncthreads();
    }
}

// ---------------- pred + BCE + final -----------------------------------------
__global__ void pred_kernel(const float* __restrict__ target_c,
                            const float* __restrict__ result,
                            const float* __restrict__ pred_w,
                            const float* __restrict__ pred_b) {
    __shared__ float sh[HHID];
    __shared__ float s_p, s_n;
    int i = blockIdx.x, tid = threadIdx.x;
    sh[tid] = g_hout[(size_t)i * HHID + tid];
    sh[tid + 128] = g_hout[(size_t)i * HHID + tid + 128];
    if (tid == 0) { s_p = 0.f; s_n = 0.f; }
    __syncthreads();
    int warp = tid >> 5, lane = tid & 31;
    float lp = 0.f, ln = 0.f;
    for (int c = warp; c < CP1N; c += 4) {
        float tc = target_c[i * CP1N + c];
        if (tc != 0.f) {
            float s = 0.f;
            for (int d = lane; d < HHID; d += 32) s += pred_w[c * HHID + d] * sh[d];
#pragma unroll
            for (int o = 16; o > 0; o >>= 1) s += __shfl_xor_sync(0xffffffffu, s, o);
            if (lane == 0) { lp += tc * (s + pred_b[c]); ln += tc; }
        }
    }
    if (lane == 0) { atomicAdd(&s_p, lp); atomicAdd(&s_n, ln); }
    __syncthreads();
    if (tid == 0) {
        float nc = s_n;
        int mask = nc > 0.f;
        float fp = s_p / (mask ? nc : 1.f);
        float ft = result[i];
        float bce = fmaxf(fp, 0.f) - fp * ft + log1pf(expf(-fabsf(fp)));
        g_fp[i] = fp;
        g_mf[i] = mask ? 1.f : 0.f;
        g_bce[i] = mask ? bce : 0.f;
    }
}

__global__ void final_kernel(const float* __restrict__ result, float* __restrict__ out,
                             int out_size) {
    __shared__ float rb[256], rm[256];
    int tid = threadIdx.x;
    float sb = 0.f, smm = 0.f;
    for (int i = tid; i < GG; i += 256) { sb += g_bce[i]; smm += g_mf[i]; }
    rb[tid] = sb; rm[tid] = smm;
    __syncthreads();
    for (int o = 128; o > 0; o >>= 1) {
        if (tid < o) { rb[tid] += rb[tid + o]; rm[tid] += rm[tid + o]; }
        __syncthreads();
    }
    if (tid == 0 && out_size > 0) out[0] = rb[0] / fmaxf(rm[0], 1.f);
    for (int i = tid; i < GG; i += 256) {
        if (1 + i < out_size) out[1 + i] = 1.f / (1.f + expf(-g_fp[i]));
        if (1 + GG + i < out_size) out[1 + GG + i] = result[i];
    }
}

// ---------------- launcher ---------------------------------------------------
extern "C" void kernel_launch(void* const* d_in, const int* in_sizes, int n_in,
                              void* d_out, int out_size) {
    const float* c_id       = (const float*)d_in[1];
    const int*   node_id    = (const int*)d_in[2];
    const int*   edge       = (const int*)d_in[3];
    const int*   edge_type  = (const int*)d_in[4];
    const float* target_c   = (const float*)d_in[5];
    const float* result     = (const float*)d_in[6];
    const float* c_embed    = (const float*)d_in[7];
    const float* cur_result = (const float*)d_in[8];
    const float* node_embed_w = (const float*)d_in[9];
    const float* edge_embed_w = (const float*)d_in[10];
    const float* ggnn_w     = (const float*)d_in[11];
    const float* gru_w_ih   = (const float*)d_in[12];
    const float* gru_w_hh   = (const float*)d_in[13];
    const float* gru_b_ih   = (const float*)d_in[14];
    const float* gru_b_hh   = (const float*)d_in[15];
    const float* transdim_w = (const float*)d_in[16];
    const float* concept_embedding = (const float*)d_in[17];
    const float* lstm_w_ih  = (const float*)d_in[18];
    const float* lstm_w_hh  = (const float*)d_in[19];
    const float* lstm_b_ih  = (const float*)d_in[20];
    const float* lstm_b_hh  = (const float*)d_in[21];
    const float* pred_w     = (const float*)d_in[22];
    const float* pred_b     = (const float*)d_in[23];
    float* out = (float*)d_out;
    (void)in_sizes; (void)n_in;

    cudaFuncSetAttribute(layer_mma, cudaFuncAttributeMaxDynamicSharedMemorySize, SM_TOT);
    cudaFuncSetAttribute(attn_kernel, cudaFuncAttributeMaxDynamicSharedMemorySize, 61440);

    void *px, *pggnn, *pTdT;
    cudaGetSymbolAddress(&px, g_x);
    cudaGetSymbolAddress(&pggnn, g_ggnn);
    cudaGetSymbolAddress(&pTdT, g_TdT);

    prep_kernel<<<1960, 256>>>(edge_embed_w, gru_w_hh, transdim_w, lstm_w_ih, lstm_w_hh);
    comb_kernel<<<(4 * 384 * 128 + 255) / 256, 256>>>(ggnn_w, gru_w_ih);
    ew_kernel<<<(GG * NEDGE + 255) / 256, 256>>>(edge_type);
    gather_kernel<<<GN / 8, 256>>>(node_id, node_embed_w);

    for (int l = 0; l < 4; l++) {
        scatter_csr<<<GG, 256>>>(edge);
        layer_mma<<<GN / 64, 256, SM_TOT>>>(l, gru_b_ih, gru_b_hh);
    }

    gemm_k128<<<dim3(GN / 64, 1), 256>>>((const float*)px, (const float*)pTdT,
                                         (float*)pggnn, 64);
    attn_kernel<<<GG, 256, 61440>>>(c_id, c_embed, concept_embedding);
    lstm_pre_kernel<<<dim3(GG, 4), 256>>>(c_embed, cur_result, lstm_b_ih);
    lstm_rec_kernel<<<BSZ, 256>>>(lstm_b_hh);
    pred_kernel<<<GG, 128>>>(target_c, result, pred_w, pred_b);
    final_kernel<<<1, 256>>>(result, out, out_size);
}

// round 5
// speedup vs baseline: 3.3555x; 1.7366x over previous
#include <cuda_runtime.h>
#include <cuda_bf16.h>
#include <math.h>
#include <stdint.h>

#define BSZ  8
#define SLEN 100
#define GG   800
#define NNODE 200
#define NEDGE 600
#define DD   128
#define DCC  64
#define HHID 256
#define CP1N 111
#define FEATN 177
#define GN   160000

// ---------------- scratch globals -------------------------------------------
__device__ float g_x[(size_t)GN * DD];
__device__ __nv_bfloat16 g_xhi[(size_t)GN * DD];
__device__ __nv_bfloat16 g_xlo[(size_t)GN * DD];
__device__ __nv_bfloat16 g_agghi[(size_t)GN * DD];
__device__ __nv_bfloat16 g_agglo[(size_t)GN * DD];
__device__ __nv_bfloat16 g_CombT_hi[4 * 384 * 128];   // [l][j][k]
__device__ __nv_bfloat16 g_CombT_lo[4 * 384 * 128];
__device__ __nv_bfloat16 g_Whh_hi[384 * 128];         // [j][k]
__device__ __nv_bfloat16 g_Whh_lo[384 * 128];
__device__ float g_ggnn[(size_t)GN * DCC];
__device__ float g_attn[GG * DCC];
__device__ float g_ew[GG * NEDGE];
__device__ float g_mean8[8];
__device__ float g_TdT[128 * 64];
__device__ float g_LihT[FEATN * 1024];
__device__ float g_WhhP[256 * 1024];
__device__ float g_pre[(size_t)GG * 1024];
__device__ float g_hout[(size_t)GG * HHID];
__device__ float g_fp[GG];
__device__ float g_bce[GG];
__device__ float g_mf[GG];

__device__ __forceinline__ float sigmoidf_(float v) { return 1.f / (1.f + expf(-v)); }

__device__ __forceinline__ void cvt_hilo(float v, __nv_bfloat16& h, __nv_bfloat16& l) {
    h = __float2bfloat16_rn(v);
    l = __float2bfloat16_rn(v - __bfloat162float(h));
}

__device__ __forceinline__ uint32_t smem_u32(const void* p) {
    uint32_t a;
    asm("{ .reg .u64 t; cvta.to.shared.u64 t, %1; cvt.u32.u64 %0, t; }" : "=r"(a) : "l"(p));
    return a;
}
__device__ __forceinline__ void ldsm_x4(uint32_t& a0, uint32_t& a1, uint32_t& a2,
                                        uint32_t& a3, uint32_t addr) {
    asm volatile("ldmatrix.sync.aligned.m8n8.x4.shared.b16 {%0,%1,%2,%3}, [%4];"
                 : "=r"(a0), "=r"(a1), "=r"(a2), "=r"(a3) : "r"(addr));
}
__device__ __forceinline__ void mma16816(float* d, uint32_t a0, uint32_t a1, uint32_t a2,
                                         uint32_t a3, uint32_t b0, uint32_t b1) {
    asm volatile("mma.sync.aligned.m16n8k16.row.col.f32.bf16.bf16.f32 "
                 "{%0,%1,%2,%3}, {%4,%5,%6,%7}, {%8,%9}, {%0,%1,%2,%3};"
                 : "+f"(d[0]), "+f"(d[1]), "+f"(d[2]), "+f"(d[3])
                 : "r"(a0), "r"(a1), "r"(a2), "r"(a3), "r"(b0), "r"(b1));
}
#define CLUSTER_BAR() do { \
    asm volatile("barrier.cluster.arrive.aligned;" ::: "memory"); \
    asm volatile("barrier.cluster.wait.aligned;" ::: "memory"); \
} while (0)

// ---------------- prep -------------------------------------------------------
__global__ void prep_kernel(const float* __restrict__ edge_embed_w,
                            const float* __restrict__ gru_w_hh,
                            const float* __restrict__ transdim_w,
                            const float* __restrict__ lstm_w_ih,
                            const float* __restrict__ lstm_w_hh) {
    const int T3 = 128 * 64, T4 = FEATN * 1024, T5 = 256 * 1024, T6 = 384 * 128;
    int total = 8 + T3 + T4 + T5 + T6;
    for (int i = blockIdx.x * blockDim.x + threadIdx.x; i < total;
         i += gridDim.x * blockDim.x) {
        int t = i;
        if (t < 8) {
            float s = 0.f;
            for (int d = 0; d < DD; d++) s += edge_embed_w[t * DD + d];
            g_mean8[t] = s / (float)DD;
            continue;
        }
        t -= 8;
        if (t < T3) { int k = t / 64, c = t % 64; g_TdT[t] = transdim_w[c * 128 + k]; continue; }
        t -= T3;
        if (t < T4) {
            int k = t / 1024, p = t % 1024; int q = p & 3, j = p >> 2;
            g_LihT[t] = lstm_w_ih[(q * 256 + j) * FEATN + k];
            continue;
        }
        t -= T4;
        if (t < T5) {
            int k = t / 1024, p = t % 1024; int q = p & 3, j = p >> 2;
            g_WhhP[t] = lstm_w_hh[(q * 256 + j) * 256 + k];
            continue;
        }
        t -= T5;
        { __nv_bfloat16 h, l; cvt_hilo(gru_w_hh[t], h, l); g_Whh_hi[t] = h; g_Whh_lo[t] = l; }
    }
}

// CombT[l][j][k] = sum_d W_l[k,d] * W_ih[j,d]
__global__ void comb_kernel(const float* __restrict__ ggnn_w,
                            const float* __restrict__ gru_w_ih) {
    int t = blockIdx.x * blockDim.x + threadIdx.x;
    if (t >= 4 * 384 * 128) return;
    int l = t / (384 * 128); int r = t % (384 * 128);
    int j = r / 128, k = r % 128;
    const float4* wl = (const float4*)(ggnn_w + ((size_t)l * 128 + k) * 128);
    const float4* wi = (const float4*)(gru_w_ih + (size_t)j * 128);
    float s = 0.f;
#pragma unroll 8
    for (int d = 0; d < 32; d++) {
        float4 a = wl[d], b = wi[d];
        s += a.x * b.x + a.y * b.y + a.z * b.z + a.w * b.w;
    }
    __nv_bfloat16 h, lo; cvt_hilo(s, h, lo);
    g_CombT_hi[t] = h; g_CombT_lo[t] = lo;
}

__global__ void ew_kernel(const int* __restrict__ edge_type) {
    int i = blockIdx.x * blockDim.x + threadIdx.x;
    if (i < GG * NEDGE) g_ew[i] = g_mean8[edge_type[i]];
}

// ---------------- gather -----------------------------------------------------
__global__ void gather_kernel(const int* __restrict__ node_id,
                              const float* __restrict__ embed) {
    int warp = threadIdx.x >> 5, lane = threadIdx.x & 31;
    int row = blockIdx.x * 8 + warp;
    if (row >= GN) return;
    int nid = node_id[row];
    float4 v = *(const float4*)&embed[(size_t)nid * DD + lane * 4];
    size_t o = (size_t)row * DD + lane * 4;
    *(float4*)&g_x[o] = v;
    __nv_bfloat16 h0, l0, h1, l1, h2, l2, h3, l3;
    cvt_hilo(v.x, h0, l0); cvt_hilo(v.y, h1, l1);
    cvt_hilo(v.z, h2, l2); cvt_hilo(v.w, h3, l3);
    ((__nv_bfloat162*)&g_xhi[o])[0] = __nv_bfloat162(h0, h1);
    ((__nv_bfloat162*)&g_xhi[o])[1] = __nv_bfloat162(h2, h3);
    ((__nv_bfloat162*)&g_xlo[o])[0] = __nv_bfloat162(l0, l1);
    ((__nv_bfloat162*)&g_xlo[o])[1] = __nv_bfloat162(l2, l3);
}

// ---------------- edge scatter: smem-resident x tile + per-graph CSR ---------
__global__ void __launch_bounds__(256, 1) scatter_csr(const int* __restrict__ edge) {
    extern __shared__ float sx[];     // 200*128 floats = 102400 B
    __shared__ int s_src[NEDGE];
    __shared__ int s_dst[NEDGE];
    __shared__ int cnt[NNODE + 1];
    __shared__ int ofs[NNODE + 1];
    __shared__ int o_src[NEDGE];
    __shared__ float o_w[NEDGE];
    int g = blockIdx.x;
    int tid = threadIdx.x;
    const int* eg = edge + (size_t)g * 2 * NEDGE;
    // stage x tile for this graph
    {
        const float4* xg4 = (const float4*)(g_x + (size_t)g * NNODE * DD);
        float4* sx4 = (float4*)sx;
#pragma unroll
        for (int q = 0; q < 25; q++) sx4[tid + 256 * q] = xg4[tid + 256 * q];
    }
    for (int e = tid; e < NEDGE; e += 256) { s_src[e] = eg[e]; s_dst[e] = eg[NEDGE + e]; }
    for (int i = tid; i <= NNODE; i += 256) cnt[i] = 0;
    __syncthreads();
    for (int e = tid; e < NEDGE; e += 256) atomicAdd(&cnt[s_dst[e]], 1);
    __syncthreads();
    if (tid == 0) {
        int acc = 0;
        for (int n = 0; n <= NNODE; n++) { int c = cnt[n]; ofs[n] = acc; acc += c; }
    }
    __syncthreads();
    for (int i = tid; i < NNODE; i += 256) cnt[i] = ofs[i];
    __syncthreads();
    for (int e = tid; e < NEDGE; e += 256) {
        int p = atomicAdd(&cnt[s_dst[e]], 1);
        o_src[p] = s_src[e];
        o_w[p] = g_ew[g * NEDGE + e];
    }
    __syncthreads();
    int warp = tid >> 5, lane = tid & 31;
    for (int n = warp; n < NNODE; n += 8) {
        float4 acc = make_float4(0.f, 0.f, 0.f, 0.f);
        int s0 = ofs[n], s1 = ofs[n + 1];
        for (int i = s0; i < s1; i++) {
            int src = o_src[i];
            float w = o_w[i];
            float4 v = *(const float4*)&sx[src * DD + lane * 4];
            acc.x += w * v.x; acc.y += w * v.y; acc.z += w * v.z; acc.w += w * v.w;
        }
        size_t o = ((size_t)(g * NNODE + n)) * DD + lane * 4;
        __nv_bfloat16 h0, l0, h1, l1, h2, l2, h3, l3;
        cvt_hilo(acc.x, h0, l0); cvt_hilo(acc.y, h1, l1);
        cvt_hilo(acc.z, h2, l2); cvt_hilo(acc.w, h3, l3);
        ((__nv_bfloat162*)&g_agghi[o])[0] = __nv_bfloat162(h0, h1);
        ((__nv_bfloat162*)&g_agghi[o])[1] = __nv_bfloat162(h2, h3);
        ((__nv_bfloat162*)&g_agglo[o])[0] = __nv_bfloat162(l0, l1);
        ((__nv_bfloat162*)&g_agglo[o])[1] = __nv_bfloat162(l2, l3);
    }
}

// ---------------- fused HMMA GGNN layer: 2 GEMMs + GRU ----------------------
#define SMA_AGH 0
#define SMA_AGL 16384
#define SMA_XH  32768
#define SMA_XL  49152
#define SMB_H   65536
#define SMB_L   98304
#define SMB_BIA 131072
#define SM_TOT  (131072 + 2048)

__global__ void __launch_bounds__(256, 1) layer_mma(int layer,
                                                    const float* __restrict__ b_ih,
                                                    const float* __restrict__ b_hh) {
    extern __shared__ __align__(128) char smx[];
    uint32_t sbase = smem_u32(smx);
    int tid = threadIdx.x, wid = tid >> 5, lane = tid & 31;
    int rowBase = blockIdx.x * 64;
    int rg = wid >> 1;            // 0..3: 16-row group
    int cg = wid & 1;             // 0..1: 64-col group
    float* sb = (float*)(smx + SMB_BIA);
    if (tid < 128) {
        sb[tid]       = b_ih[tid] + b_hh[tid];
        sb[128 + tid] = b_ih[128 + tid] + b_hh[128 + tid];
        sb[256 + tid] = b_ih[256 + tid];
        sb[384 + tid] = b_hh[256 + tid];
    }
    // load A tiles with XOR-16B swizzle
    {
        const uint4* s0 = (const uint4*)(g_agghi + (size_t)rowBase * 128);
        const uint4* s1 = (const uint4*)(g_agglo + (size_t)rowBase * 128);
        const uint4* s2 = (const uint4*)(g_xhi + (size_t)rowBase * 128);
        const uint4* s3 = (const uint4*)(g_xlo + (size_t)rowBase * 128);
#pragma unroll
        for (int q = 0; q < 4; q++) {
            int i = tid + 256 * q;
            int r = i >> 4, c = i & 15;
            uint32_t off = r * 256 + ((c ^ (r & 7)) << 4);
            *(uint4*)(smx + SMA_AGH + off) = s0[i];
            *(uint4*)(smx + SMA_AGL + off) = s1[i];
            *(uint4*)(smx + SMA_XH + off) = s2[i];
            *(uint4*)(smx + SMA_XL + off) = s3[i];
        }
    }

    float acc[4][8][4];
#pragma unroll
    for (int b = 0; b < 4; b++)
#pragma unroll
        for (int n = 0; n < 8; n++)
#pragma unroll
            for (int e = 0; e < 4; e++) acc[b][n][e] = 0.f;

    const int rloc = rg * 16;
    const int a_r = rloc + (lane & 15);
    const int a_kh = lane >> 4;
    // B ldsm_x4: lane group 0..3 -> (nt offset, k-half)
    const int b_grp = lane >> 3;
    const int b_nt_off = b_grp >> 1;     // 0 or 1
    const int b_kh = b_grp & 1;
    const int b_nl = lane & 7;

#pragma unroll
    for (int chunk = 0; chunk < 6; chunk++) {
        const int j0 = (chunk < 2) ? 0 : (chunk < 4) ? 128 : 256;
        const bool isComb = (chunk == 0) || (chunk == 2) || (chunk == 4);
        const int bank = (chunk < 2) ? 0 : (chunk < 4) ? 1 : (chunk == 4) ? 2 : 3;
        const __nv_bfloat16* bh_src = isComb ? (g_CombT_hi + ((size_t)layer * 384 + j0) * 128)
                                             : (g_Whh_hi + (size_t)j0 * 128);
        const __nv_bfloat16* bl_src = isComb ? (g_CombT_lo + ((size_t)layer * 384 + j0) * 128)
                                             : (g_Whh_lo + (size_t)j0 * 128);
        __syncthreads();
        {
            const uint4* bh4 = (const uint4*)bh_src;
            const uint4* bl4 = (const uint4*)bl_src;
#pragma unroll
            for (int q = 0; q < 8; q++) {
                int i = tid + 256 * q;
                int r = i >> 4, c = i & 15;
                uint32_t off = r * 256 + ((c ^ (r & 7)) << 4);
                *(uint4*)(smx + SMB_H + off) = bh4[i];
                *(uint4*)(smx + SMB_L + off) = bl4[i];
            }
        }
        __syncthreads();
        const uint32_t aHi = sbase + (isComb ? SMA_AGH : SMA_XH);
        const uint32_t aLo = sbase + (isComb ? SMA_AGL : SMA_XL);
        for (int ks = 0; ks < 8; ks++) {
            uint32_t ach = (uint32_t)(((ks * 2 + a_kh) ^ (a_r & 7)) << 4) + a_r * 256;
            uint32_t ah0, ah1, ah2, ah3, al0, al1, al2, al3;
            ldsm_x4(ah0, ah1, ah2, ah3, aHi + ach);
            ldsm_x4(al0, al1, al2, al3, aLo + ach);
#pragma unroll
            for (int nt2 = 0; nt2 < 8; nt2 += 2) {
                int n = cg * 64 + (nt2 + b_nt_off) * 8 + b_nl;
                uint32_t boff = (uint32_t)n * 256 + (uint32_t)(((ks * 2 + b_kh) ^ (n & 7)) << 4);
                uint32_t bh0, bh1, bh2, bh3, bl0, bl1, bl2, bl3;
                ldsm_x4(bh0, bh1, bh2, bh3, sbase + SMB_H + boff);
                ldsm_x4(bl0, bl1, bl2, bl3, sbase + SMB_L + boff);
                mma16816(acc[bank][nt2], ah0, ah1, ah2, ah3, bh0, bh1);
                mma16816(acc[bank][nt2], al0, al1, al2, al3, bh0, bh1);
                mma16816(acc[bank][nt2], ah0, ah1, ah2, ah3, bl0, bl1);
                mma16816(acc[bank][nt2 + 1], ah0, ah1, ah2, ah3, bh2, bh3);
                mma16816(acc[bank][nt2 + 1], al0, al1, al2, al3, bh2, bh3);
                mma16816(acc[bank][nt2 + 1], ah0, ah1, ah2, ah3, bl2, bl3);
            }
        }
    }

    // ---------- GRU epilogue in registers ----------
    int tq = lane >> 2, tr = lane & 3;
#pragma unroll
    for (int nt = 0; nt < 8; nt++) {
        int j = cg * 64 + nt * 8 + tr * 2;
#pragma unroll
        for (int h = 0; h < 2; h++) {
            int m = rowBase + rg * 16 + tq + h * 8;
            float r0 = sigmoidf_(acc[0][nt][2 * h] + sb[j]);
            float r1 = sigmoidf_(acc[0][nt][2 * h + 1] + sb[j + 1]);
            float z0 = sigmoidf_(acc[1][nt][2 * h] + sb[128 + j]);
            float z1 = sigmoidf_(acc[1][nt][2 * h + 1] + sb[128 + j + 1]);
            float n0 = tanhf(acc[2][nt][2 * h] + sb[256 + j] +
                             r0 * (acc[3][nt][2 * h] + sb[384 + j]));
            float n1 = tanhf(acc[2][nt][2 * h + 1] + sb[256 + j + 1] +
                             r1 * (acc[3][nt][2 * h + 1] + sb[384 + j + 1]));
            size_t o = (size_t)m * 128 + j;
            float2 xo = *(const float2*)&g_x[o];
            float xn0 = (1.f - z0) * n0 + z0 * xo.x;
            float xn1 = (1.f - z1) * n1 + z1 * xo.y;
            *(float2*)&g_x[o] = make_float2(xn0, xn1);
            __nv_bfloat16 h0, l0, h1, l1;
            cvt_hilo(xn0, h0, l0); cvt_hilo(xn1, h1, l1);
            *(__nv_bfloat162*)&g_xhi[o] = __nv_bfloat162(h0, h1);
            *(__nv_bfloat162*)&g_xlo[o] = __nv_bfloat162(l0, l1);
        }
    }
}

// ---------------- transdim GEMM (fp32, N=64) ---------------------------------
__global__ void gemm_k128(const float* __restrict__ A, const float* __restrict__ B,
                          float* __restrict__ C, int Ncols) {
    __shared__ float Ast[64][68];
    __shared__ float Bs[64][64];
    int tid = threadIdx.x;
    int tx = tid & 15, ty = tid >> 4;
    int rowBase = blockIdx.x * 64;
    int colBase = blockIdx.y * 64;
    float acc[4][4] = {};
    for (int kc = 0; kc < 2; kc++) {
        {
            int c4 = tid & 15;
            int r0 = tid >> 4;
#pragma unroll
            for (int rr = 0; rr < 4; rr++) {
                int row = r0 + 16 * rr;
                float4 v = *(const float4*)&A[(size_t)(rowBase + row) * 128 + kc * 64 + c4 * 4];
                Ast[c4 * 4 + 0][row] = v.x;
                Ast[c4 * 4 + 1][row] = v.y;
                Ast[c4 * 4 + 2][row] = v.z;
                Ast[c4 * 4 + 3][row] = v.w;
            }
#pragma unroll
            for (int kk2 = 0; kk2 < 4; kk2++) {
                int kr = r0 + 16 * kk2;
                float4 v = *(const float4*)&B[(size_t)(kc * 64 + kr) * Ncols + colBase + c4 * 4];
                *(float4*)&Bs[kr][c4 * 4] = v;
            }
        }
        __syncthreads();
#pragma unroll 8
        for (int kk = 0; kk < 64; kk++) {
            float4 a = *(const float4*)&Ast[kk][ty * 4];
            float4 b = *(const float4*)&Bs[kk][tx * 4];
            float av[4] = {a.x, a.y, a.z, a.w};
            float bv[4] = {b.x, b.y, b.z, b.w};
#pragma unroll
            for (int i = 0; i < 4; i++)
#pragma unroll
                for (int j = 0; j < 4; j++) acc[i][j] += av[i] * bv[j];
        }
        __syncthreads();
    }
#pragma unroll
    for (int i = 0; i < 4; i++) {
        float4 o = make_float4(acc[i][0], acc[i][1], acc[i][2], acc[i][3]);
        *(float4*)&C[(size_t)(rowBase + ty * 4 + i) * Ncols + colBase + tx * 4] = o;
    }
}

// ---------------- attention --------------------------------------------------
__global__ void attn_kernel(const float* __restrict__ c_id,
                            const float* __restrict__ c_embed,
                            const float* __restrict__ concept_embedding) {
    extern __shared__ float smf[];
    float* shg = smf;
    float* pbuf = shg + NNODE * 65;
    float* qbuf = pbuf + 8 * NNODE;
    float* acc = qbuf + 8 * 64;
    float* snum = acc + 64;
    int g = blockIdx.x;
    int tid = threadIdx.x;
    for (int i = tid; i < NNODE * DCC; i += 256) {
        int n = i >> 6, d = i & 63;
        shg[n * 65 + d] = g_ggnn[(size_t)(g * NNODE + n) * DCC + d];
    }
    if (tid < 64) acc[tid] = 0.f;
    if (tid == 0) snum[0] = 0.f;
    __syncthreads();
    if (tid < CP1N) atomicAdd(snum, c_id[g * CP1N + tid]);
    __syncthreads();
    int warp = tid >> 5, lane = tid & 31;
    for (int c = warp; c < CP1N; c += 8) {
        float ce = c_embed[g * CP1N + c];
        if (ce == 0.f) continue;
        qbuf[warp * 64 + lane] = ce * concept_embedding[c * DCC + lane];
        qbuf[warp * 64 + lane + 32] = ce * concept_embedding[c * DCC + lane + 32];
        __syncwarp();
        float mx = -1e30f;
        for (int n = lane; n < NNODE; n += 32) {
            float s = 0.f;
#pragma unroll 16
            for (int d = 0; d < DCC; d++) s += qbuf[warp * 64 + d] * shg[n * 65 + d];
            pbuf[warp * NNODE + n] = s;
            mx = fmaxf(mx, s);
        }
#pragma unroll
        for (int o = 16; o > 0; o >>= 1) mx = fmaxf(mx, __shfl_xor_sync(0xffffffffu, mx, o));
        float ssum = 0.f;
        for (int n = lane; n < NNODE; n += 32) {
            float p = expf(pbuf[warp * NNODE + n] - mx);
            pbuf[warp * NNODE + n] = p;
            ssum += p;
        }
#pragma unroll
        for (int o = 16; o > 0; o >>= 1) ssum += __shfl_xor_sync(0xffffffffu, ssum, o);
        __syncwarp();
        float inv = ce / ssum;
        float a0 = 0.f, a1 = 0.f;
        for (int n = 0; n < NNODE; n++) {
            float p = pbuf[warp * NNODE + n];
            a0 += p * shg[n * 65 + lane];
            a1 += p * shg[n * 65 + lane + 32];
        }
        atomicAdd(&acc[lane], a0 * inv);
        atomicAdd(&acc[lane + 32], a1 * inv);
        __syncwarp();
    }
    __syncthreads();
    if (tid < DCC) {
        float nv = snum[0];
        if (nv == 0.f) nv = 1.f;
        g_attn[g * DCC + tid] = acc[tid] / nv;
    }
}

// ---------------- LSTM -------------------------------------------------------
__global__ void lstm_pre_kernel(const float* __restrict__ c_embed,
                                const float* __restrict__ cur_result,
                                const float* __restrict__ lstm_b_ih) {
    __shared__ float xin[FEATN];
    int s = blockIdx.x;
    int tid = threadIdx.x;
    if (tid < CP1N) xin[tid] = c_embed[s * CP1N + tid];
    else if (tid < CP1N + DCC) xin[tid] = g_attn[s * DCC + (tid - CP1N)];
    else if (tid < FEATN) xin[tid] = cur_result[s * 2 + (tid - CP1N - DCC)];
    __syncthreads();
    int m = blockIdx.y * 256 + tid;
    int q = m & 3, j = m >> 2;
    float acc = lstm_b_ih[q * 256 + j];
    for (int k = 0; k < FEATN; k++) acc += xin[k] * g_LihT[k * 1024 + m];
    g_pre[(size_t)s * 1024 + m] = acc;
}

// LSTM recurrence: cluster of 8 CTAs per batch element; each CTA holds a
// 128-column fp32 W_hh slice (256x128 = 128KB) in smem; h replicated per CTA,
// exchanged via DSMEM stores + cluster barriers.
__global__ void __cluster_dims__(8, 1, 1) __launch_bounds__(128, 1)
lstm_rec_kernel(const float* __restrict__ b_hh) {
    extern __shared__ float sml[];
    float* sW = sml;                 // 256*128
    float* sh = sml + 256 * 128;     // 256 (full h, replicated)
    int tid = threadIdx.x;
    int r = blockIdx.x & 7;          // cluster rank
    int b = blockIdx.x >> 3;         // batch element
    for (int i = tid; i < 256 * 128; i += 128)
        sW[i] = g_WhhP[(size_t)(i >> 7) * 1024 + r * 128 + (i & 127)];
    for (int i = tid; i < 256; i += 128) sh[i] = 0.f;
    int q = tid & 3, jl = tid >> 2;
    int jg = r * 32 + jl;
    float bias = b_hh[q * 256 + jg];
    float c = 0.f;
    uint32_t sh_my = smem_u32(&sh[jg]);
    __syncthreads();
    CLUSTER_BAR();
    int lbase = (tid & 31) & ~3;
    for (int t = 0; t < SLEN; t++) {
        int s = b * SLEN + t;
        float acc = g_pre[(size_t)s * 1024 + r * 128 + tid] + bias;
#pragma unroll 8
        for (int k = 0; k < 256; k++) acc += sh[k] * sW[k * 128 + tid];
        float vi = __shfl_sync(0xffffffffu, acc, lbase + 0);
        float vf = __shfl_sync(0xffffffffu, acc, lbase + 1);
        float vg = __shfl_sync(0xffffffffu, acc, lbase + 2);
        float vo = __shfl_sync(0xffffffffu, acc, lbase + 3);
        CLUSTER_BAR();                 // all CTAs done reading sh
        if (q == 0) {
            c = sigmoidf_(vf) * c + sigmoidf_(vi) * tanhf(vg);
            float h = sigmoidf_(vo) * tanhf(c);
            g_hout[(size_t)s * HHID + jg] = h;
#pragma unroll
            for (int dst = 0; dst < 8; dst++) {
                uint32_t rem;
                asm("mapa.shared::cluster.u32 %0, %1, %2;" : "=r"(rem)
                    : "r"(sh_my), "r"(dst));
                asm volatile("st.shared::cluster.f32 [%0], %1;" :: "r"(rem), "f"(h)
                             : "memory");
            }
        }
        CLUSTER_BAR();                 // new h visible everywhere
    }
}

// ---------------- pred + BCE + final -----------------------------------------
__global__ void pred_kernel(const float* __restrict__ target_c,
                            const float* __restrict__ result,
                            const float* __restrict__ pred_w,
                            const float* __restrict__ pred_b) {
    __shared__ float sh[HHID];
    __shared__ float s_p, s_n;
    int i = blockIdx.x, tid = threadIdx.x;
    sh[tid] = g_hout[(size_t)i * HHID + tid];
    sh[tid + 128] = g_hout[(size_t)i * HHID + tid + 128];
    if (tid == 0) { s_p = 0.f; s_n = 0.f; }
    __syncthreads();
    int warp = tid >> 5, lane = tid & 31;
    float lp = 0.f, ln = 0.f;
    for (int c = warp; c < CP1N; c += 4) {
        float tc = target_c[i * CP1N + c];
        if (tc != 0.f) {
            float s = 0.f;
            for (int d = lane; d < HHID; d += 32) s += pred_w[c * HHID + d] * sh[d];
#pragma unroll
            for (int o = 16; o > 0; o >>= 1) s += __shfl_xor_sync(0xffffffffu, s, o);
            if (lane == 0) { lp += tc * (s + pred_b[c]); ln += tc; }
        }
    }
    if (lane == 0) { atomicAdd(&s_p, lp); atomicAdd(&s_n, ln); }
    __syncthreads();
    if (tid == 0) {
        float nc = s_n;
        int mask = nc > 0.f;
        float fp = s_p / (mask ? nc : 1.f);
        float ft = result[i];
        float bce = fmaxf(fp, 0.f) - fp * ft + log1pf(expf(-fabsf(fp)));
        g_fp[i] = fp;
        g_mf[i] = mask ? 1.f : 0.f;
        g_bce[i] = mask ? bce : 0.f;
    }
}

__global__ void final_kernel(const float* __restrict__ result, float* __restrict__ out,
                             int out_size) {
    __shared__ float rb[256], rm[256];
    int tid = threadIdx.x;
    float sb = 0.f, smm = 0.f;
    for (int i = tid; i < GG; i += 256) { sb += g_bce[i]; smm += g_mf[i]; }
    rb[tid] = sb; rm[tid] = smm;
    __syncthreads();
    for (int o = 128; o > 0; o >>= 1) {
        if (tid < o) { rb[tid] += rb[tid + o]; rm[tid] += rm[tid + o]; }
        __syncthreads();
    }
    if (tid == 0 && out_size > 0) out[0] = rb[0] / fmaxf(rm[0], 1.f);
    for (int i = tid; i < GG; i += 256) {
        if (1 + i < out_size) out[1 + i] = 1.f / (1.f + expf(-g_fp[i]));
        if (1 + GG + i < out_size) out[1 + GG + i] = result[i];
    }
}

// ---------------- launcher ---------------------------------------------------
extern "C" void kernel_launch(void* const* d_in, const int* in_sizes, int n_in,
                              void* d_out, int out_size) {
    const float* c_id       = (const float*)d_in[1];
    const int*   node_id    = (const int*)d_in[2];
    const int*   edge       = (const int*)d_in[3];
    const int*   edge_type  = (const int*)d_in[4];
    const float* target_c   = (const float*)d_in[5];
    const float* result     = (const float*)d_in[6];
    const float* c_embed    = (const float*)d_in[7];
    const float* cur_result = (const float*)d_in[8];
    const float* node_embed_w = (const float*)d_in[9];
    const float* edge_embed_w = (const float*)d_in[10];
    const float* ggnn_w     = (const float*)d_in[11];
    const float* gru_w_ih   = (const float*)d_in[12];
    const float* gru_w_hh   = (const float*)d_in[13];
    const float* gru_b_ih   = (const float*)d_in[14];
    const float* gru_b_hh   = (const float*)d_in[15];
    const float* transdim_w = (const float*)d_in[16];
    const float* concept_embedding = (const float*)d_in[17];
    const float* lstm_w_ih  = (const float*)d_in[18];
    const float* lstm_w_hh  = (const float*)d_in[19];
    const float* lstm_b_ih  = (const float*)d_in[20];
    const float* lstm_b_hh  = (const float*)d_in[21];
    const float* pred_w     = (const float*)d_in[22];
    const float* pred_b     = (const float*)d_in[23];
    float* out = (float*)d_out;
    (void)in_sizes; (void)n_in;

    const int SCAT_SMEM = NNODE * DD * 4;            // 102400
    const int LSTM_SMEM = 256 * 128 * 4 + 256 * 4;   // 132096
    cudaFuncSetAttribute(layer_mma, cudaFuncAttributeMaxDynamicSharedMemorySize, SM_TOT);
    cudaFuncSetAttribute(attn_kernel, cudaFuncAttributeMaxDynamicSharedMemorySize, 61440);
    cudaFuncSetAttribute(scatter_csr, cudaFuncAttributeMaxDynamicSharedMemorySize, SCAT_SMEM);
    cudaFuncSetAttribute(lstm_rec_kernel, cudaFuncAttributeMaxDynamicSharedMemorySize,
                         LSTM_SMEM);

    void *px, *pggnn, *pTdT;
    cudaGetSymbolAddress(&px, g_x);
    cudaGetSymbolAddress(&pggnn, g_ggnn);
    cudaGetSymbolAddress(&pTdT, g_TdT);

    prep_kernel<<<1960, 256>>>(edge_embed_w, gru_w_hh, transdim_w, lstm_w_ih, lstm_w_hh);
    comb_kernel<<<(4 * 384 * 128 + 255) / 256, 256>>>(ggnn_w, gru_w_ih);
    ew_kernel<<<(GG * NEDGE + 255) / 256, 256>>>(edge_type);
    gather_kernel<<<GN / 8, 256>>>(node_id, node_embed_w);

    for (int l = 0; l < 4; l++) {
        scatter_csr<<<GG, 256, SCAT_SMEM>>>(edge);
        layer_mma<<<GN / 64, 256, SM_TOT>>>(l, gru_b_ih, gru_b_hh);
    }

    gemm_k128<<<dim3(GN / 64, 1), 256>>>((const float*)px, (const float*)pTdT,
                                         (float*)pggnn, 64);
    attn_kernel<<<GG, 256, 61440>>>(c_id, c_embed, concept_embedding);
    lstm_pre_kernel<<<dim3(GG, 4), 256>>>(c_embed, cur_result, lstm_b_ih);
    lstm_rec_kernel<<<BSZ * 8, 128, LSTM_SMEM>>>(lstm_b_hh);
    pred_kernel<<<GG, 128>>>(target_c, result, pred_w, pred_b);
    final_kernel<<<1, 256>>>(result, out, out_size);
}

// round 6
// speedup vs baseline: 3.6281x; 1.0812x over previous
#include <cuda_runtime.h>
#include <cuda_bf16.h>
#include <math.h>
#include <stdint.h>

#define BSZ  8
#define SLEN 100
#define GG   800
#define NNODE 200
#define NEDGE 600
#define DD   128
#define DCC  64
#define HHID 256
#define CP1N 111
#define FEATN 177
#define GN   160000

// ---------------- scratch globals -------------------------------------------
__device__ float g_x[(size_t)GN * DD];
__device__ __nv_bfloat16 g_xhi[(size_t)GN * DD];
__device__ __nv_bfloat16 g_xlo[(size_t)GN * DD];
__device__ __nv_bfloat16 g_agghi[(size_t)GN * DD];
__device__ __nv_bfloat16 g_agglo[(size_t)GN * DD];
__device__ __nv_bfloat16 g_CombT_hi[4 * 384 * 128];   // [l][j][k]
__device__ __nv_bfloat16 g_CombT_lo[4 * 384 * 128];
__device__ __nv_bfloat16 g_Whh_hi[384 * 128];         // [j][k]
__device__ __nv_bfloat16 g_Whh_lo[384 * 128];
__device__ float g_ggnn[(size_t)GN * DCC];
__device__ float g_attn[GG * DCC];
__device__ float g_mean8[8];
__device__ float g_TdT[128 * 64];
__device__ float g_LihT[FEATN * 1024];
__device__ float g_WhhP[256 * 1024];
__device__ float g_pre[(size_t)GG * 1024];
__device__ float g_hout[(size_t)GG * HHID];
__device__ float g_fp[GG];
__device__ float g_bce[GG];
__device__ float g_mf[GG];

__device__ __forceinline__ float sigmoidf_(float v) { return 1.f / (1.f + expf(-v)); }

__device__ __forceinline__ void cvt_hilo(float v, __nv_bfloat16& h, __nv_bfloat16& l) {
    h = __float2bfloat16_rn(v);
    l = __float2bfloat16_rn(v - __bfloat162float(h));
}

__device__ __forceinline__ uint32_t smem_u32(const void* p) {
    uint32_t a;
    asm("{ .reg .u64 t; cvta.to.shared.u64 t, %1; cvt.u32.u64 %0, t; }" : "=r"(a) : "l"(p));
    return a;
}
__device__ __forceinline__ void ldsm_x4(uint32_t& a0, uint32_t& a1, uint32_t& a2,
                                        uint32_t& a3, uint32_t addr) {
    asm volatile("ldmatrix.sync.aligned.m8n8.x4.shared.b16 {%0,%1,%2,%3}, [%4];"
                 : "=r"(a0), "=r"(a1), "=r"(a2), "=r"(a3) : "r"(addr));
}
__device__ __forceinline__ void mma16816(float* d, uint32_t a0, uint32_t a1, uint32_t a2,
                                         uint32_t a3, uint32_t b0, uint32_t b1) {
    asm volatile("mma.sync.aligned.m16n8k16.row.col.f32.bf16.bf16.f32 "
                 "{%0,%1,%2,%3}, {%4,%5,%6,%7}, {%8,%9}, {%0,%1,%2,%3};"
                 : "+f"(d[0]), "+f"(d[1]), "+f"(d[2]), "+f"(d[3])
                 : "r"(a0), "r"(a1), "r"(a2), "r"(a3), "r"(b0), "r"(b1));
}
__device__ __forceinline__ void cp_async16(uint32_t saddr, const void* gaddr) {
    asm volatile("cp.async.cg.shared.global [%0], [%1], 16;" :: "r"(saddr), "l"(gaddr));
}
#define CP_COMMIT() asm volatile("cp.async.commit_group;" ::: "memory")
#define CP_WAIT(n)  asm volatile("cp.async.wait_group %0;" :: "n"(n) : "memory")
#define CLUSTER_BAR() do { \
    asm volatile("barrier.cluster.arrive.aligned;" ::: "memory"); \
    asm volatile("barrier.cluster.wait.aligned;" ::: "memory"); \
} while (0)

// ---------------- prep -------------------------------------------------------
__global__ void prep_kernel(const float* __restrict__ edge_embed_w,
                            const float* __restrict__ gru_w_hh,
                            const float* __restrict__ transdim_w,
                            const float* __restrict__ lstm_w_ih,
                            const float* __restrict__ lstm_w_hh) {
    const int T3 = 128 * 64, T4 = FEATN * 1024, T5 = 256 * 1024, T6 = 384 * 128;
    int total = 8 + T3 + T4 + T5 + T6;
    for (int i = blockIdx.x * blockDim.x + threadIdx.x; i < total;
         i += gridDim.x * blockDim.x) {
        int t = i;
        if (t < 8) {
            float s = 0.f;
            for (int d = 0; d < DD; d++) s += edge_embed_w[t * DD + d];
            g_mean8[t] = s / (float)DD;
            continue;
        }
        t -= 8;
        if (t < T3) { int k = t / 64, c = t % 64; g_TdT[t] = transdim_w[c * 128 + k]; continue; }
        t -= T3;
        if (t < T4) {
            int k = t / 1024, p = t % 1024; int q = p & 3, j = p >> 2;
            g_LihT[t] = lstm_w_ih[(q * 256 + j) * FEATN + k];
            continue;
        }
        t -= T4;
        if (t < T5) {
            int k = t / 1024, p = t % 1024; int q = p & 3, j = p >> 2;
            g_WhhP[t] = lstm_w_hh[(q * 256 + j) * 256 + k];
            continue;
        }
        t -= T5;
        { __nv_bfloat16 h, l; cvt_hilo(gru_w_hh[t], h, l); g_Whh_hi[t] = h; g_Whh_lo[t] = l; }
    }
}

// CombT[l][j][k] = sum_d W_l[k,d] * W_ih[j,d]
__global__ void comb_kernel(const float* __restrict__ ggnn_w,
                            const float* __restrict__ gru_w_ih) {
    int t = blockIdx.x * blockDim.x + threadIdx.x;
    if (t >= 4 * 384 * 128) return;
    int l = t / (384 * 128); int r = t % (384 * 128);
    int j = r / 128, k = r % 128;
    const float4* wl = (const float4*)(ggnn_w + ((size_t)l * 128 + k) * 128);
    const float4* wi = (const float4*)(gru_w_ih + (size_t)j * 128);
    float s = 0.f;
#pragma unroll 8
    for (int d = 0; d < 32; d++) {
        float4 a = wl[d], b = wi[d];
        s += a.x * b.x + a.y * b.y + a.z * b.z + a.w * b.w;
    }
    __nv_bfloat16 h, lo; cvt_hilo(s, h, lo);
    g_CombT_hi[t] = h; g_CombT_lo[t] = lo;
}

// ---------------- gather -----------------------------------------------------
__global__ void gather_kernel(const int* __restrict__ node_id,
                              const float* __restrict__ embed) {
    int warp = threadIdx.x >> 5, lane = threadIdx.x & 31;
    int row = blockIdx.x * 8 + warp;
    if (row >= GN) return;
    int nid = node_id[row];
    float4 v = *(const float4*)&embed[(size_t)nid * DD + lane * 4];
    size_t o = (size_t)row * DD + lane * 4;
    *(float4*)&g_x[o] = v;
    __nv_bfloat16 h0, l0, h1, l1, h2, l2, h3, l3;
    cvt_hilo(v.x, h0, l0); cvt_hilo(v.y, h1, l1);
    cvt_hilo(v.z, h2, l2); cvt_hilo(v.w, h3, l3);
    ((__nv_bfloat162*)&g_xhi[o])[0] = __nv_bfloat162(h0, h1);
    ((__nv_bfloat162*)&g_xhi[o])[1] = __nv_bfloat162(h2, h3);
    ((__nv_bfloat162*)&g_xlo[o])[0] = __nv_bfloat162(l0, l1);
    ((__nv_bfloat162*)&g_xlo[o])[1] = __nv_bfloat162(l2, l3);
}

// ---------------- edge scatter: smem x tile + CSR + inline edge weights ------
__global__ void __launch_bounds__(256, 1) scatter_csr(const int* __restrict__ edge,
                                                      const int* __restrict__ edge_type) {
    extern __shared__ float sx[];     // 200*128 floats
    __shared__ int s_src[NEDGE];
    __shared__ int s_dst[NEDGE];
    __shared__ int cnt[NNODE + 1];
    __shared__ int ofs[NNODE + 1];
    __shared__ int o_src[NEDGE];
    __shared__ float o_w[NEDGE];
    __shared__ float sm8[8];
    int g = blockIdx.x;
    int tid = threadIdx.x;
    const int* eg = edge + (size_t)g * 2 * NEDGE;
    {
        const float4* xg4 = (const float4*)(g_x + (size_t)g * NNODE * DD);
        float4* sx4 = (float4*)sx;
#pragma unroll
        for (int q = 0; q < 25; q++) sx4[tid + 256 * q] = xg4[tid + 256 * q];
    }
    if (tid < 8) sm8[tid] = g_mean8[tid];
    for (int e = tid; e < NEDGE; e += 256) { s_src[e] = eg[e]; s_dst[e] = eg[NEDGE + e]; }
    for (int i = tid; i <= NNODE; i += 256) cnt[i] = 0;
    __syncthreads();
    for (int e = tid; e < NEDGE; e += 256) atomicAdd(&cnt[s_dst[e]], 1);
    __syncthreads();
    if (tid == 0) {
        int acc = 0;
        for (int n = 0; n <= NNODE; n++) { int c = cnt[n]; ofs[n] = acc; acc += c; }
    }
    __syncthreads();
    for (int i = tid; i < NNODE; i += 256) cnt[i] = ofs[i];
    __syncthreads();
    for (int e = tid; e < NEDGE; e += 256) {
        int p = atomicAdd(&cnt[s_dst[e]], 1);
        o_src[p] = s_src[e];
        o_w[p] = sm8[edge_type[(size_t)g * NEDGE + e]];
    }
    __syncthreads();
    int warp = tid >> 5, lane = tid & 31;
    for (int n = warp; n < NNODE; n += 8) {
        float4 acc = make_float4(0.f, 0.f, 0.f, 0.f);
        int s0 = ofs[n], s1 = ofs[n + 1];
        for (int i = s0; i < s1; i++) {
            int src = o_src[i];
            float w = o_w[i];
            float4 v = *(const float4*)&sx[src * DD + lane * 4];
            acc.x += w * v.x; acc.y += w * v.y; acc.z += w * v.z; acc.w += w * v.w;
        }
        size_t o = ((size_t)(g * NNODE + n)) * DD + lane * 4;
        __nv_bfloat16 h0, l0, h1, l1, h2, l2, h3, l3;
        cvt_hilo(acc.x, h0, l0); cvt_hilo(acc.y, h1, l1);
        cvt_hilo(acc.z, h2, l2); cvt_hilo(acc.w, h3, l3);
        ((__nv_bfloat162*)&g_agghi[o])[0] = __nv_bfloat162(h0, h1);
        ((__nv_bfloat162*)&g_agghi[o])[1] = __nv_bfloat162(h2, h3);
        ((__nv_bfloat162*)&g_agglo[o])[0] = __nv_bfloat162(l0, l1);
        ((__nv_bfloat162*)&g_agglo[o])[1] = __nv_bfloat162(l2, l3);
    }
}

// ---------------- fused HMMA GGNN layer: double-buffered B ------------------
#define SMA_AGH 0
#define SMA_AGL 16384
#define SMA_XH  32768
#define SMA_XL  49152
#define SMB0    65536
#define SMB1    131072
#define SMB_BIA 196608
#define SM_TOT  (196608 + 2048)

__global__ void __launch_bounds__(256, 1) layer_mma(int layer,
                                                    const float* __restrict__ b_ih,
                                                    const float* __restrict__ b_hh) {
    extern __shared__ __align__(128) char smx[];
    uint32_t sbase = smem_u32(smx);
    int tid = threadIdx.x, wid = tid >> 5, lane = tid & 31;
    int rowBase = blockIdx.x * 64;
    int rg = wid >> 1;
    int cg = wid & 1;
    float* sb = (float*)(smx + SMB_BIA);
    if (tid < 128) {
        sb[tid]       = b_ih[tid] + b_hh[tid];
        sb[128 + tid] = b_ih[128 + tid] + b_hh[128 + tid];
        sb[256 + tid] = b_ih[256 + tid];
        sb[384 + tid] = b_hh[256 + tid];
    }
    // async A tiles (swizzled)
    {
        const __nv_bfloat16* s0 = g_agghi + (size_t)rowBase * 128;
        const __nv_bfloat16* s1 = g_agglo + (size_t)rowBase * 128;
        const __nv_bfloat16* s2 = g_xhi + (size_t)rowBase * 128;
        const __nv_bfloat16* s3 = g_xlo + (size_t)rowBase * 128;
#pragma unroll
        for (int q = 0; q < 4; q++) {
            int i = tid + 256 * q;
            int r = i >> 4, c = i & 15;
            uint32_t off = r * 256 + ((c ^ (r & 7)) << 4);
            cp_async16(sbase + SMA_AGH + off, s0 + i * 8);
            cp_async16(sbase + SMA_AGL + off, s1 + i * 8);
            cp_async16(sbase + SMA_XH + off, s2 + i * 8);
            cp_async16(sbase + SMA_XL + off, s3 + i * 8);
        }
    }
    // async B chunk loader
    auto load_b = [&](int c) {
        int j0 = (c >> 1) * 128;
        bool isComb = !(c & 1);
        const __nv_bfloat16* bh = isComb ? (g_CombT_hi + ((size_t)layer * 384 + j0) * 128)
                                         : (g_Whh_hi + (size_t)j0 * 128);
        const __nv_bfloat16* bl = isComb ? (g_CombT_lo + ((size_t)layer * 384 + j0) * 128)
                                         : (g_Whh_lo + (size_t)j0 * 128);
        uint32_t dst = sbase + ((c & 1) ? SMB1 : SMB0);
#pragma unroll
        for (int q = 0; q < 8; q++) {
            int i = tid + 256 * q;
            int r = i >> 4, cc = i & 15;
            uint32_t off = r * 256 + ((cc ^ (r & 7)) << 4);
            cp_async16(dst + off, bh + i * 8);
            cp_async16(dst + 32768 + off, bl + i * 8);
        }
    };
    load_b(0);
    CP_COMMIT();      // group: A tiles + B chunk0

    float acc[4][8][4];
#pragma unroll
    for (int b = 0; b < 4; b++)
#pragma unroll
        for (int n = 0; n < 8; n++)
#pragma unroll
            for (int e = 0; e < 4; e++) acc[b][n][e] = 0.f;

    const int a_r = rg * 16 + (lane & 15);
    const int a_kh = lane >> 4;
    const int b_grp = lane >> 3;
    const int b_nt_off = b_grp >> 1;
    const int b_kh = b_grp & 1;
    const int b_nl = lane & 7;

#pragma unroll
    for (int chunk = 0; chunk < 6; chunk++) {
        if (chunk < 5) { load_b(chunk + 1); CP_COMMIT(); }
        if (chunk < 5) { CP_WAIT(1); } else { CP_WAIT(0); }
        __syncthreads();
        const bool isComb = !(chunk & 1);
        const int bank = (chunk < 2) ? 0 : (chunk < 4) ? 1 : (chunk == 4) ? 2 : 3;
        const uint32_t bufH = sbase + ((chunk & 1) ? SMB1 : SMB0);
        const uint32_t bufL = bufH + 32768;
        const uint32_t aHi = sbase + (isComb ? SMA_AGH : SMA_XH);
        const uint32_t aLo = sbase + (isComb ? SMA_AGL : SMA_XL);
        for (int ks = 0; ks < 8; ks++) {
            uint32_t ach = (uint32_t)(((ks * 2 + a_kh) ^ (a_r & 7)) << 4) + a_r * 256;
            uint32_t ah0, ah1, ah2, ah3, al0, al1, al2, al3;
            ldsm_x4(ah0, ah1, ah2, ah3, aHi + ach);
            ldsm_x4(al0, al1, al2, al3, aLo + ach);
#pragma unroll
            for (int nt2 = 0; nt2 < 8; nt2 += 2) {
                int n = cg * 64 + (nt2 + b_nt_off) * 8 + b_nl;
                uint32_t boff = (uint32_t)n * 256 + (uint32_t)(((ks * 2 + b_kh) ^ (n & 7)) << 4);
                uint32_t bh0, bh1, bh2, bh3, bl0, bl1, bl2, bl3;
                ldsm_x4(bh0, bh1, bh2, bh3, bufH + boff);
                ldsm_x4(bl0, bl1, bl2, bl3, bufL + boff);
                mma16816(acc[bank][nt2], ah0, ah1, ah2, ah3, bh0, bh1);
                mma16816(acc[bank][nt2], al0, al1, al2, al3, bh0, bh1);
                mma16816(acc[bank][nt2], ah0, ah1, ah2, ah3, bl0, bl1);
                mma16816(acc[bank][nt2 + 1], ah0, ah1, ah2, ah3, bh2, bh3);
                mma16816(acc[bank][nt2 + 1], al0, al1, al2, al3, bh2, bh3);
                mma16816(acc[bank][nt2 + 1], ah0, ah1, ah2, ah3, bl2, bl3);
            }
        }
        __syncthreads();
    }

    // ---------- GRU epilogue in registers ----------
    int tq = lane >> 2, tr = lane & 3;
#pragma unroll
    for (int nt = 0; nt < 8; nt++) {
        int j = cg * 64 + nt * 8 + tr * 2;
#pragma unroll
        for (int h = 0; h < 2; h++) {
            int m = rowBase + rg * 16 + tq + h * 8;
            float r0 = sigmoidf_(acc[0][nt][2 * h] + sb[j]);
            float r1 = sigmoidf_(acc[0][nt][2 * h + 1] + sb[j + 1]);
            float z0 = sigmoidf_(acc[1][nt][2 * h] + sb[128 + j]);
            float z1 = sigmoidf_(acc[1][nt][2 * h + 1] + sb[128 + j + 1]);
            float n0 = tanhf(acc[2][nt][2 * h] + sb[256 + j] +
                             r0 * (acc[3][nt][2 * h] + sb[384 + j]));
            float n1 = tanhf(acc[2][nt][2 * h + 1] + sb[256 + j + 1] +
                             r1 * (acc[3][nt][2 * h + 1] + sb[384 + j + 1]));
            size_t o = (size_t)m * 128 + j;
            float2 xo = *(const float2*)&g_x[o];
            float xn0 = (1.f - z0) * n0 + z0 * xo.x;
            float xn1 = (1.f - z1) * n1 + z1 * xo.y;
            *(float2*)&g_x[o] = make_float2(xn0, xn1);
            __nv_bfloat16 h0, l0, h1, l1;
            cvt_hilo(xn0, h0, l0); cvt_hilo(xn1, h1, l1);
            *(__nv_bfloat162*)&g_xhi[o] = __nv_bfloat162(h0, h1);
            *(__nv_bfloat162*)&g_xlo[o] = __nv_bfloat162(l0, l1);
        }
    }
}

// ---------------- transdim GEMM (fp32, N=64) ---------------------------------
__global__ void gemm_k128(const float* __restrict__ A, const float* __restrict__ B,
                          float* __restrict__ C, int Ncols) {
    __shared__ float Ast[64][68];
    __shared__ float Bs[64][64];
    int tid = threadIdx.x;
    int tx = tid & 15, ty = tid >> 4;
    int rowBase = blockIdx.x * 64;
    int colBase = blockIdx.y * 64;
    float acc[4][4] = {};
    for (int kc = 0; kc < 2; kc++) {
        {
            int c4 = tid & 15;
            int r0 = tid >> 4;
#pragma unroll
            for (int rr = 0; rr < 4; rr++) {
                int row = r0 + 16 * rr;
                float4 v = *(const float4*)&A[(size_t)(rowBase + row) * 128 + kc * 64 + c4 * 4];
                Ast[c4 * 4 + 0][row] = v.x;
                Ast[c4 * 4 + 1][row] = v.y;
                Ast[c4 * 4 + 2][row] = v.z;
                Ast[c4 * 4 + 3][row] = v.w;
            }
#pragma unroll
            for (int kk2 = 0; kk2 < 4; kk2++) {
                int kr = r0 + 16 * kk2;
                float4 v = *(const float4*)&B[(size_t)(kc * 64 + kr) * Ncols + colBase + c4 * 4];
                *(float4*)&Bs[kr][c4 * 4] = v;
            }
        }
        __syncthreads();
#pragma unroll 8
        for (int kk = 0; kk < 64; kk++) {
            float4 a = *(const float4*)&Ast[kk][ty * 4];
            float4 b = *(const float4*)&Bs[kk][tx * 4];
            float av[4] = {a.x, a.y, a.z, a.w};
            float bv[4] = {b.x, b.y, b.z, b.w};
#pragma unroll
            for (int i = 0; i < 4; i++)
#pragma unroll
                for (int j = 0; j < 4; j++) acc[i][j] += av[i] * bv[j];
        }
        __syncthreads();
    }
#pragma unroll
    for (int i = 0; i < 4; i++) {
        float4 o = make_float4(acc[i][0], acc[i][1], acc[i][2], acc[i][3]);
        *(float4*)&C[(size_t)(rowBase + ty * 4 + i) * Ncols + colBase + tx * 4] = o;
    }
}

// ---------------- attention --------------------------------------------------
__global__ void attn_kernel(const float* __restrict__ c_id,
                            const float* __restrict__ c_embed,
                            const float* __restrict__ concept_embedding) {
    extern __shared__ float smf[];
    float* shg = smf;
    float* pbuf = shg + NNODE * 65;
    float* qbuf = pbuf + 8 * NNODE;
    float* acc = qbuf + 8 * 64;
    float* snum = acc + 64;
    int g = blockIdx.x;
    int tid = threadIdx.x;
    for (int i = tid; i < NNODE * DCC; i += 256) {
        int n = i >> 6, d = i & 63;
        shg[n * 65 + d] = g_ggnn[(size_t)(g * NNODE + n) * DCC + d];
    }
    if (tid < 64) acc[tid] = 0.f;
    if (tid == 0) snum[0] = 0.f;
    __syncthreads();
    if (tid < CP1N) atomicAdd(snum, c_id[g * CP1N + tid]);
    __syncthreads();
    int warp = tid >> 5, lane = tid & 31;
    for (int c = warp; c < CP1N; c += 8) {
        float ce = c_embed[g * CP1N + c];
        if (ce == 0.f) continue;
        qbuf[warp * 64 + lane] = ce * concept_embedding[c * DCC + lane];
        qbuf[warp * 64 + lane + 32] = ce * concept_embedding[c * DCC + lane + 32];
        __syncwarp();
        float mx = -1e30f;
        for (int n = lane; n < NNODE; n += 32) {
            float s = 0.f;
#pragma unroll 16
            for (int d = 0; d < DCC; d++) s += qbuf[warp * 64 + d] * shg[n * 65 + d];
            pbuf[warp * NNODE + n] = s;
            mx = fmaxf(mx, s);
        }
#pragma unroll
        for (int o = 16; o > 0; o >>= 1) mx = fmaxf(mx, __shfl_xor_sync(0xffffffffu, mx, o));
        float ssum = 0.f;
        for (int n = lane; n < NNODE; n += 32) {
            float p = expf(pbuf[warp * NNODE + n] - mx);
            pbuf[warp * NNODE + n] = p;
            ssum += p;
        }
#pragma unroll
        for (int o = 16; o > 0; o >>= 1) ssum += __shfl_xor_sync(0xffffffffu, ssum, o);
        __syncwarp();
        float inv = ce / ssum;
        float a0 = 0.f, a1 = 0.f;
        for (int n = 0; n < NNODE; n++) {
            float p = pbuf[warp * NNODE + n];
            a0 += p * shg[n * 65 + lane];
            a1 += p * shg[n * 65 + lane + 32];
        }
        atomicAdd(&acc[lane], a0 * inv);
        atomicAdd(&acc[lane + 32], a1 * inv);
        __syncwarp();
    }
    __syncthreads();
    if (tid < DCC) {
        float nv = snum[0];
        if (nv == 0.f) nv = 1.f;
        g_attn[g * DCC + tid] = acc[tid] / nv;
    }
}

// ---------------- LSTM input GEMM: 8 sequences per block ---------------------
__global__ void lstm_pre_kernel(const float* __restrict__ c_embed,
                                const float* __restrict__ cur_result,
                                const float* __restrict__ lstm_b_ih) {
    __shared__ float xin[8][FEATN];
    int s0 = blockIdx.x * 8;
    int tid = threadIdx.x;
    for (int i = tid; i < 8 * FEATN; i += 256) {
        int si = i / FEATN, f = i % FEATN;
        int s = s0 + si;
        float v;
        if (f < CP1N) v = c_embed[(size_t)s * CP1N + f];
        else if (f < CP1N + DCC) v = g_attn[(size_t)s * DCC + (f - CP1N)];
        else v = cur_result[(size_t)s * 2 + (f - CP1N - DCC)];
        xin[si][f] = v;
    }
    __syncthreads();
    int m = blockIdx.y * 256 + tid;
    int q = m & 3, j = m >> 2;
    float b = lstm_b_ih[q * 256 + j];
    float a0 = b, a1 = b, a2 = b, a3 = b, a4 = b, a5 = b, a6 = b, a7 = b;
    for (int k = 0; k < FEATN; k++) {
        float w = g_LihT[(size_t)k * 1024 + m];
        a0 += xin[0][k] * w; a1 += xin[1][k] * w;
        a2 += xin[2][k] * w; a3 += xin[3][k] * w;
        a4 += xin[4][k] * w; a5 += xin[5][k] * w;
        a6 += xin[6][k] * w; a7 += xin[7][k] * w;
    }
    g_pre[(size_t)(s0 + 0) * 1024 + m] = a0;
    g_pre[(size_t)(s0 + 1) * 1024 + m] = a1;
    g_pre[(size_t)(s0 + 2) * 1024 + m] = a2;
    g_pre[(size_t)(s0 + 3) * 1024 + m] = a3;
    g_pre[(size_t)(s0 + 4) * 1024 + m] = a4;
    g_pre[(size_t)(s0 + 5) * 1024 + m] = a5;
    g_pre[(size_t)(s0 + 6) * 1024 + m] = a6;
    g_pre[(size_t)(s0 + 7) * 1024 + m] = a7;
}

// LSTM recurrence: cluster of 8 CTAs per batch element
__global__ void __cluster_dims__(8, 1, 1) __launch_bounds__(128, 1)
lstm_rec_kernel(const float* __restrict__ b_hh) {
    extern __shared__ float sml[];
    float* sW = sml;
    float* sh = sml + 256 * 128;
    int tid = threadIdx.x;
    int r = blockIdx.x & 7;
    int b = blockIdx.x >> 3;
    for (int i = tid; i < 256 * 128; i += 128)
        sW[i] = g_WhhP[(size_t)(i >> 7) * 1024 + r * 128 + (i & 127)];
    for (int i = tid; i < 256; i += 128) sh[i] = 0.f;
    int q = tid & 3, jl = tid >> 2;
    int jg = r * 32 + jl;
    float bias = b_hh[q * 256 + jg];
    float c = 0.f;
    uint32_t sh_my = smem_u32(&sh[jg]);
    __syncthreads();
    CLUSTER_BAR();
    int lbase = (tid & 31) & ~3;
    for (int t = 0; t < SLEN; t++) {
        int s = b * SLEN + t;
        float acc = g_pre[(size_t)s * 1024 + r * 128 + tid] + bias;
#pragma unroll 8
        for (int k = 0; k < 256; k++) acc += sh[k] * sW[k * 128 + tid];
        float vi = __shfl_sync(0xffffffffu, acc, lbase + 0);
        float vf = __shfl_sync(0xffffffffu, acc, lbase + 1);
        float vg = __shfl_sync(0xffffffffu, acc, lbase + 2);
        float vo = __shfl_sync(0xffffffffu, acc, lbase + 3);
        CLUSTER_BAR();
        if (q == 0) {
            c = sigmoidf_(vf) * c + sigmoidf_(vi) * tanhf(vg);
            float h = sigmoidf_(vo) * tanhf(c);
            g_hout[(size_t)s * HHID + jg] = h;
#pragma unroll
            for (int dst = 0; dst < 8; dst++) {
                uint32_t rem;
                asm("mapa.shared::cluster.u32 %0, %1, %2;" : "=r"(rem)
                    : "r"(sh_my), "r"(dst));
                asm volatile("st.shared::cluster.f32 [%0], %1;" :: "r"(rem), "f"(h)
                             : "memory");
            }
        }
        CLUSTER_BAR();
    }
}

// ---------------- pred + BCE + final -----------------------------------------
__global__ void pred_kernel(const float* __restrict__ target_c,
                            const float* __restrict__ result,
                            const float* __restrict__ pred_w,
                            const float* __restrict__ pred_b) {
    __shared__ float sh[HHID];
    __shared__ float s_p, s_n;
    int i = blockIdx.x, tid = threadIdx.x;
    sh[tid] = g_hout[(size_t)i * HHID + tid];
    sh[tid + 128] = g_hout[(size_t)i * HHID + tid + 128];
    if (tid == 0) { s_p = 0.f; s_n = 0.f; }
    __syncthreads();
    int warp = tid >> 5, lane = tid & 31;
    float lp = 0.f, ln = 0.f;
    for (int c = warp; c < CP1N; c += 4) {
        float tc = target_c[i * CP1N + c];
        if (tc != 0.f) {
            float s = 0.f;
            for (int d = lane; d < HHID; d += 32) s += pred_w[c * HHID + d] * sh[d];
#pragma unroll
            for (int o = 16; o > 0; o >>= 1) s += __shfl_xor_sync(0xffffffffu, s, o);
            if (lane == 0) { lp += tc * (s + pred_b[c]); ln += tc; }
        }
    }
    if (lane == 0) { atomicAdd(&s_p, lp); atomicAdd(&s_n, ln); }
    __syncthreads();
    if (tid == 0) {
        float nc = s_n;
        int mask = nc > 0.f;
        float fp = s_p / (mask ? nc : 1.f);
        float ft = result[i];
        float bce = fmaxf(fp, 0.f) - fp * ft + log1pf(expf(-fabsf(fp)));
        g_fp[i] = fp;
        g_mf[i] = mask ? 1.f : 0.f;
        g_bce[i] = mask ? bce : 0.f;
    }
}

__global__ void final_kernel(const float* __restrict__ result, float* __restrict__ out,
                             int out_size) {
    __shared__ float rb[256], rm[256];
    int tid = threadIdx.x;
    float sb = 0.f, smm = 0.f;
    for (int i = tid; i < GG; i += 256) { sb += g_bce[i]; smm += g_mf[i]; }
    rb[tid] = sb; rm[tid] = smm;
    __syncthreads();
    for (int o = 128; o > 0; o >>= 1) {
        if (tid < o) { rb[tid] += rb[tid + o]; rm[tid] += rm[tid + o]; }
        __syncthreads();
    }
    if (tid == 0 && out_size > 0) out[0] = rb[0] / fmaxf(rm[0], 1.f);
    for (int i = tid; i < GG; i += 256) {
        if (1 + i < out_size) out[1 + i] = 1.f / (1.f + expf(-g_fp[i]));
        if (1 + GG + i < out_size) out[1 + GG + i] = result[i];
    }
}

// ---------------- launcher ---------------------------------------------------
extern "C" void kernel_launch(void* const* d_in, const int* in_sizes, int n_in,
                              void* d_out, int out_size) {
    const float* c_id       = (const float*)d_in[1];
    const int*   node_id    = (const int*)d_in[2];
    const int*   edge       = (const int*)d_in[3];
    const int*   edge_type  = (const int*)d_in[4];
    const float* target_c   = (const float*)d_in[5];
    const float* result     = (const float*)d_in[6];
    const float* c_embed    = (const float*)d_in[7];
    const float* cur_result = (const float*)d_in[8];
    const float* node_embed_w = (const float*)d_in[9];
    const float* edge_embed_w = (const float*)d_in[10];
    const float* ggnn_w     = (const float*)d_in[11];
    const float* gru_w_ih   = (const float*)d_in[12];
    const float* gru_w_hh   = (const float*)d_in[13];
    const float* gru_b_ih   = (const float*)d_in[14];
    const float* gru_b_hh   = (const float*)d_in[15];
    const float* transdim_w = (const float*)d_in[16];
    const float* concept_embedding = (const float*)d_in[17];
    const float* lstm_w_ih  = (const float*)d_in[18];
    const float* lstm_w_hh  = (const float*)d_in[19];
    const float* lstm_b_ih  = (const float*)d_in[20];
    const float* lstm_b_hh  = (const float*)d_in[21];
    const float* pred_w     = (const float*)d_in[22];
    const float* pred_b     = (const float*)d_in[23];
    float* out = (float*)d_out;
    (void)in_sizes; (void)n_in;

    const int SCAT_SMEM = NNODE * DD * 4;
    const int LSTM_SMEM = 256 * 128 * 4 + 256 * 4;
    cudaFuncSetAttribute(layer_mma, cudaFuncAttributeMaxDynamicSharedMemorySize, SM_TOT);
    cudaFuncSetAttribute(attn_kernel, cudaFuncAttributeMaxDynamicSharedMemorySize, 61440);
    cudaFuncSetAttribute(scatter_csr, cudaFuncAttributeMaxDynamicSharedMemorySize, SCAT_SMEM);
    cudaFuncSetAttribute(lstm_rec_kernel, cudaFuncAttributeMaxDynamicSharedMemorySize,
                         LSTM_SMEM);

    void *px, *pggnn, *pTdT;
    cudaGetSymbolAddress(&px, g_x);
    cudaGetSymbolAddress(&pggnn, g_ggnn);
    cudaGetSymbolAddress(&pTdT, g_TdT);

    prep_kernel<<<1960, 256>>>(edge_embed_w, gru_w_hh, transdim_w, lstm_w_ih, lstm_w_hh);
    comb_kernel<<<(4 * 384 * 128 + 255) / 256, 256>>>(ggnn_w, gru_w_ih);
    gather_kernel<<<GN / 8, 256>>>(node_id, node_embed_w);

    for (int l = 0; l < 4; l++) {
        scatter_csr<<<GG, 256, SCAT_SMEM>>>(edge, edge_type);
        layer_mma<<<GN / 64, 256, SM_TOT>>>(l, gru_b_ih, gru_b_hh);
    }

    gemm_k128<<<dim3(GN / 64, 1), 256>>>((const float*)px, (const float*)pTdT,
                                         (float*)pggnn, 64);
    attn_kernel<<<GG, 256, 61440>>>(c_id, c_embed, concept_embedding);
    lstm_pre_kernel<<<dim3(GG / 8, 4), 256>>>(c_embed, cur_result, lstm_b_ih);
    lstm_rec_kernel<<<BSZ * 8, 128, LSTM_SMEM>>>(lstm_b_hh);
    pred_kernel<<<GG, 128>>>(target_c, result, pred_w, pred_b);
    final_kernel<<<1, 256>>>(result, out, out_size);
}

// round 7
// speedup vs baseline: 3.7375x; 1.0302x over previous
#include <cuda_runtime.h>
#include <cuda_bf16.h>
#include <math.h>
#include <stdint.h>

#define BSZ  8
#define SLEN 100
#define GG   800
#define NNODE 200
#define NEDGE 600
#define DD   128
#define DCC  64
#define HHID 256
#define CP1N 111
#define FEATN 177
#define GN   160000

// ---------------- scratch globals -------------------------------------------
__device__ float g_x[(size_t)GN * DD];
__device__ __nv_bfloat16 g_xhi[(size_t)GN * DD];
__device__ __nv_bfloat16 g_xlo[(size_t)GN * DD];
__device__ __nv_bfloat16 g_agghi[(size_t)GN * DD];
__device__ __nv_bfloat16 g_agglo[(size_t)GN * DD];
__device__ __nv_bfloat16 g_CombT_hi[4 * 384 * 128];   // [l][j][k]
__device__ __nv_bfloat16 g_CombT_lo[4 * 384 * 128];
__device__ __nv_bfloat16 g_Whh_hi[384 * 128];         // [j][k]
__device__ __nv_bfloat16 g_Whh_lo[384 * 128];
__device__ __nv_bfloat16 g_Td_hi[64 * 128];           // [c][k]
__device__ __nv_bfloat16 g_Td_lo[64 * 128];
__device__ float g_ggnn[(size_t)GN * DCC];
__device__ float g_attn[GG * DCC];
__device__ float g_mean8[8];
__device__ float g_LihT[FEATN * 1024];
__device__ float g_WhhP[256 * 1024];
__device__ float g_pre[(size_t)GG * 1024];
__device__ float g_hout[(size_t)GG * HHID];
__device__ float g_fp[GG];
__device__ float g_bce[GG];
__device__ float g_mf[GG];
// CSR scratch (layer-invariant)
__device__ int   g_csr_src[GG * NEDGE];
__device__ float g_csr_w[GG * NEDGE];
__device__ int   g_csr_ofs[GG * (NNODE + 1)];

__device__ __forceinline__ float sigmoidf_(float v) { return 1.f / (1.f + expf(-v)); }

__device__ __forceinline__ void cvt_hilo(float v, __nv_bfloat16& h, __nv_bfloat16& l) {
    h = __float2bfloat16_rn(v);
    l = __float2bfloat16_rn(v - __bfloat162float(h));
}

__device__ __forceinline__ uint32_t smem_u32(const void* p) {
    uint32_t a;
    asm("{ .reg .u64 t; cvta.to.shared.u64 t, %1; cvt.u32.u64 %0, t; }" : "=r"(a) : "l"(p));
    return a;
}
__device__ __forceinline__ void ldsm_x4(uint32_t& a0, uint32_t& a1, uint32_t& a2,
                                        uint32_t& a3, uint32_t addr) {
    asm volatile("ldmatrix.sync.aligned.m8n8.x4.shared.b16 {%0,%1,%2,%3}, [%4];"
                 : "=r"(a0), "=r"(a1), "=r"(a2), "=r"(a3) : "r"(addr));
}
__device__ __forceinline__ void mma16816(float* d, uint32_t a0, uint32_t a1, uint32_t a2,
                                         uint32_t a3, uint32_t b0, uint32_t b1) {
    asm volatile("mma.sync.aligned.m16n8k16.row.col.f32.bf16.bf16.f32 "
                 "{%0,%1,%2,%3}, {%4,%5,%6,%7}, {%8,%9}, {%0,%1,%2,%3};"
                 : "+f"(d[0]), "+f"(d[1]), "+f"(d[2]), "+f"(d[3])
                 : "r"(a0), "r"(a1), "r"(a2), "r"(a3), "r"(b0), "r"(b1));
}
__device__ __forceinline__ void cp_async16(uint32_t saddr, const void* gaddr) {
    asm volatile("cp.async.cg.shared.global [%0], [%1], 16;" :: "r"(saddr), "l"(gaddr));
}
#define CP_COMMIT() asm volatile("cp.async.commit_group;" ::: "memory")
#define CP_WAIT(n)  asm volatile("cp.async.wait_group %0;" :: "n"(n) : "memory")
#define CLUSTER_BAR() do { \
    asm volatile("barrier.cluster.arrive.aligned;" ::: "memory"); \
    asm volatile("barrier.cluster.wait.aligned;" ::: "memory"); \
} while (0)

// ---------------- prep -------------------------------------------------------
__global__ void prep_kernel(const float* __restrict__ edge_embed_w,
                            const float* __restrict__ gru_w_hh,
                            const float* __restrict__ transdim_w,
                            const float* __restrict__ lstm_w_ih,
                            const float* __restrict__ lstm_w_hh) {
    const int T3 = 64 * 128, T4 = FEATN * 1024, T5 = 256 * 1024, T6 = 384 * 128;
    int total = 8 + T3 + T4 + T5 + T6;
    for (int i = blockIdx.x * blockDim.x + threadIdx.x; i < total;
         i += gridDim.x * blockDim.x) {
        int t = i;
        if (t < 8) {
            float s = 0.f;
            for (int d = 0; d < DD; d++) s += edge_embed_w[t * DD + d];
            g_mean8[t] = s / (float)DD;
            continue;
        }
        t -= 8;
        if (t < T3) {
            __nv_bfloat16 h, l; cvt_hilo(transdim_w[t], h, l);
            g_Td_hi[t] = h; g_Td_lo[t] = l;
            continue;
        }
        t -= T3;
        if (t < T4) {
            int k = t / 1024, p = t % 1024; int q = p & 3, j = p >> 2;
            g_LihT[t] = lstm_w_ih[(q * 256 + j) * FEATN + k];
            continue;
        }
        t -= T4;
        if (t < T5) {
            int k = t / 1024, p = t % 1024; int q = p & 3, j = p >> 2;
            g_WhhP[t] = lstm_w_hh[(q * 256 + j) * 256 + k];
            continue;
        }
        t -= T5;
        { __nv_bfloat16 h, l; cvt_hilo(gru_w_hh[t], h, l); g_Whh_hi[t] = h; g_Whh_lo[t] = l; }
    }
}

// CombT[l][j][k] = sum_d W_l[k,d] * W_ih[j,d]
__global__ void comb_kernel(const float* __restrict__ ggnn_w,
                            const float* __restrict__ gru_w_ih) {
    int t = blockIdx.x * blockDim.x + threadIdx.x;
    if (t >= 4 * 384 * 128) return;
    int l = t / (384 * 128); int r = t % (384 * 128);
    int j = r / 128, k = r % 128;
    const float4* wl = (const float4*)(ggnn_w + ((size_t)l * 128 + k) * 128);
    const float4* wi = (const float4*)(gru_w_ih + (size_t)j * 128);
    float s = 0.f;
#pragma unroll 8
    for (int d = 0; d < 32; d++) {
        float4 a = wl[d], b = wi[d];
        s += a.x * b.x + a.y * b.y + a.z * b.z + a.w * b.w;
    }
    __nv_bfloat16 h, lo; cvt_hilo(s, h, lo);
    g_CombT_hi[t] = h; g_CombT_lo[t] = lo;
}

// ---------------- gather -----------------------------------------------------
__global__ void gather_kernel(const int* __restrict__ node_id,
                              const float* __restrict__ embed) {
    int warp = threadIdx.x >> 5, lane = threadIdx.x & 31;
    int row = blockIdx.x * 8 + warp;
    if (row >= GN) return;
    int nid = node_id[row];
    float4 v = *(const float4*)&embed[(size_t)nid * DD + lane * 4];
    size_t o = (size_t)row * DD + lane * 4;
    *(float4*)&g_x[o] = v;
    __nv_bfloat16 h0, l0, h1, l1, h2, l2, h3, l3;
    cvt_hilo(v.x, h0, l0); cvt_hilo(v.y, h1, l1);
    cvt_hilo(v.z, h2, l2); cvt_hilo(v.w, h3, l3);
    ((__nv_bfloat162*)&g_xhi[o])[0] = __nv_bfloat162(h0, h1);
    ((__nv_bfloat162*)&g_xhi[o])[1] = __nv_bfloat162(h2, h3);
    ((__nv_bfloat162*)&g_xlo[o])[0] = __nv_bfloat162(l0, l1);
    ((__nv_bfloat162*)&g_xlo[o])[1] = __nv_bfloat162(l2, l3);
}

// ---------------- CSR build (once; layer-invariant) --------------------------
__global__ void csr_build(const int* __restrict__ edge,
                          const int* __restrict__ edge_type) {
    __shared__ int s_src[NEDGE];
    __shared__ int s_dst[NEDGE];
    __shared__ int cnt[NNODE + 1];
    __shared__ int ofs[NNODE + 1];
    __shared__ float sm8[8];
    int g = blockIdx.x;
    int tid = threadIdx.x;
    const int* eg = edge + (size_t)g * 2 * NEDGE;
    if (tid < 8) sm8[tid] = g_mean8[tid];
    for (int e = tid; e < NEDGE; e += 256) { s_src[e] = eg[e]; s_dst[e] = eg[NEDGE + e]; }
    for (int i = tid; i <= NNODE; i += 256) cnt[i] = 0;
    __syncthreads();
    for (int e = tid; e < NEDGE; e += 256) atomicAdd(&cnt[s_dst[e]], 1);
    __syncthreads();
    if (tid == 0) {
        int acc = 0;
        for (int n = 0; n <= NNODE; n++) { int c = cnt[n]; ofs[n] = acc; acc += c; }
    }
    __syncthreads();
    for (int i = tid; i <= NNODE; i += 256) g_csr_ofs[g * (NNODE + 1) + i] = ofs[i];
    for (int i = tid; i < NNODE; i += 256) cnt[i] = ofs[i];
    __syncthreads();
    for (int e = tid; e < NEDGE; e += 256) {
        int p = atomicAdd(&cnt[s_dst[e]], 1);
        g_csr_src[g * NEDGE + p] = s_src[e];
        g_csr_w[g * NEDGE + p] = sm8[edge_type[(size_t)g * NEDGE + e]];
    }
}

// ---------------- per-layer edge scatter: smem x tile + prebuilt CSR ---------
__global__ void __launch_bounds__(512, 2) scatter_csr(int dummy) {
    extern __shared__ float sx[];     // 200*128 floats = 102400 B
    int g = blockIdx.x;
    int tid = threadIdx.x;
    {
        const float4* xg4 = (const float4*)(g_x + (size_t)g * NNODE * DD);
        float4* sx4 = (float4*)sx;
        for (int i = tid; i < NNODE * DD / 4; i += 512) sx4[i] = xg4[i];
    }
    __syncthreads();
    int warp = tid >> 5, lane = tid & 31;
    const int* ofs = g_csr_ofs + g * (NNODE + 1);
    const int* srcv = g_csr_src + g * NEDGE;
    const float* wv = g_csr_w + g * NEDGE;
    for (int n = warp; n < NNODE; n += 16) {
        float4 acc = make_float4(0.f, 0.f, 0.f, 0.f);
        int s0 = ofs[n], s1 = ofs[n + 1];
        for (int i = s0; i < s1; i++) {
            int src = srcv[i];
            float w = wv[i];
            float4 v = *(const float4*)&sx[src * DD + lane * 4];
            acc.x += w * v.x; acc.y += w * v.y; acc.z += w * v.z; acc.w += w * v.w;
        }
        size_t o = ((size_t)(g * NNODE + n)) * DD + lane * 4;
        __nv_bfloat16 h0, l0, h1, l1, h2, l2, h3, l3;
        cvt_hilo(acc.x, h0, l0); cvt_hilo(acc.y, h1, l1);
        cvt_hilo(acc.z, h2, l2); cvt_hilo(acc.w, h3, l3);
        ((__nv_bfloat162*)&g_agghi[o])[0] = __nv_bfloat162(h0, h1);
        ((__nv_bfloat162*)&g_agghi[o])[1] = __nv_bfloat162(h2, h3);
        ((__nv_bfloat162*)&g_agglo[o])[0] = __nv_bfloat162(l0, l1);
        ((__nv_bfloat162*)&g_agglo[o])[1] = __nv_bfloat162(l2, l3);
    }
    (void)dummy;
}

// ---------------- fused HMMA GGNN layer: double-buffered B ------------------
#define SMA_AGH 0
#define SMA_AGL 16384
#define SMA_XH  32768
#define SMA_XL  49152
#define SMB0    65536
#define SMB1    131072
#define SMB_BIA 196608
#define SM_TOT  (196608 + 2048)

__global__ void __launch_bounds__(256, 1) layer_mma(int layer,
                                                    const float* __restrict__ b_ih,
                                                    const float* __restrict__ b_hh) {
    extern __shared__ __align__(128) char smx[];
    uint32_t sbase = smem_u32(smx);
    int tid = threadIdx.x, wid = tid >> 5, lane = tid & 31;
    int rowBase = blockIdx.x * 64;
    int rg = wid >> 1;
    int cg = wid & 1;
    float* sb = (float*)(smx + SMB_BIA);
    if (tid < 128) {
        sb[tid]       = b_ih[tid] + b_hh[tid];
        sb[128 + tid] = b_ih[128 + tid] + b_hh[128 + tid];
        sb[256 + tid] = b_ih[256 + tid];
        sb[384 + tid] = b_hh[256 + tid];
    }
    {
        const __nv_bfloat16* s0 = g_agghi + (size_t)rowBase * 128;
        const __nv_bfloat16* s1 = g_agglo + (size_t)rowBase * 128;
        const __nv_bfloat16* s2 = g_xhi + (size_t)rowBase * 128;
        const __nv_bfloat16* s3 = g_xlo + (size_t)rowBase * 128;
#pragma unroll
        for (int q = 0; q < 4; q++) {
            int i = tid + 256 * q;
            int r = i >> 4, c = i & 15;
            uint32_t off = r * 256 + ((c ^ (r & 7)) << 4);
            cp_async16(sbase + SMA_AGH + off, s0 + i * 8);
            cp_async16(sbase + SMA_AGL + off, s1 + i * 8);
            cp_async16(sbase + SMA_XH + off, s2 + i * 8);
            cp_async16(sbase + SMA_XL + off, s3 + i * 8);
        }
    }
    auto load_b = [&](int c) {
        int j0 = (c >> 1) * 128;
        bool isComb = !(c & 1);
        const __nv_bfloat16* bh = isComb ? (g_CombT_hi + ((size_t)layer * 384 + j0) * 128)
                                         : (g_Whh_hi + (size_t)j0 * 128);
        const __nv_bfloat16* bl = isComb ? (g_CombT_lo + ((size_t)layer * 384 + j0) * 128)
                                         : (g_Whh_lo + (size_t)j0 * 128);
        uint32_t dst = sbase + ((c & 1) ? SMB1 : SMB0);
#pragma unroll
        for (int q = 0; q < 8; q++) {
            int i = tid + 256 * q;
            int r = i >> 4, cc = i & 15;
            uint32_t off = r * 256 + ((cc ^ (r & 7)) << 4);
            cp_async16(dst + off, bh + i * 8);
            cp_async16(dst + 32768 + off, bl + i * 8);
        }
    };
    load_b(0);
    CP_COMMIT();

    float acc[4][8][4];
#pragma unroll
    for (int b = 0; b < 4; b++)
#pragma unroll
        for (int n = 0; n < 8; n++)
#pragma unroll
            for (int e = 0; e < 4; e++) acc[b][n][e] = 0.f;

    const int a_r = rg * 16 + (lane & 15);
    const int a_kh = lane >> 4;
    const int b_grp = lane >> 3;
    const int b_nt_off = b_grp >> 1;
    const int b_kh = b_grp & 1;
    const int b_nl = lane & 7;

#pragma unroll
    for (int chunk = 0; chunk < 6; chunk++) {
        if (chunk < 5) { load_b(chunk + 1); CP_COMMIT(); }
        if (chunk < 5) { CP_WAIT(1); } else { CP_WAIT(0); }
        __syncthreads();
        const bool isComb = !(chunk & 1);
        const int bank = (chunk < 2) ? 0 : (chunk < 4) ? 1 : (chunk == 4) ? 2 : 3;
        const uint32_t bufH = sbase + ((chunk & 1) ? SMB1 : SMB0);
        const uint32_t bufL = bufH + 32768;
        const uint32_t aHi = sbase + (isComb ? SMA_AGH : SMA_XH);
        const uint32_t aLo = sbase + (isComb ? SMA_AGL : SMA_XL);
        for (int ks = 0; ks < 8; ks++) {
            uint32_t ach = (uint32_t)(((ks * 2 + a_kh) ^ (a_r & 7)) << 4) + a_r * 256;
            uint32_t ah0, ah1, ah2, ah3, al0, al1, al2, al3;
            ldsm_x4(ah0, ah1, ah2, ah3, aHi + ach);
            ldsm_x4(al0, al1, al2, al3, aLo + ach);
#pragma unroll
            for (int nt2 = 0; nt2 < 8; nt2 += 2) {
                int n = cg * 64 + (nt2 + b_nt_off) * 8 + b_nl;
                uint32_t boff = (uint32_t)n * 256 + (uint32_t)(((ks * 2 + b_kh) ^ (n & 7)) << 4);
                uint32_t bh0, bh1, bh2, bh3, bl0, bl1, bl2, bl3;
                ldsm_x4(bh0, bh1, bh2, bh3, bufH + boff);
                ldsm_x4(bl0, bl1, bl2, bl3, bufL + boff);
                mma16816(acc[bank][nt2], ah0, ah1, ah2, ah3, bh0, bh1);
                mma16816(acc[bank][nt2], al0, al1, al2, al3, bh0, bh1);
                mma16816(acc[bank][nt2], ah0, ah1, ah2, ah3, bl0, bl1);
                mma16816(acc[bank][nt2 + 1], ah0, ah1, ah2, ah3, bh2, bh3);
                mma16816(acc[bank][nt2 + 1], al0, al1, al2, al3, bh2, bh3);
                mma16816(acc[bank][nt2 + 1], ah0, ah1, ah2, ah3, bl2, bl3);
            }
        }
        __syncthreads();
    }

    int tq = lane >> 2, tr = lane & 3;
#pragma unroll
    for (int nt = 0; nt < 8; nt++) {
        int j = cg * 64 + nt * 8 + tr * 2;
#pragma unroll
        for (int h = 0; h < 2; h++) {
            int m = rowBase + rg * 16 + tq + h * 8;
            float r0 = sigmoidf_(acc[0][nt][2 * h] + sb[j]);
            float r1 = sigmoidf_(acc[0][nt][2 * h + 1] + sb[j + 1]);
            float z0 = sigmoidf_(acc[1][nt][2 * h] + sb[128 + j]);
            float z1 = sigmoidf_(acc[1][nt][2 * h + 1] + sb[128 + j + 1]);
            float n0 = tanhf(acc[2][nt][2 * h] + sb[256 + j] +
                             r0 * (acc[3][nt][2 * h] + sb[384 + j]));
            float n1 = tanhf(acc[2][nt][2 * h + 1] + sb[256 + j + 1] +
                             r1 * (acc[3][nt][2 * h + 1] + sb[384 + j + 1]));
            size_t o = (size_t)m * 128 + j;
            float2 xo = *(const float2*)&g_x[o];
            float xn0 = (1.f - z0) * n0 + z0 * xo.x;
            float xn1 = (1.f - z1) * n1 + z1 * xo.y;
            *(float2*)&g_x[o] = make_float2(xn0, xn1);
            __nv_bfloat16 h0, l0, h1, l1;
            cvt_hilo(xn0, h0, l0); cvt_hilo(xn1, h1, l1);
            *(__nv_bfloat162*)&g_xhi[o] = __nv_bfloat162(h0, h1);
            *(__nv_bfloat162*)&g_xlo[o] = __nv_bfloat162(l0, l1);
        }
    }
}

// ---------------- transdim GEMM via HMMA (bf16 hi/lo, 3-pass) -----------------
// C[m][c] = sum_k x[m][k] * Td[c][k];  128 rows/CTA, N=64.
#define TD_AH 0
#define TD_AL 32768
#define TD_BH 65536
#define TD_BL 81920
#define TD_TOT 98304
__global__ void __launch_bounds__(256, 2) gemm_td() {
    extern __shared__ __align__(128) char smt[];
    uint32_t sbase = smem_u32(smt);
    int tid = threadIdx.x, wid = tid >> 5, lane = tid & 31;
    int rowBase = blockIdx.x * 128;
    // A tiles: 128 rows x 128 k bf16, hi/lo (2048 16B chunks each)
    {
        const __nv_bfloat16* s2 = g_xhi + (size_t)rowBase * 128;
        const __nv_bfloat16* s3 = g_xlo + (size_t)rowBase * 128;
#pragma unroll
        for (int q = 0; q < 8; q++) {
            int i = tid + 256 * q;
            int r = i >> 4, c = i & 15;
            uint32_t off = r * 256 + ((c ^ (r & 7)) << 4);
            cp_async16(sbase + TD_AH + off, s2 + i * 8);
            cp_async16(sbase + TD_AL + off, s3 + i * 8);
        }
    }
    // B tiles: 64 rows x 128 k bf16 hi/lo (1024 chunks each)
    {
#pragma unroll
        for (int q = 0; q < 4; q++) {
            int i = tid + 256 * q;
            int r = i >> 4, c = i & 15;
            uint32_t off = r * 256 + ((c ^ (r & 7)) << 4);
            cp_async16(sbase + TD_BH + off, g_Td_hi + i * 8);
            cp_async16(sbase + TD_BL + off, g_Td_lo + i * 8);
        }
    }
    CP_COMMIT();
    CP_WAIT(0);
    __syncthreads();

    float acc[8][4];
#pragma unroll
    for (int n = 0; n < 8; n++)
#pragma unroll
        for (int e = 0; e < 4; e++) acc[n][e] = 0.f;

    const int a_r = wid * 16 + (lane & 15);
    const int a_kh = lane >> 4;
    const int b_grp = lane >> 3;
    const int b_nt_off = b_grp >> 1;
    const int b_kh = b_grp & 1;
    const int b_nl = lane & 7;

    for (int ks = 0; ks < 8; ks++) {
        uint32_t ach = (uint32_t)(((ks * 2 + a_kh) ^ (a_r & 7)) << 4) + a_r * 256;
        uint32_t ah0, ah1, ah2, ah3, al0, al1, al2, al3;
        ldsm_x4(ah0, ah1, ah2, ah3, sbase + TD_AH + ach);
        ldsm_x4(al0, al1, al2, al3, sbase + TD_AL + ach);
#pragma unroll
        for (int nt2 = 0; nt2 < 8; nt2 += 2) {
            int n = (nt2 + b_nt_off) * 8 + b_nl;
            uint32_t boff = (uint32_t)n * 256 + (uint32_t)(((ks * 2 + b_kh) ^ (n & 7)) << 4);
            uint32_t bh0, bh1, bh2, bh3, bl0, bl1, bl2, bl3;
            ldsm_x4(bh0, bh1, bh2, bh3, sbase + TD_BH + boff);
            ldsm_x4(bl0, bl1, bl2, bl3, sbase + TD_BL + boff);
            mma16816(acc[nt2], ah0, ah1, ah2, ah3, bh0, bh1);
            mma16816(acc[nt2], al0, al1, al2, al3, bh0, bh1);
            mma16816(acc[nt2], ah0, ah1, ah2, ah3, bl0, bl1);
            mma16816(acc[nt2 + 1], ah0, ah1, ah2, ah3, bh2, bh3);
            mma16816(acc[nt2 + 1], al0, al1, al2, al3, bh2, bh3);
            mma16816(acc[nt2 + 1], ah0, ah1, ah2, ah3, bl2, bl3);
        }
    }
    int tq = lane >> 2, tr = lane & 3;
#pragma unroll
    for (int nt = 0; nt < 8; nt++) {
        int j = nt * 8 + tr * 2;
#pragma unroll
        for (int h = 0; h < 2; h++) {
            int m = rowBase + wid * 16 + tq + h * 8;
            *(float2*)&g_ggnn[(size_t)m * DCC + j] =
                make_float2(acc[nt][2 * h], acc[nt][2 * h + 1]);
        }
    }
}

// ---------------- attention (collapsed node weights) --------------------------
__global__ void attn_kernel(const float* __restrict__ c_id,
                            const float* __restrict__ c_embed,
                            const float* __restrict__ concept_embedding) {
    extern __shared__ float smf[];
    float* shg = smf;                       // 200*65
    float* pbuf = shg + NNODE * 65;         // 8*200
    float* qbuf = pbuf + 8 * NNODE;         // 8*64
    float* wnode = qbuf + 8 * 64;           // 200
    float* accd = wnode + NNODE;            // 64
    float* snum = accd + 64;                // 1
    int g = blockIdx.x;
    int tid = threadIdx.x;
    for (int i = tid; i < NNODE * DCC; i += 256) {
        int n = i >> 6, d = i & 63;
        shg[n * 65 + d] = g_ggnn[(size_t)(g * NNODE + n) * DCC + d];
    }
    for (int i = tid; i < NNODE; i += 256) wnode[i] = 0.f;
    if (tid < 64) accd[tid] = 0.f;
    if (tid == 0) snum[0] = 0.f;
    __syncthreads();
    if (tid < CP1N) atomicAdd(snum, c_id[g * CP1N + tid]);
    __syncthreads();
    int warp = tid >> 5, lane = tid & 31;
    for (int c = warp; c < CP1N; c += 8) {
        float ce = c_embed[g * CP1N + c];
        if (ce == 0.f) continue;
        qbuf[warp * 64 + lane] = ce * concept_embedding[c * DCC + lane];
        qbuf[warp * 64 + lane + 32] = ce * concept_embedding[c * DCC + lane + 32];
        __syncwarp();
        float mx = -1e30f;
        for (int n = lane; n < NNODE; n += 32) {
            float s = 0.f;
#pragma unroll 16
            for (int d = 0; d < DCC; d++) s += qbuf[warp * 64 + d] * shg[n * 65 + d];
            pbuf[warp * NNODE + n] = s;
            mx = fmaxf(mx, s);
        }
#pragma unroll
        for (int o = 16; o > 0; o >>= 1) mx = fmaxf(mx, __shfl_xor_sync(0xffffffffu, mx, o));
        float ssum = 0.f;
        for (int n = lane; n < NNODE; n += 32) {
            float p = expf(pbuf[warp * NNODE + n] - mx);
            pbuf[warp * NNODE + n] = p;
            ssum += p;
        }
#pragma unroll
        for (int o = 16; o > 0; o >>= 1) ssum += __shfl_xor_sync(0xffffffffu, ssum, o);
        float inv = ce / ssum;
        for (int n = lane; n < NNODE; n += 32)
            atomicAdd(&wnode[n], inv * pbuf[warp * NNODE + n]);
    }
    __syncthreads();
    // acc_d = sum_n wnode[n] * G[n][d], 4 partials per d
    {
        int d = tid & 63, q = tid >> 6;
        float partial = 0.f;
        for (int n = q * 50; n < q * 50 + 50; n++)
            partial += wnode[n] * shg[n * 65 + d];
        atomicAdd(&accd[d], partial);
    }
    __syncthreads();
    if (tid < DCC) {
        float nv = snum[0];
        if (nv == 0.f) nv = 1.f;
        g_attn[g * DCC + tid] = accd[tid] / nv;
    }
}

// ---------------- LSTM input GEMM: 8 sequences per block ---------------------
__global__ void lstm_pre_kernel(const float* __restrict__ c_embed,
                                const float* __restrict__ cur_result,
                                const float* __restrict__ lstm_b_ih) {
    __shared__ float xin[8][FEATN];
    int s0 = blockIdx.x * 8;
    int tid = threadIdx.x;
    for (int i = tid; i < 8 * FEATN; i += 256) {
        int si = i / FEATN, f = i % FEATN;
        int s = s0 + si;
        float v;
        if (f < CP1N) v = c_embed[(size_t)s * CP1N + f];
        else if (f < CP1N + DCC) v = g_attn[(size_t)s * DCC + (f - CP1N)];
        else v = cur_result[(size_t)s * 2 + (f - CP1N - DCC)];
        xin[si][f] = v;
    }
    __syncthreads();
    int m = blockIdx.y * 256 + tid;
    int q = m & 3, j = m >> 2;
    float b = lstm_b_ih[q * 256 + j];
    float a0 = b, a1 = b, a2 = b, a3 = b, a4 = b, a5 = b, a6 = b, a7 = b;
    for (int k = 0; k < FEATN; k++) {
        float w = g_LihT[(size_t)k * 1024 + m];
        a0 += xin[0][k] * w; a1 += xin[1][k] * w;
        a2 += xin[2][k] * w; a3 += xin[3][k] * w;
        a4 += xin[4][k] * w; a5 += xin[5][k] * w;
        a6 += xin[6][k] * w; a7 += xin[7][k] * w;
    }
    g_pre[(size_t)(s0 + 0) * 1024 + m] = a0;
    g_pre[(size_t)(s0 + 1) * 1024 + m] = a1;
    g_pre[(size_t)(s0 + 2) * 1024 + m] = a2;
    g_pre[(size_t)(s0 + 3) * 1024 + m] = a3;
    g_pre[(size_t)(s0 + 4) * 1024 + m] = a4;
    g_pre[(size_t)(s0 + 5) * 1024 + m] = a5;
    g_pre[(size_t)(s0 + 6) * 1024 + m] = a6;
    g_pre[(size_t)(s0 + 7) * 1024 + m] = a7;
}

// LSTM recurrence: cluster of 8 CTAs per batch element
__global__ void __cluster_dims__(8, 1, 1) __launch_bounds__(128, 1)
lstm_rec_kernel(const float* __restrict__ b_hh) {
    extern __shared__ float sml[];
    float* sW = sml;
    float* sh = sml + 256 * 128;
    int tid = threadIdx.x;
    int r = blockIdx.x & 7;
    int b = blockIdx.x >> 3;
    for (int i = tid; i < 256 * 128; i += 128)
        sW[i] = g_WhhP[(size_t)(i >> 7) * 1024 + r * 128 + (i & 127)];
    for (int i = tid; i < 256; i += 128) sh[i] = 0.f;
    int q = tid & 3, jl = tid >> 2;
    int jg = r * 32 + jl;
    float bias = b_hh[q * 256 + jg];
    float c = 0.f;
    uint32_t sh_my = smem_u32(&sh[jg]);
    __syncthreads();
    CLUSTER_BAR();
    int lbase = (tid & 31) & ~3;
    for (int t = 0; t < SLEN; t++) {
        int s = b * SLEN + t;
        float acc = g_pre[(size_t)s * 1024 + r * 128 + tid] + bias;
#pragma unroll 8
        for (int k = 0; k < 256; k++) acc += sh[k] * sW[k * 128 + tid];
        float vi = __shfl_sync(0xffffffffu, acc, lbase + 0);
        float vf = __shfl_sync(0xffffffffu, acc, lbase + 1);
        float vg = __shfl_sync(0xffffffffu, acc, lbase + 2);
        float vo = __shfl_sync(0xffffffffu, acc, lbase + 3);
        CLUSTER_BAR();
        if (q == 0) {
            c = sigmoidf_(vf) * c + sigmoidf_(vi) * tanhf(vg);
            float h = sigmoidf_(vo) * tanhf(c);
            g_hout[(size_t)s * HHID + jg] = h;
#pragma unroll
            for (int dst = 0; dst < 8; dst++) {
                uint32_t rem;
                asm("mapa.shared::cluster.u32 %0, %1, %2;" : "=r"(rem)
                    : "r"(sh_my), "r"(dst));
                asm volatile("st.shared::cluster.f32 [%0], %1;" :: "r"(rem), "f"(h)
                             : "memory");
            }
        }
        CLUSTER_BAR();
    }
}

// ---------------- pred + BCE + final -----------------------------------------
__global__ void pred_kernel(const float* __restrict__ target_c,
                            const float* __restrict__ result,
                            const float* __restrict__ pred_w,
                            const float* __restrict__ pred_b) {
    __shared__ float sh[HHID];
    __shared__ float s_p, s_n;
    int i = blockIdx.x, tid = threadIdx.x;
    sh[tid] = g_hout[(size_t)i * HHID + tid];
    sh[tid + 128] = g_hout[(size_t)i * HHID + tid + 128];
    if (tid == 0) { s_p = 0.f; s_n = 0.f; }
    __syncthreads();
    int warp = tid >> 5, lane = tid & 31;
    float lp = 0.f, ln = 0.f;
    for (int c = warp; c < CP1N; c += 4) {
        float tc = target_c[i * CP1N + c];
        if (tc != 0.f) {
            float s = 0.f;
            for (int d = lane; d < HHID; d += 32) s += pred_w[c * HHID + d] * sh[d];
#pragma unroll
            for (int o = 16; o > 0; o >>= 1) s += __shfl_xor_sync(0xffffffffu, s, o);
            if (lane == 0) { lp += tc * (s + pred_b[c]); ln += tc; }
        }
    }
    if (lane == 0) { atomicAdd(&s_p, lp); atomicAdd(&s_n, ln); }
    __syncthreads();
    if (tid == 0) {
        float nc = s_n;
        int mask = nc > 0.f;
        float fp = s_p / (mask ? nc : 1.f);
        float ft = result[i];
        float bce = fmaxf(fp, 0.f) - fp * ft + log1pf(expf(-fabsf(fp)));
        g_fp[i] = fp;
        g_mf[i] = mask ? 1.f : 0.f;
        g_bce[i] = mask ? bce : 0.f;
    }
}

__global__ void final_kernel(const float* __restrict__ result, float* __restrict__ out,
                             int out_size) {
    __shared__ float rb[256], rm[256];
    int tid = threadIdx.x;
    float sb = 0.f, smm = 0.f;
    for (int i = tid; i < GG; i += 256) { sb += g_bce[i]; smm += g_mf[i]; }
    rb[tid] = sb; rm[tid] = smm;
    __syncthreads();
    for (int o = 128; o > 0; o >>= 1) {
        if (tid < o) { rb[tid] += rb[tid + o]; rm[tid] += rm[tid + o]; }
        __syncthreads();
    }
    if (tid == 0 && out_size > 0) out[0] = rb[0] / fmaxf(rm[0], 1.f);
    for (int i = tid; i < GG; i += 256) {
        if (1 + i < out_size) out[1 + i] = 1.f / (1.f + expf(-g_fp[i]));
        if (1 + GG + i < out_size) out[1 + GG + i] = result[i];
    }
}

// ---------------- launcher ---------------------------------------------------
extern "C" void kernel_launch(void* const* d_in, const int* in_sizes, int n_in,
                              void* d_out, int out_size) {
    const float* c_id       = (const float*)d_in[1];
    const int*   node_id    = (const int*)d_in[2];
    const int*   edge       = (const int*)d_in[3];
    const int*   edge_type  = (const int*)d_in[4];
    const float* target_c   = (const float*)d_in[5];
    const float* result     = (const float*)d_in[6];
    const float* c_embed    = (const float*)d_in[7];
    const float* cur_result = (const float*)d_in[8];
    const float* node_embed_w = (const float*)d_in[9];
    const float* edge_embed_w = (const float*)d_in[10];
    const float* ggnn_w     = (const float*)d_in[11];
    const float* gru_w_ih   = (const float*)d_in[12];
    const float* gru_w_hh   = (const float*)d_in[13];
    const float* gru_b_ih   = (const float*)d_in[14];
    const float* gru_b_hh   = (const float*)d_in[15];
    const float* transdim_w = (const float*)d_in[16];
    const float* concept_embedding = (const float*)d_in[17];
    const float* lstm_w_ih  = (const float*)d_in[18];
    const float* lstm_w_hh  = (const float*)d_in[19];
    const float* lstm_b_ih  = (const float*)d_in[20];
    const float* lstm_b_hh  = (const float*)d_in[21];
    const float* pred_w     = (const float*)d_in[22];
    const float* pred_b     = (const float*)d_in[23];
    float* out = (float*)d_out;
    (void)in_sizes; (void)n_in;

    const int SCAT_SMEM = NNODE * DD * 4;            // 102400
    const int LSTM_SMEM = 256 * 128 * 4 + 256 * 4;   // 132096
    const int ATTN_SMEM = (NNODE * 65 + 8 * NNODE + 8 * 64 + NNODE + 64 + 4) * 4;
    cudaFuncSetAttribute(layer_mma, cudaFuncAttributeMaxDynamicSharedMemorySize, SM_TOT);
    cudaFuncSetAttribute(gemm_td, cudaFuncAttributeMaxDynamicSharedMemorySize, TD_TOT);
    cudaFuncSetAttribute(attn_kernel, cudaFuncAttributeMaxDynamicSharedMemorySize, ATTN_SMEM);
    cudaFuncSetAttribute(scatter_csr, cudaFuncAttributeMaxDynamicSharedMemorySize, SCAT_SMEM);
    cudaFuncSetAttribute(lstm_rec_kernel, cudaFuncAttributeMaxDynamicSharedMemorySize,
                         LSTM_SMEM);

    prep_kernel<<<1960, 256>>>(edge_embed_w, gru_w_hh, transdim_w, lstm_w_ih, lstm_w_hh);
    comb_kernel<<<(4 * 384 * 128 + 255) / 256, 256>>>(ggnn_w, gru_w_ih);
    gather_kernel<<<GN / 8, 256>>>(node_id, node_embed_w);
    csr_build<<<GG, 256>>>(edge, edge_type);

    for (int l = 0; l < 4; l++) {
        scatter_csr<<<GG, 512, SCAT_SMEM>>>(0);
        layer_mma<<<GN / 64, 256, SM_TOT>>>(l, gru_b_ih, gru_b_hh);
    }

    gemm_td<<<GN / 128, 256, TD_TOT>>>();
    attn_kernel<<<GG, 256, ATTN_SMEM>>>(c_id, c_embed, concept_embedding);
    lstm_pre_kernel<<<dim3(GG / 8, 4), 256>>>(c_embed, cur_result, lstm_b_ih);
    lstm_rec_kernel<<<BSZ * 8, 128, LSTM_SMEM>>>(lstm_b_hh);
    pred_kernel<<<GG, 128>>>(target_c, result, pred_w, pred_b);
    final_kernel<<<1, 256>>>(result, out, out_size);
}

// round 8
// speedup vs baseline: 4.3255x; 1.1573x over previous
#include <cuda_runtime.h>
#include <cuda_bf16.h>
#include <math.h>
#include <stdint.h>

#define BSZ  8
#define SLEN 100
#define GG   800
#define NNODE 200
#define NEDGE 600
#define DD   128
#define DCC  64
#define HHID 256
#define CP1N 111
#define FEATN 177
#define GN   160000

// ---------------- scratch globals -------------------------------------------
__device__ float g_x[(size_t)GN * DD];
__device__ __nv_bfloat16 g_xhi[(size_t)GN * DD];
__device__ __nv_bfloat16 g_xlo[(size_t)GN * DD];
__device__ __nv_bfloat16 g_agghi[(size_t)GN * DD];
__device__ __nv_bfloat16 g_agglo[(size_t)GN * DD];
__device__ __nv_bfloat16 g_CombT_hi[4 * 384 * 128];   // [l][j][k]
__device__ __nv_bfloat16 g_Whh_hi[384 * 128];         // [j][k]
__device__ __nv_bfloat16 g_Td_hi[64 * 128];           // [c][k]
__device__ float g_ggnn[(size_t)GN * DCC];
__device__ float g_attn[GG * DCC];
__device__ float g_mean8[8];
__device__ float g_LihT[FEATN * 1024];
__device__ float g_WhhP[256 * 1024];
__device__ float g_pre[(size_t)GG * 1024];
__device__ float g_hout[(size_t)GG * HHID];
__device__ float g_fp[GG];
__device__ float g_bce[GG];
__device__ float g_mf[GG];
// CSR scratch (layer-invariant)
__device__ int   g_csr_src[GG * NEDGE];
__device__ float g_csr_w[GG * NEDGE];
__device__ int   g_csr_ofs[GG * (NNODE + 1)];

__device__ __forceinline__ float sigmoidf_(float v) { return 1.f / (1.f + expf(-v)); }

__device__ __forceinline__ void cvt_hilo(float v, __nv_bfloat16& h, __nv_bfloat16& l) {
    h = __float2bfloat16_rn(v);
    l = __float2bfloat16_rn(v - __bfloat162float(h));
}

__device__ __forceinline__ uint32_t smem_u32(const void* p) {
    uint32_t a;
    asm("{ .reg .u64 t; cvta.to.shared.u64 t, %1; cvt.u32.u64 %0, t; }" : "=r"(a) : "l"(p));
    return a;
}
__device__ __forceinline__ void ldsm_x4(uint32_t& a0, uint32_t& a1, uint32_t& a2,
                                        uint32_t& a3, uint32_t addr) {
    asm volatile("ldmatrix.sync.aligned.m8n8.x4.shared.b16 {%0,%1,%2,%3}, [%4];"
                 : "=r"(a0), "=r"(a1), "=r"(a2), "=r"(a3) : "r"(addr));
}
__device__ __forceinline__ void mma16816(float* d, uint32_t a0, uint32_t a1, uint32_t a2,
                                         uint32_t a3, uint32_t b0, uint32_t b1) {
    asm volatile("mma.sync.aligned.m16n8k16.row.col.f32.bf16.bf16.f32 "
                 "{%0,%1,%2,%3}, {%4,%5,%6,%7}, {%8,%9}, {%0,%1,%2,%3};"
                 : "+f"(d[0]), "+f"(d[1]), "+f"(d[2]), "+f"(d[3])
                 : "r"(a0), "r"(a1), "r"(a2), "r"(a3), "r"(b0), "r"(b1));
}
__device__ __forceinline__ void cp_async16(uint32_t saddr, const void* gaddr) {
    asm volatile("cp.async.cg.shared.global [%0], [%1], 16;" :: "r"(saddr), "l"(gaddr));
}
#define CP_COMMIT() asm volatile("cp.async.commit_group;" ::: "memory")
#define CP_WAIT(n)  asm volatile("cp.async.wait_group %0;" :: "n"(n) : "memory")
#define CLUSTER_BAR() do { \
    asm volatile("barrier.cluster.arrive.aligned;" ::: "memory"); \
    asm volatile("barrier.cluster.wait.aligned;" ::: "memory"); \
} while (0)

// ---------------- prep -------------------------------------------------------
__global__ void prep_kernel(const float* __restrict__ edge_embed_w,
                            const float* __restrict__ gru_w_hh,
                            const float* __restrict__ transdim_w,
                            const float* __restrict__ lstm_w_ih,
                            const float* __restrict__ lstm_w_hh) {
    const int T3 = 64 * 128, T4 = FEATN * 1024, T5 = 256 * 1024, T6 = 384 * 128;
    int total = 8 + T3 + T4 + T5 + T6;
    for (int i = blockIdx.x * blockDim.x + threadIdx.x; i < total;
         i += gridDim.x * blockDim.x) {
        int t = i;
        if (t < 8) {
            float s = 0.f;
            for (int d = 0; d < DD; d++) s += edge_embed_w[t * DD + d];
            g_mean8[t] = s / (float)DD;
            continue;
        }
        t -= 8;
        if (t < T3) { g_Td_hi[t] = __float2bfloat16_rn(transdim_w[t]); continue; }
        t -= T3;
        if (t < T4) {
            int k = t / 1024, p = t % 1024; int q = p & 3, j = p >> 2;
            g_LihT[t] = lstm_w_ih[(q * 256 + j) * FEATN + k];
            continue;
        }
        t -= T4;
        if (t < T5) {
            int k = t / 1024, p = t % 1024; int q = p & 3, j = p >> 2;
            g_WhhP[t] = lstm_w_hh[(q * 256 + j) * 256 + k];
            continue;
        }
        t -= T5;
        g_Whh_hi[t] = __float2bfloat16_rn(gru_w_hh[t]);
    }
}

// CombT[l][j][k] = sum_d W_l[k,d] * W_ih[j,d]
__global__ void comb_kernel(const float* __restrict__ ggnn_w,
                            const float* __restrict__ gru_w_ih) {
    int t = blockIdx.x * blockDim.x + threadIdx.x;
    if (t >= 4 * 384 * 128) return;
    int l = t / (384 * 128); int r = t % (384 * 128);
    int j = r / 128, k = r % 128;
    const float4* wl = (const float4*)(ggnn_w + ((size_t)l * 128 + k) * 128);
    const float4* wi = (const float4*)(gru_w_ih + (size_t)j * 128);
    float s = 0.f;
#pragma unroll 8
    for (int d = 0; d < 32; d++) {
        float4 a = wl[d], b = wi[d];
        s += a.x * b.x + a.y * b.y + a.z * b.z + a.w * b.w;
    }
    g_CombT_hi[t] = __float2bfloat16_rn(s);
}

// ---------------- gather -----------------------------------------------------
__global__ void gather_kernel(const int* __restrict__ node_id,
                              const float* __restrict__ embed) {
    int warp = threadIdx.x >> 5, lane = threadIdx.x & 31;
    int row = blockIdx.x * 8 + warp;
    if (row >= GN) return;
    int nid = node_id[row];
    float4 v = *(const float4*)&embed[(size_t)nid * DD + lane * 4];
    size_t o = (size_t)row * DD + lane * 4;
    *(float4*)&g_x[o] = v;
    __nv_bfloat16 h0, l0, h1, l1, h2, l2, h3, l3;
    cvt_hilo(v.x, h0, l0); cvt_hilo(v.y, h1, l1);
    cvt_hilo(v.z, h2, l2); cvt_hilo(v.w, h3, l3);
    ((__nv_bfloat162*)&g_xhi[o])[0] = __nv_bfloat162(h0, h1);
    ((__nv_bfloat162*)&g_xhi[o])[1] = __nv_bfloat162(h2, h3);
    ((__nv_bfloat162*)&g_xlo[o])[0] = __nv_bfloat162(l0, l1);
    ((__nv_bfloat162*)&g_xlo[o])[1] = __nv_bfloat162(l2, l3);
}

// ---------------- CSR build (once; layer-invariant) --------------------------
__global__ void csr_build(const int* __restrict__ edge,
                          const int* __restrict__ edge_type) {
    __shared__ int s_src[NEDGE];
    __shared__ int s_dst[NEDGE];
    __shared__ int cnt[NNODE + 1];
    __shared__ int ofs[NNODE + 1];
    __shared__ float sm8[8];
    int g = blockIdx.x;
    int tid = threadIdx.x;
    const int* eg = edge + (size_t)g * 2 * NEDGE;
    if (tid < 8) sm8[tid] = g_mean8[tid];
    for (int e = tid; e < NEDGE; e += 256) { s_src[e] = eg[e]; s_dst[e] = eg[NEDGE + e]; }
    for (int i = tid; i <= NNODE; i += 256) cnt[i] = 0;
    __syncthreads();
    for (int e = tid; e < NEDGE; e += 256) atomicAdd(&cnt[s_dst[e]], 1);
    __syncthreads();
    if (tid == 0) {
        int acc = 0;
        for (int n = 0; n <= NNODE; n++) { int c = cnt[n]; ofs[n] = acc; acc += c; }
    }
    __syncthreads();
    for (int i = tid; i <= NNODE; i += 256) g_csr_ofs[g * (NNODE + 1) + i] = ofs[i];
    for (int i = tid; i < NNODE; i += 256) cnt[i] = ofs[i];
    __syncthreads();
    for (int e = tid; e < NEDGE; e += 256) {
        int p = atomicAdd(&cnt[s_dst[e]], 1);
        g_csr_src[g * NEDGE + p] = s_src[e];
        g_csr_w[g * NEDGE + p] = sm8[edge_type[(size_t)g * NEDGE + e]];
    }
}

// ---------------- per-layer edge scatter: smem x tile + prebuilt CSR ---------
__global__ void __launch_bounds__(512, 2) scatter_csr(int dummy) {
    extern __shared__ float sx[];
    int g = blockIdx.x;
    int tid = threadIdx.x;
    {
        const float4* xg4 = (const float4*)(g_x + (size_t)g * NNODE * DD);
        float4* sx4 = (float4*)sx;
        for (int i = tid; i < NNODE * DD / 4; i += 512) sx4[i] = xg4[i];
    }
    __syncthreads();
    int warp = tid >> 5, lane = tid & 31;
    const int* ofs = g_csr_ofs + g * (NNODE + 1);
    const int* srcv = g_csr_src + g * NEDGE;
    const float* wv = g_csr_w + g * NEDGE;
    for (int n = warp; n < NNODE; n += 16) {
        float4 acc = make_float4(0.f, 0.f, 0.f, 0.f);
        int s0 = ofs[n], s1 = ofs[n + 1];
        for (int i = s0; i < s1; i++) {
            int src = srcv[i];
            float w = wv[i];
            float4 v = *(const float4*)&sx[src * DD + lane * 4];
            acc.x += w * v.x; acc.y += w * v.y; acc.z += w * v.z; acc.w += w * v.w;
        }
        size_t o = ((size_t)(g * NNODE + n)) * DD + lane * 4;
        __nv_bfloat16 h0, l0, h1, l1, h2, l2, h3, l3;
        cvt_hilo(acc.x, h0, l0); cvt_hilo(acc.y, h1, l1);
        cvt_hilo(acc.z, h2, l2); cvt_hilo(acc.w, h3, l3);
        ((__nv_bfloat162*)&g_agghi[o])[0] = __nv_bfloat162(h0, h1);
        ((__nv_bfloat162*)&g_agghi[o])[1] = __nv_bfloat162(h2, h3);
        ((__nv_bfloat162*)&g_agglo[o])[0] = __nv_bfloat162(l0, l1);
        ((__nv_bfloat162*)&g_agglo[o])[1] = __nv_bfloat162(l2, l3);
    }
    (void)dummy;
}

// ---------------- fused HMMA GGNN layer: 2-pass (A hi/lo x B hi) -------------
#define SMA_AGH 0
#define SMA_AGL 16384
#define SMA_XH  32768
#define SMA_XL  49152
#define SMB0    65536
#define SMB1    98304
#define SMB_BIA 131072
#define SM_TOT  (131072 + 2048)

__global__ void __launch_bounds__(256, 1) layer_mma(int layer,
                                                    const float* __restrict__ b_ih,
                                                    const float* __restrict__ b_hh) {
    extern __shared__ __align__(128) char smx[];
    uint32_t sbase = smem_u32(smx);
    int tid = threadIdx.x, wid = tid >> 5, lane = tid & 31;
    int rowBase = blockIdx.x * 64;
    int rg = wid >> 1;
    int cg = wid & 1;
    float* sb = (float*)(smx + SMB_BIA);
    if (tid < 128) {
        sb[tid]       = b_ih[tid] + b_hh[tid];
        sb[128 + tid] = b_ih[128 + tid] + b_hh[128 + tid];
        sb[256 + tid] = b_ih[256 + tid];
        sb[384 + tid] = b_hh[256 + tid];
    }
    {
        const __nv_bfloat16* s0 = g_agghi + (size_t)rowBase * 128;
        const __nv_bfloat16* s1 = g_agglo + (size_t)rowBase * 128;
        const __nv_bfloat16* s2 = g_xhi + (size_t)rowBase * 128;
        const __nv_bfloat16* s3 = g_xlo + (size_t)rowBase * 128;
#pragma unroll
        for (int q = 0; q < 4; q++) {
            int i = tid + 256 * q;
            int r = i >> 4, c = i & 15;
            uint32_t off = r * 256 + ((c ^ (r & 7)) << 4);
            cp_async16(sbase + SMA_AGH + off, s0 + i * 8);
            cp_async16(sbase + SMA_AGL + off, s1 + i * 8);
            cp_async16(sbase + SMA_XH + off, s2 + i * 8);
            cp_async16(sbase + SMA_XL + off, s3 + i * 8);
        }
    }
    auto load_b = [&](int c) {
        int j0 = (c >> 1) * 128;
        bool isComb = !(c & 1);
        const __nv_bfloat16* bh = isComb ? (g_CombT_hi + ((size_t)layer * 384 + j0) * 128)
                                         : (g_Whh_hi + (size_t)j0 * 128);
        uint32_t dst = sbase + ((c & 1) ? SMB1 : SMB0);
#pragma unroll
        for (int q = 0; q < 8; q++) {
            int i = tid + 256 * q;
            int r = i >> 4, cc = i & 15;
            uint32_t off = r * 256 + ((cc ^ (r & 7)) << 4);
            cp_async16(dst + off, bh + i * 8);
        }
    };
    load_b(0);
    CP_COMMIT();

    float acc[4][8][4];
#pragma unroll
    for (int b = 0; b < 4; b++)
#pragma unroll
        for (int n = 0; n < 8; n++)
#pragma unroll
            for (int e = 0; e < 4; e++) acc[b][n][e] = 0.f;

    const int a_r = rg * 16 + (lane & 15);
    const int a_kh = lane >> 4;
    const int b_grp = lane >> 3;
    const int b_nt_off = b_grp >> 1;
    const int b_kh = b_grp & 1;
    const int b_nl = lane & 7;

#pragma unroll
    for (int chunk = 0; chunk < 6; chunk++) {
        if (chunk < 5) { load_b(chunk + 1); CP_COMMIT(); }
        if (chunk < 5) { CP_WAIT(1); } else { CP_WAIT(0); }
        __syncthreads();
        const bool isComb = !(chunk & 1);
        const int bank = (chunk < 2) ? 0 : (chunk < 4) ? 1 : (chunk == 4) ? 2 : 3;
        const uint32_t bufH = sbase + ((chunk & 1) ? SMB1 : SMB0);
        const uint32_t aHi = sbase + (isComb ? SMA_AGH : SMA_XH);
        const uint32_t aLo = sbase + (isComb ? SMA_AGL : SMA_XL);
        for (int ks = 0; ks < 8; ks++) {
            uint32_t ach = (uint32_t)(((ks * 2 + a_kh) ^ (a_r & 7)) << 4) + a_r * 256;
            uint32_t ah0, ah1, ah2, ah3, al0, al1, al2, al3;
            ldsm_x4(ah0, ah1, ah2, ah3, aHi + ach);
            ldsm_x4(al0, al1, al2, al3, aLo + ach);
#pragma unroll
            for (int nt2 = 0; nt2 < 8; nt2 += 2) {
                int n = cg * 64 + (nt2 + b_nt_off) * 8 + b_nl;
                uint32_t boff = (uint32_t)n * 256 + (uint32_t)(((ks * 2 + b_kh) ^ (n & 7)) << 4);
                uint32_t bh0, bh1, bh2, bh3;
                ldsm_x4(bh0, bh1, bh2, bh3, bufH + boff);
                mma16816(acc[bank][nt2], ah0, ah1, ah2, ah3, bh0, bh1);
                mma16816(acc[bank][nt2], al0, al1, al2, al3, bh0, bh1);
                mma16816(acc[bank][nt2 + 1], ah0, ah1, ah2, ah3, bh2, bh3);
                mma16816(acc[bank][nt2 + 1], al0, al1, al2, al3, bh2, bh3);
            }
        }
        __syncthreads();
    }

    int tq = lane >> 2, tr = lane & 3;
#pragma unroll
    for (int nt = 0; nt < 8; nt++) {
        int j = cg * 64 + nt * 8 + tr * 2;
#pragma unroll
        for (int h = 0; h < 2; h++) {
            int m = rowBase + rg * 16 + tq + h * 8;
            float r0 = sigmoidf_(acc[0][nt][2 * h] + sb[j]);
            float r1 = sigmoidf_(acc[0][nt][2 * h + 1] + sb[j + 1]);
            float z0 = sigmoidf_(acc[1][nt][2 * h] + sb[128 + j]);
            float z1 = sigmoidf_(acc[1][nt][2 * h + 1] + sb[128 + j + 1]);
            float n0 = tanhf(acc[2][nt][2 * h] + sb[256 + j] +
                             r0 * (acc[3][nt][2 * h] + sb[384 + j]));
            float n1 = tanhf(acc[2][nt][2 * h + 1] + sb[256 + j + 1] +
                             r1 * (acc[3][nt][2 * h + 1] + sb[384 + j + 1]));
            size_t o = (size_t)m * 128 + j;
            float2 xo = *(const float2*)&g_x[o];
            float xn0 = (1.f - z0) * n0 + z0 * xo.x;
            float xn1 = (1.f - z1) * n1 + z1 * xo.y;
            *(float2*)&g_x[o] = make_float2(xn0, xn1);
            __nv_bfloat16 h0, l0, h1, l1;
            cvt_hilo(xn0, h0, l0); cvt_hilo(xn1, h1, l1);
            *(__nv_bfloat162*)&g_xhi[o] = __nv_bfloat162(h0, h1);
            *(__nv_bfloat162*)&g_xlo[o] = __nv_bfloat162(l0, l1);
        }
    }
}

// ---------------- transdim GEMM via HMMA (2-pass) -----------------------------
#define TD_AH 0
#define TD_AL 32768
#define TD_BH 65536
#define TD_TOT 81920
__global__ void __launch_bounds__(256, 2) gemm_td() {
    extern __shared__ __align__(128) char smt[];
    uint32_t sbase = smem_u32(smt);
    int tid = threadIdx.x, wid = tid >> 5, lane = tid & 31;
    int rowBase = blockIdx.x * 128;
    {
        const __nv_bfloat16* s2 = g_xhi + (size_t)rowBase * 128;
        const __nv_bfloat16* s3 = g_xlo + (size_t)rowBase * 128;
#pragma unroll
        for (int q = 0; q < 8; q++) {
            int i = tid + 256 * q;
            int r = i >> 4, c = i & 15;
            uint32_t off = r * 256 + ((c ^ (r & 7)) << 4);
            cp_async16(sbase + TD_AH + off, s2 + i * 8);
            cp_async16(sbase + TD_AL + off, s3 + i * 8);
        }
    }
    {
#pragma unroll
        for (int q = 0; q < 4; q++) {
            int i = tid + 256 * q;
            int r = i >> 4, c = i & 15;
            uint32_t off = r * 256 + ((c ^ (r & 7)) << 4);
            cp_async16(sbase + TD_BH + off, g_Td_hi + i * 8);
        }
    }
    CP_COMMIT();
    CP_WAIT(0);
    __syncthreads();

    float acc[8][4];
#pragma unroll
    for (int n = 0; n < 8; n++)
#pragma unroll
        for (int e = 0; e < 4; e++) acc[n][e] = 0.f;

    const int a_r = wid * 16 + (lane & 15);
    const int a_kh = lane >> 4;
    const int b_grp = lane >> 3;
    const int b_nt_off = b_grp >> 1;
    const int b_kh = b_grp & 1;
    const int b_nl = lane & 7;

    for (int ks = 0; ks < 8; ks++) {
        uint32_t ach = (uint32_t)(((ks * 2 + a_kh) ^ (a_r & 7)) << 4) + a_r * 256;
        uint32_t ah0, ah1, ah2, ah3, al0, al1, al2, al3;
        ldsm_x4(ah0, ah1, ah2, ah3, sbase + TD_AH + ach);
        ldsm_x4(al0, al1, al2, al3, sbase + TD_AL + ach);
#pragma unroll
        for (int nt2 = 0; nt2 < 8; nt2 += 2) {
            int n = (nt2 + b_nt_off) * 8 + b_nl;
            uint32_t boff = (uint32_t)n * 256 + (uint32_t)(((ks * 2 + b_kh) ^ (n & 7)) << 4);
            uint32_t bh0, bh1, bh2, bh3;
            ldsm_x4(bh0, bh1, bh2, bh3, sbase + TD_BH + boff);
            mma16816(acc[nt2], ah0, ah1, ah2, ah3, bh0, bh1);
            mma16816(acc[nt2], al0, al1, al2, al3, bh0, bh1);
            mma16816(acc[nt2 + 1], ah0, ah1, ah2, ah3, bh2, bh3);
            mma16816(acc[nt2 + 1], al0, al1, al2, al3, bh2, bh3);
        }
    }
    int tq = lane >> 2, tr = lane & 3;
#pragma unroll
    for (int nt = 0; nt < 8; nt++) {
        int j = nt * 8 + tr * 2;
#pragma unroll
        for (int h = 0; h < 2; h++) {
            int m = rowBase + wid * 16 + tq + h * 8;
            *(float2*)&g_ggnn[(size_t)m * DCC + j] =
                make_float2(acc[nt][2 * h], acc[nt][2 * h + 1]);
        }
    }
}

// ---------------- attention (collapsed node weights) --------------------------
__global__ void attn_kernel(const float* __restrict__ c_id,
                            const float* __restrict__ c_embed,
                            const float* __restrict__ concept_embedding) {
    extern __shared__ float smf[];
    float* shg = smf;
    float* pbuf = shg + NNODE * 65;
    float* qbuf = pbuf + 8 * NNODE;
    float* wnode = qbuf + 8 * 64;
    float* accd = wnode + NNODE;
    float* snum = accd + 64;
    int g = blockIdx.x;
    int tid = threadIdx.x;
    for (int i = tid; i < NNODE * DCC; i += 256) {
        int n = i >> 6, d = i & 63;
        shg[n * 65 + d] = g_ggnn[(size_t)(g * NNODE + n) * DCC + d];
    }
    for (int i = tid; i < NNODE; i += 256) wnode[i] = 0.f;
    if (tid < 64) accd[tid] = 0.f;
    if (tid == 0) snum[0] = 0.f;
    __syncthreads();
    if (tid < CP1N) atomicAdd(snum, c_id[g * CP1N + tid]);
    __syncthreads();
    int warp = tid >> 5, lane = tid & 31;
    for (int c = warp; c < CP1N; c += 8) {
        float ce = c_embed[g * CP1N + c];
        if (ce == 0.f) continue;
        qbuf[warp * 64 + lane] = ce * concept_embedding[c * DCC + lane];
        qbuf[warp * 64 + lane + 32] = ce * concept_embedding[c * DCC + lane + 32];
        __syncwarp();
        float mx = -1e30f;
        for (int n = lane; n < NNODE; n += 32) {
            float s = 0.f;
#pragma unroll 16
            for (int d = 0; d < DCC; d++) s += qbuf[warp * 64 + d] * shg[n * 65 + d];
            pbuf[warp * NNODE + n] = s;
            mx = fmaxf(mx, s);
        }
#pragma unroll
        for (int o = 16; o > 0; o >>= 1) mx = fmaxf(mx, __shfl_xor_sync(0xffffffffu, mx, o));
        float ssum = 0.f;
        for (int n = lane; n < NNODE; n += 32) {
            float p = expf(pbuf[warp * NNODE + n] - mx);
            pbuf[warp * NNODE + n] = p;
            ssum += p;
        }
#pragma unroll
        for (int o = 16; o > 0; o >>= 1) ssum += __shfl_xor_sync(0xffffffffu, ssum, o);
        float inv = ce / ssum;
        for (int n = lane; n < NNODE; n += 32)
            atomicAdd(&wnode[n], inv * pbuf[warp * NNODE + n]);
    }
    __syncthreads();
    {
        int d = tid & 63, q = tid >> 6;
        float partial = 0.f;
        for (int n = q * 50; n < q * 50 + 50; n++)
            partial += wnode[n] * shg[n * 65 + d];
        atomicAdd(&accd[d], partial);
    }
    __syncthreads();
    if (tid < DCC) {
        float nv = snum[0];
        if (nv == 0.f) nv = 1.f;
        g_attn[g * DCC + tid] = accd[tid] / nv;
    }
}

// ---------------- LSTM input GEMM: 8 sequences per block ---------------------
__global__ void lstm_pre_kernel(const float* __restrict__ c_embed,
                                const float* __restrict__ cur_result,
                                const float* __restrict__ lstm_b_ih) {
    __shared__ float xin[8][FEATN];
    int s0 = blockIdx.x * 8;
    int tid = threadIdx.x;
    for (int i = tid; i < 8 * FEATN; i += 256) {
        int si = i / FEATN, f = i % FEATN;
        int s = s0 + si;
        float v;
        if (f < CP1N) v = c_embed[(size_t)s * CP1N + f];
        else if (f < CP1N + DCC) v = g_attn[(size_t)s * DCC + (f - CP1N)];
        else v = cur_result[(size_t)s * 2 + (f - CP1N - DCC)];
        xin[si][f] = v;
    }
    __syncthreads();
    int m = blockIdx.y * 256 + tid;
    int q = m & 3, j = m >> 2;
    float b = lstm_b_ih[q * 256 + j];
    float a0 = b, a1 = b, a2 = b, a3 = b, a4 = b, a5 = b, a6 = b, a7 = b;
    for (int k = 0; k < FEATN; k++) {
        float w = g_LihT[(size_t)k * 1024 + m];
        a0 += xin[0][k] * w; a1 += xin[1][k] * w;
        a2 += xin[2][k] * w; a3 += xin[3][k] * w;
        a4 += xin[4][k] * w; a5 += xin[5][k] * w;
        a6 += xin[6][k] * w; a7 += xin[7][k] * w;
    }
    g_pre[(size_t)(s0 + 0) * 1024 + m] = a0;
    g_pre[(size_t)(s0 + 1) * 1024 + m] = a1;
    g_pre[(size_t)(s0 + 2) * 1024 + m] = a2;
    g_pre[(size_t)(s0 + 3) * 1024 + m] = a3;
    g_pre[(size_t)(s0 + 4) * 1024 + m] = a4;
    g_pre[(size_t)(s0 + 5) * 1024 + m] = a5;
    g_pre[(size_t)(s0 + 6) * 1024 + m] = a6;
    g_pre[(size_t)(s0 + 7) * 1024 + m] = a7;
}

// LSTM recurrence: cluster of 8 CTAs per batch element; double-buffered h,
// ONE cluster barrier per step.
__global__ void __cluster_dims__(8, 1, 1) __launch_bounds__(128, 1)
lstm_rec_kernel(const float* __restrict__ b_hh) {
    extern __shared__ float sml[];
    float* sW = sml;                  // 256*128
    float* sh = sml + 256 * 128;      // 2 x 256 (double buffer)
    int tid = threadIdx.x;
    int r = blockIdx.x & 7;
    int b = blockIdx.x >> 3;
    for (int i = tid; i < 256 * 128; i += 128)
        sW[i] = g_WhhP[(size_t)(i >> 7) * 1024 + r * 128 + (i & 127)];
    for (int i = tid; i < 512; i += 128) sh[i] = 0.f;
    int q = tid & 3, jl = tid >> 2;
    int jg = r * 32 + jl;
    float bias = b_hh[q * 256 + jg];
    float c = 0.f;
    uint32_t sh_my0 = smem_u32(&sh[jg]);
    uint32_t sh_my1 = smem_u32(&sh[256 + jg]);
    __syncthreads();
    CLUSTER_BAR();
    int lbase = (tid & 31) & ~3;
    for (int t = 0; t < SLEN; t++) {
        int s = b * SLEN + t;
        const float* shc = sh + 256 * (t & 1);
        uint32_t sh_next = (t & 1) ? sh_my0 : sh_my1;
        float acc = g_pre[(size_t)s * 1024 + r * 128 + tid] + bias;
#pragma unroll 8
        for (int k = 0; k < 256; k++) acc += shc[k] * sW[k * 128 + tid];
        float vi = __shfl_sync(0xffffffffu, acc, lbase + 0);
        float vf = __shfl_sync(0xffffffffu, acc, lbase + 1);
        float vg = __shfl_sync(0xffffffffu, acc, lbase + 2);
        float vo = __shfl_sync(0xffffffffu, acc, lbase + 3);
        if (q == 0) {
            c = sigmoidf_(vf) * c + sigmoidf_(vi) * tanhf(vg);
            float h = sigmoidf_(vo) * tanhf(c);
            g_hout[(size_t)s * HHID + jg] = h;
#pragma unroll
            for (int dst = 0; dst < 8; dst++) {
                uint32_t rem;
                asm("mapa.shared::cluster.u32 %0, %1, %2;" : "=r"(rem)
                    : "r"(sh_next), "r"(dst));
                asm volatile("st.shared::cluster.f32 [%0], %1;" :: "r"(rem), "f"(h)
                             : "memory");
            }
        }
        CLUSTER_BAR();
    }
}

// ---------------- pred + BCE + final -----------------------------------------
__global__ void pred_kernel(const float* __restrict__ target_c,
                            const float* __restrict__ result,
                            const float* __restrict__ pred_w,
                            const float* __restrict__ pred_b) {
    __shared__ float sh[HHID];
    __shared__ float s_p, s_n;
    int i = blockIdx.x, tid = threadIdx.x;
    sh[tid] = g_hout[(size_t)i * HHID + tid];
    sh[tid + 128] = g_hout[(size_t)i * HHID + tid + 128];
    if (tid == 0) { s_p = 0.f; s_n = 0.f; }
    __syncthreads();
    int warp = tid >> 5, lane = tid & 31;
    float lp = 0.f, ln = 0.f;
    for (int c = warp; c < CP1N; c += 4) {
        float tc = target_c[i * CP1N + c];
        if (tc != 0.f) {
            float s = 0.f;
            for (int d = lane; d < HHID; d += 32) s += pred_w[c * HHID + d] * sh[d];
#pragma unroll
            for (int o = 16; o > 0; o >>= 1) s += __shfl_xor_sync(0xffffffffu, s, o);
            if (lane == 0) { lp += tc * (s + pred_b[c]); ln += tc; }
        }
    }
    if (lane == 0) { atomicAdd(&s_p, lp); atomicAdd(&s_n, ln); }
    __syncthreads();
    if (tid == 0) {
        float nc = s_n;
        int mask = nc > 0.f;
        float fp = s_p / (mask ? nc : 1.f);
        float ft = result[i];
        float bce = fmaxf(fp, 0.f) - fp * ft + log1pf(expf(-fabsf(fp)));
        g_fp[i] = fp;
        g_mf[i] = mask ? 1.f : 0.f;
        g_bce[i] = mask ? bce : 0.f;
    }
}

__global__ void final_kernel(const float* __restrict__ result, float* __restrict__ out,
                             int out_size) {
    __shared__ float rb[256], rm[256];
    int tid = threadIdx.x;
    float sb = 0.f, smm = 0.f;
    for (int i = tid; i < GG; i += 256) { sb += g_bce[i]; smm += g_mf[i]; }
    rb[tid] = sb; rm[tid] = smm;
    __syncthreads();
    for (int o = 128; o > 0; o >>= 1) {
        if (tid < o) { rb[tid] += rb[tid + o]; rm[tid] += rm[tid + o]; }
        __syncthreads();
    }
    if (tid == 0 && out_size > 0) out[0] = rb[0] / fmaxf(rm[0], 1.f);
    for (int i = tid; i < GG; i += 256) {
        if (1 + i < out_size) out[1 + i] = 1.f / (1.f + expf(-g_fp[i]));
        if (1 + GG + i < out_size) out[1 + GG + i] = result[i];
    }
}

// ---------------- launcher ---------------------------------------------------
extern "C" void kernel_launch(void* const* d_in, const int* in_sizes, int n_in,
                              void* d_out, int out_size) {
    const float* c_id       = (const float*)d_in[1];
    const int*   node_id    = (const int*)d_in[2];
    const int*   edge       = (const int*)d_in[3];
    const int*   edge_type  = (const int*)d_in[4];
    const float* target_c   = (const float*)d_in[5];
    const float* result     = (const float*)d_in[6];
    const float* c_embed    = (const float*)d_in[7];
    const float* cur_result = (const float*)d_in[8];
    const float* node_embed_w = (const float*)d_in[9];
    const float* edge_embed_w = (const float*)d_in[10];
    const float* ggnn_w     = (const float*)d_in[11];
    const float* gru_w_ih   = (const float*)d_in[12];
    const float* gru_w_hh   = (const float*)d_in[13];
    const float* gru_b_ih   = (const float*)d_in[14];
    const float* gru_b_hh   = (const float*)d_in[15];
    const float* transdim_w = (const float*)d_in[16];
    const float* concept_embedding = (const float*)d_in[17];
    const float* lstm_w_ih  = (const float*)d_in[18];
    const float* lstm_w_hh  = (const float*)d_in[19];
    const float* lstm_b_ih  = (const float*)d_in[20];
    const float* lstm_b_hh  = (const float*)d_in[21];
    const float* pred_w     = (const float*)d_in[22];
    const float* pred_b     = (const float*)d_in[23];
    float* out = (float*)d_out;
    (void)in_sizes; (void)n_in;

    const int SCAT_SMEM = NNODE * DD * 4;
    const int LSTM_SMEM = 256 * 128 * 4 + 512 * 4;
    const int ATTN_SMEM = (NNODE * 65 + 8 * NNODE + 8 * 64 + NNODE + 64 + 4) * 4;
    cudaFuncSetAttribute(layer_mma, cudaFuncAttributeMaxDynamicSharedMemorySize, SM_TOT);
    cudaFuncSetAttribute(gemm_td, cudaFuncAttributeMaxDynamicSharedMemorySize, TD_TOT);
    cudaFuncSetAttribute(attn_kernel, cudaFuncAttributeMaxDynamicSharedMemorySize, ATTN_SMEM);
    cudaFuncSetAttribute(scatter_csr, cudaFuncAttributeMaxDynamicSharedMemorySize, SCAT_SMEM);
    cudaFuncSetAttribute(lstm_rec_kernel, cudaFuncAttributeMaxDynamicSharedMemorySize,
                         LSTM_SMEM);

    prep_kernel<<<1960, 256>>>(edge_embed_w, gru_w_hh, transdim_w, lstm_w_ih, lstm_w_hh);
    comb_kernel<<<(4 * 384 * 128 + 255) / 256, 256>>>(ggnn_w, gru_w_ih);
    gather_kernel<<<GN / 8, 256>>>(node_id, node_embed_w);
    csr_build<<<GG, 256>>>(edge, edge_type);

    for (int l = 0; l < 4; l++) {
        scatter_csr<<<GG, 512, SCAT_SMEM>>>(0);
        layer_mma<<<GN / 64, 256, SM_TOT>>>(l, gru_b_ih, gru_b_hh);
    }

    gemm_td<<<GN / 128, 256, TD_TOT>>>();
    attn_kernel<<<GG, 256, ATTN_SMEM>>>(c_id, c_embed, concept_embedding);
    lstm_pre_kernel<<<dim3(GG / 8, 4), 256>>>(c_embed, cur_result, lstm_b_ih);
    lstm_rec_kernel<<<BSZ * 8, 128, LSTM_SMEM>>>(lstm_b_hh);
    pred_kernel<<<GG, 128>>>(target_c, result, pred_w, pred_b);
    final_kernel<<<1, 256>>>(result, out, out_size);
}